// round 7
// baseline (speedup 1.0000x reference)
#include <cuda_runtime.h>
#include <cuda_bf16.h>
#include <math.h>
#include <stdint.h>

// Problem constants
#define BB 2
#define LL 4096
#define DD 1024
#define HH 16
#define GG 2
#define HD 64
#define KVD 128
#define KVC 256
#define QKVC 1280        // Q(1024) | K(128) | V(128)
#define EE 8
#define HID 1024
#define NTOK (BB*LL)     // 8192
#define NWIN 16
#define WIN 256
#define TCK 32           // K-chunk (32 bf16 columns per stage)
#define NCH (DD/TCK)     // 32 chunks
#define BSTR 40          // padded smem row stride (80B = 5x16B odd -> ldmatrix conflict-free)
#define TILE (128*BSTR)
#define TILEB (TILE*2)
#define BUFB (4*TILEB)   // one stage = Ah|Al|Bh|Bl = 40960 bytes
#define GSMEM (2*BUFB)   // 81920 bytes -> 2 CTAs/SM
#define APAD 72          // attention smem row stride (144B = 9x16B odd)

// ---------------- scratch (static device globals) ----------------
__device__ __nv_bfloat16 g_ln1h[NTOK*DD];
__device__ __nv_bfloat16 g_ln1l[NTOK*DD];
__device__ float         g_qkv [NTOK*QKVC];
__device__ __nv_bfloat16 g_atth[NTOK*DD];
__device__ __nv_bfloat16 g_attl[NTOK*DD];
__device__ float         g_ln2f[NTOK*DD];
__device__ __nv_bfloat16 g_ln2h[NTOK*DD];
__device__ __nv_bfloat16 g_ln2l[NTOK*DD];
__device__ __nv_bfloat16 g_wqkvh[QKVC*DD], g_wqkvl[QKVC*DD];
__device__ __nv_bfloat16 g_woth[DD*DD],  g_wotl[DD*DD];
__device__ __nv_bfloat16 g_weth[EE*DD*HID], g_wetl[EE*DD*HID];
__device__ float g_bqkv[QKVC];
__device__ int   g_ecount[EE];
__device__ float g_entsum;
__device__ int   g_etok[EE*NTOK];
__device__ float g_ewt [EE*NTOK];

// ---------------- helpers ----------------
__device__ __forceinline__ uint32_t su32(const void* p) {
    uint32_t r;
    asm("{ .reg .u64 t; cvta.to.shared.u64 t, %1; cvt.u32.u64 %0, t; }" : "=r"(r) : "l"(p));
    return r;
}
__device__ __forceinline__ void split2(float x, __nv_bfloat16& h, __nv_bfloat16& l) {
    h = __float2bfloat16_rn(x);
    l = __float2bfloat16_rn(x - __bfloat162float(h));
}
#define CP16(dst, src) asm volatile("cp.async.cg.shared.global [%0], [%1], 16;" :: "r"(dst), "l"(src))
#define CP_COMMIT()    asm volatile("cp.async.commit_group;" ::: "memory")
#define CP_WAIT0()     asm volatile("cp.async.wait_group 0;" ::: "memory")
#define CP_WAIT1()     asm volatile("cp.async.wait_group 1;" ::: "memory")

#define LDSM4(r0, r1, r2, r3, addr) \
    asm volatile("ldmatrix.sync.aligned.m8n8.x4.shared.b16 {%0,%1,%2,%3}, [%4];" \
                 : "=r"(r0), "=r"(r1), "=r"(r2), "=r"(r3) : "r"(addr))

__device__ __forceinline__ void mma_bf16(float* c, const uint32_t* a, const uint32_t* b) {
    asm volatile(
        "mma.sync.aligned.m16n8k16.row.col.f32.bf16.bf16.f32 "
        "{%0,%1,%2,%3}, {%4,%5,%6,%7}, {%8,%9}, {%0,%1,%2,%3};"
        : "+f"(c[0]), "+f"(c[1]), "+f"(c[2]), "+f"(c[3])
        : "r"(a[0]), "r"(a[1]), "r"(a[2]), "r"(a[3]), "r"(b[0]), "r"(b[1]));
}
__device__ __forceinline__ uint32_t packbf(__nv_bfloat16 lo, __nv_bfloat16 hi) {
    return (uint32_t)__bfloat16_as_ushort(lo) | ((uint32_t)__bfloat16_as_ushort(hi) << 16);
}

// ---------------- zero bookkeeping ----------------
__global__ void zero_kernel() {
    int t = threadIdx.x;
    if (t < EE) g_ecount[t] = 0;
    if (t == EE) g_entsum = 0.f;
}

// ---------------- weight transpose + bf16 split ----------------
__global__ void transpose_kernel(const float* __restrict__ src,
                                 __nv_bfloat16* __restrict__ dh,
                                 __nv_bfloat16* __restrict__ dl,
                                 int rows, int cols, size_t srcBStride, size_t dstBStride,
                                 int rowOff) {
    __shared__ float t[32][33];
    src += (size_t)blockIdx.z * srcBStride;
    dh  += (size_t)blockIdx.z * dstBStride;
    dl  += (size_t)blockIdx.z * dstBStride;
    int c0 = blockIdx.x * 32, r0 = blockIdx.y * 32;
    int tx = threadIdx.x, ty = threadIdx.y;
    #pragma unroll
    for (int i = 0; i < 32; i += 8)
        t[ty + i][tx] = src[(size_t)(r0 + ty + i) * cols + c0 + tx];
    __syncthreads();
    #pragma unroll
    for (int i = 0; i < 32; i += 8) {
        __nv_bfloat16 h, l;
        split2(t[tx][ty + i], h, l);
        size_t o = (size_t)(c0 + ty + i + rowOff) * rows + r0 + tx;
        dh[o] = h;
        dl[o] = l;
    }
}

__global__ void bqkv_kernel(const float* __restrict__ bq, const float* __restrict__ bk,
                            const float* __restrict__ bv) {
    int t = threadIdx.x + blockIdx.x * 256;
    if (t < DD) g_bqkv[t] = bq[t];
    else if (t < DD + KVD) g_bqkv[t] = bk[t - DD];
    else if (t < QKVC) g_bqkv[t] = bv[t - DD - KVD];
}

// ---------------- LayerNorm (split-bf16 output; optional fp32) ----------
__global__ void ln_kernel(const float* __restrict__ x, const float* __restrict__ g,
                          const float* __restrict__ b,
                          __nv_bfloat16* __restrict__ yh, __nv_bfloat16* __restrict__ yl,
                          float* __restrict__ yf) {
    int row = blockIdx.x;
    const float4* xr = (const float4*)(x + (size_t)row * DD);
    int tid = threadIdx.x;
    float4 v = xr[tid];
    float s  = v.x + v.y + v.z + v.w;
    float ss = v.x*v.x + v.y*v.y + v.z*v.z + v.w*v.w;
    #pragma unroll
    for (int o = 16; o > 0; o >>= 1) {
        s  += __shfl_down_sync(0xffffffffu, s,  o);
        ss += __shfl_down_sync(0xffffffffu, ss, o);
    }
    __shared__ float sh_s[8], sh_ss[8];
    __shared__ float s_mean, s_rstd;
    int warp = tid >> 5, lane = tid & 31;
    if (lane == 0) { sh_s[warp] = s; sh_ss[warp] = ss; }
    __syncthreads();
    if (tid == 0) {
        float S = 0.f, SS = 0.f;
        #pragma unroll
        for (int i = 0; i < 8; i++) { S += sh_s[i]; SS += sh_ss[i]; }
        float mean = S / (float)DD;
        float var  = SS / (float)DD - mean * mean;
        s_mean = mean;
        s_rstd = rsqrtf(var + 1e-5f);
    }
    __syncthreads();
    float mean = s_mean, rstd = s_rstd;
    float4 gg = ((const float4*)g)[tid];
    float4 bb = ((const float4*)b)[tid];
    float o[4];
    o[0] = (v.x - mean) * rstd * gg.x + bb.x;
    o[1] = (v.y - mean) * rstd * gg.y + bb.y;
    o[2] = (v.z - mean) * rstd * gg.z + bb.z;
    o[3] = (v.w - mean) * rstd * gg.w + bb.w;
    size_t base = (size_t)row * DD + tid * 4;
    __nv_bfloat16 hh[4], ll[4];
    #pragma unroll
    for (int i = 0; i < 4; i++) split2(o[i], hh[i], ll[i]);
    *(uint2*)&yh[base] = *(uint2*)hh;
    *(uint2*)&yl[base] = *(uint2*)ll;
    if (yf) *(float4*)&yf[base] = make_float4(o[0], o[1], o[2], o[3]);
}

// ---------------- bf16x3 mma.sync GEMM (warp tile 64x64, 128 thr, 2 CTA/SM)
// Tile 128x128, K = DD in 32 chunks of 32. 4 warps (2M x 2N), warp tile 64x64
// via m16n8k16, 3 split passes (hh, hl, lh). 2-stage cp.async.
// MODE 0: C = acc + bias
// MODE 2: C = acc + bias + resid
// MODE 3: MoE gathered rows; atomicAdd(C[tok*ldc+c], wt*(acc + bias[c]))
template<int MODE>
__global__ void __launch_bounds__(128)
tc_gemm(const __nv_bfloat16* __restrict__ Ah, const __nv_bfloat16* __restrict__ Al,
        const __nv_bfloat16* __restrict__ Bh, const __nv_bfloat16* __restrict__ Bl,
        const float* __restrict__ bias, const float* __restrict__ resid,
        float* __restrict__ C, int ldc) {
    __shared__ int   stok[128];
    __shared__ float swt[128];
    extern __shared__ __nv_bfloat16 smb[];

    int row0 = blockIdx.y * 128;
    int col0 = blockIdx.x * 128;
    int tid = threadIdx.x, wid = tid >> 5, lane = tid & 31;
    int quad = lane >> 2, tq = lane & 3;
    int wm = wid & 1, wn = wid >> 1;    // 2 x 2 warp grid, warp tile 64x64

    if (MODE == 3) {
        int e = blockIdx.z;
        int cnt = g_ecount[e];
        if (row0 >= cnt) return;
        Bh   += (size_t)e * DD * HID;
        Bl   += (size_t)e * DD * HID;
        bias += (size_t)e * HID;
        int r = row0 + tid;
        if (r < cnt) { stok[tid] = g_etok[e * NTOK + r]; swt[tid] = g_ewt[e * NTOK + r]; }
        else         { stok[tid] = -1; swt[tid] = 0.f; }
        __syncthreads();
    }

    // cp.async mapping: 128 threads, each covers rows {crow+32i, i=0..3}, one 16B seg.
    int crow = tid >> 2;
    int seg  = tid & 3;
    int arow[4];
    uint32_t doff[4];
    #pragma unroll
    for (int i = 0; i < 4; i++) {
        int r = crow + 32 * i;
        int tok;
        if (MODE == 3) { tok = stok[r]; if (tok < 0) tok = 0; }
        else           tok = row0 + r;
        arow[i] = tok;
        doff[i] = (uint32_t)(r * (BSTR * 2) + seg * 16);
    }
    uint32_t sbase = su32(smb);

    int lrow = lane & 15, lhalf = lane >> 4;
    uint32_t aLane = (uint32_t)(((wm * 64 + lrow) * BSTR + lhalf * 8) * 2);
    uint32_t bLane = (uint32_t)(((wn * 64 + lrow) * BSTR + lhalf * 8) * 2);

    float acc[4][8][4];
    #pragma unroll
    for (int mt = 0; mt < 4; mt++)
        #pragma unroll
        for (int nt = 0; nt < 8; nt++)
            #pragma unroll
            for (int i = 0; i < 4; i++) acc[mt][nt][i] = 0.f;

    // prologue: chunk 0 into buffer 0
    #pragma unroll
    for (int i = 0; i < 4; i++) {
        CP16(sbase + 0 * TILEB + doff[i], Ah + (size_t)arow[i] * DD + seg * 8);
        CP16(sbase + 1 * TILEB + doff[i], Al + (size_t)arow[i] * DD + seg * 8);
        CP16(sbase + 2 * TILEB + doff[i], Bh + (size_t)(col0 + crow + 32 * i) * DD + seg * 8);
        CP16(sbase + 3 * TILEB + doff[i], Bl + (size_t)(col0 + crow + 32 * i) * DD + seg * 8);
    }
    CP_COMMIT();

    for (int c = 0; c < NCH; c++) {
        int b = c & 1, nb = b ^ 1;
        if (c + 1 < NCH) {
            int k0 = (c + 1) * TCK;
            uint32_t base = sbase + (nb ? BUFB : 0u);
            #pragma unroll
            for (int i = 0; i < 4; i++) {
                CP16(base + 0 * TILEB + doff[i], Ah + (size_t)arow[i] * DD + seg * 8 + k0);
                CP16(base + 1 * TILEB + doff[i], Al + (size_t)arow[i] * DD + seg * 8 + k0);
                CP16(base + 2 * TILEB + doff[i], Bh + (size_t)(col0 + crow + 32 * i) * DD + seg * 8 + k0);
                CP16(base + 3 * TILEB + doff[i], Bl + (size_t)(col0 + crow + 32 * i) * DD + seg * 8 + k0);
            }
            CP_COMMIT();
            CP_WAIT1();
        } else {
            CP_WAIT0();
        }
        __syncthreads();

        uint32_t sb = sbase + (b ? BUFB : 0u);
        #pragma unroll
        for (int kk = 0; kk < 2; kk++) {
            uint32_t kof = kk * 16 * 2;
            uint32_t bh[8][2], bl[8][2];
            #pragma unroll
            for (int p = 0; p < 4; p++) {
                uint32_t bb = sb + 2 * TILEB + bLane + kof + p * 16 * BSTR * 2;
                LDSM4(bh[2*p][0], bh[2*p+1][0], bh[2*p][1], bh[2*p+1][1], bb);
                LDSM4(bl[2*p][0], bl[2*p+1][0], bl[2*p][1], bl[2*p+1][1], bb + TILEB);
            }
            #pragma unroll
            for (int mt = 0; mt < 4; mt++) {
                uint32_t ah[4], al[4];
                uint32_t aa = sb + aLane + kof + mt * 16 * BSTR * 2;
                LDSM4(ah[0], ah[1], ah[2], ah[3], aa);
                LDSM4(al[0], al[1], al[2], al[3], aa + TILEB);
                #pragma unroll
                for (int nt = 0; nt < 8; nt++) {
                    mma_bf16(acc[mt][nt], ah, bh[nt]);
                    mma_bf16(acc[mt][nt], ah, bl[nt]);
                    mma_bf16(acc[mt][nt], al, bh[nt]);
                }
            }
        }
        __syncthreads();
    }

    #pragma unroll
    for (int mt = 0; mt < 4; mt++) {
        #pragma unroll
        for (int half = 0; half < 2; half++) {
            int lr = wm * 64 + mt * 16 + quad + half * 8;
            int r = row0 + lr;
            #pragma unroll
            for (int nt = 0; nt < 8; nt++) {
                int col = col0 + wn * 64 + nt * 8 + tq * 2;
                float v0 = acc[mt][nt][half * 2 + 0] + bias[col];
                float v1 = acc[mt][nt][half * 2 + 1] + bias[col + 1];
                if (MODE == 0) {
                    *(float2*)&C[(size_t)r * ldc + col] = make_float2(v0, v1);
                } else if (MODE == 2) {
                    size_t o = (size_t)r * ldc + col;
                    float2 rr = *(const float2*)&resid[o];
                    *(float2*)&C[o] = make_float2(v0 + rr.x, v1 + rr.y);
                } else {
                    int tok = stok[lr];
                    if (tok >= 0) {
                        float w = swt[lr];
                        atomicAdd(&C[(size_t)tok * ldc + col],     w * v0);
                        atomicAdd(&C[(size_t)tok * ldc + col + 1], w * v1);
                    }
                }
            }
        }
    }
}

// ---------------- tensor-core attention (bf16x3, single-pass softmax) ------
__global__ void __launch_bounds__(256)
attn_kernel(const float* __restrict__ qkv,
            __nv_bfloat16* __restrict__ oh, __nv_bfloat16* __restrict__ ol) {
    extern __shared__ __nv_bfloat16 sma[];
    __nv_bfloat16* Qh = sma;                  // 256 x APAD
    __nv_bfloat16* Ql = Qh + 256 * APAD;
    __nv_bfloat16* Kh = Ql + 256 * APAD;      // 64 x APAD
    __nv_bfloat16* Kl = Kh + 64 * APAD;
    __nv_bfloat16* Vh = Kl + 64 * APAD;       // transposed: [dim][key] 64 x APAD
    __nv_bfloat16* Vl = Vh + 64 * APAD;

    int n = blockIdx.x, h = blockIdx.y, b = blockIdx.z;
    int g = h & (GG - 1);
    int base = b * LL + n * 128;
    int tid = threadIdx.x, wid = tid >> 5, lane = tid & 31;
    int quad = lane >> 2, tq = lane & 3;
    int lrow = lane & 15, lhalf = lane >> 4;

    // load Q (scaled by 1/sqrt(HD)), split
    {
        const float4* qp = (const float4*)(qkv + (size_t)(base + tid) * QKVC + h * 64);
        #pragma unroll
        for (int c = 0; c < 16; c++) {
            float4 q4 = qp[c];
            float v[4] = {q4.x * 0.125f, q4.y * 0.125f, q4.z * 0.125f, q4.w * 0.125f};
            __nv_bfloat16 hh[4], ll[4];
            #pragma unroll
            for (int i = 0; i < 4; i++) split2(v[i], hh[i], ll[i]);
            *(uint2*)&Qh[tid * APAD + c * 4] = *(uint2*)hh;
            *(uint2*)&Ql[tid * APAD + c * 4] = *(uint2*)ll;
        }
    }

    float o[2][8][4];
    #pragma unroll
    for (int mt = 0; mt < 2; mt++)
        #pragma unroll
        for (int nt = 0; nt < 8; nt++)
            #pragma unroll
            for (int i = 0; i < 4; i++) o[mt][nt][i] = 0.f;
    float denomAcc[2][2] = {{0.f, 0.f}, {0.f, 0.f}};

    uint32_t qBase = su32(Qh), kBase = su32(Kh), vBase = su32(Vh);
    uint32_t loQ = (uint32_t)(256 * APAD * 2);
    uint32_t loK = (uint32_t)(64 * APAD * 2);

    for (int kt = 0; kt < 4; kt++) {
        __syncthreads();   // protect Kh/Vh from previous tile's readers (also covers Q load)
        {
            int r = tid >> 2, sgi = tid & 3;
            const float* kp = qkv + (size_t)(base + kt * 64 + r) * QKVC + DD + g * 64 + sgi * 16;
            #pragma unroll
            for (int c4 = 0; c4 < 4; c4++) {
                float4 kk = *(const float4*)(kp + c4 * 4);
                float kv4[4] = {kk.x, kk.y, kk.z, kk.w};
                __nv_bfloat16 hh[4], ll[4];
                #pragma unroll
                for (int e = 0; e < 4; e++) split2(kv4[e], hh[e], ll[e]);
                *(uint2*)&Kh[r * APAD + sgi * 16 + c4 * 4] = *(uint2*)hh;
                *(uint2*)&Kl[r * APAD + sgi * 16 + c4 * 4] = *(uint2*)ll;
                float4 vv = *(const float4*)(kp + KVD + c4 * 4);
                float va[4] = {vv.x, vv.y, vv.z, vv.w};
                #pragma unroll
                for (int e = 0; e < 4; e++) {
                    __nv_bfloat16 vh_, vl_;
                    split2(va[e], vh_, vl_);
                    int d = sgi * 16 + c4 * 4 + e;
                    Vh[d * APAD + r] = vh_;
                    Vl[d * APAD + r] = vl_;
                }
            }
        }
        __syncthreads();

        // ---- S = Q @ K^T ----
        float s[2][8][4];
        #pragma unroll
        for (int mt = 0; mt < 2; mt++)
            #pragma unroll
            for (int nt = 0; nt < 8; nt++)
                #pragma unroll
                for (int i = 0; i < 4; i++) s[mt][nt][i] = 0.f;

        #pragma unroll
        for (int ks = 0; ks < 4; ks++) {
            uint32_t kof = (uint32_t)(ks * 16 + lhalf * 8) * 2;
            uint32_t ah[2][4], al[2][4];
            #pragma unroll
            for (int mt = 0; mt < 2; mt++) {
                uint32_t aa = qBase + (uint32_t)((wid * 32 + mt * 16 + lrow) * APAD) * 2 + kof;
                LDSM4(ah[mt][0], ah[mt][1], ah[mt][2], ah[mt][3], aa);
                LDSM4(al[mt][0], al[mt][1], al[mt][2], al[mt][3], aa + loQ);
            }
            uint32_t bh[8][2], bl[8][2];
            #pragma unroll
            for (int p = 0; p < 4; p++) {
                uint32_t bb = kBase + (uint32_t)((p * 16 + lrow) * APAD) * 2 + kof;
                LDSM4(bh[2*p][0], bh[2*p+1][0], bh[2*p][1], bh[2*p+1][1], bb);
                LDSM4(bl[2*p][0], bl[2*p+1][0], bl[2*p][1], bl[2*p+1][1], bb + loK);
            }
            #pragma unroll
            for (int mt = 0; mt < 2; mt++)
                #pragma unroll
                for (int nt = 0; nt < 8; nt++) {
                    mma_bf16(s[mt][nt], ah[mt], bh[nt]);
                    mma_bf16(s[mt][nt], ah[mt], bl[nt]);
                    mma_bf16(s[mt][nt], al[mt], bh[nt]);
                }
        }

        // ---- exp, denominators, pack P to split-bf16 in regs ----
        uint32_t ph[2][8][2], pl[2][8][2];
        #pragma unroll
        for (int mt = 0; mt < 2; mt++) {
            float d0 = 0.f, d1 = 0.f;
            #pragma unroll
            for (int nt = 0; nt < 8; nt++) {
                float p0 = __expf(fminf(s[mt][nt][0], 75.f));
                float p1 = __expf(fminf(s[mt][nt][1], 75.f));
                float p2 = __expf(fminf(s[mt][nt][2], 75.f));
                float p3 = __expf(fminf(s[mt][nt][3], 75.f));
                d0 += p0 + p1;
                d1 += p2 + p3;
                __nv_bfloat16 h0, l0, h1, l1, h2, l2, h3, l3;
                split2(p0, h0, l0); split2(p1, h1, l1);
                split2(p2, h2, l2); split2(p3, h3, l3);
                ph[mt][nt][0] = packbf(h0, h1);
                ph[mt][nt][1] = packbf(h2, h3);
                pl[mt][nt][0] = packbf(l0, l1);
                pl[mt][nt][1] = packbf(l2, l3);
            }
            d0 += __shfl_xor_sync(0xffffffffu, d0, 1);
            d0 += __shfl_xor_sync(0xffffffffu, d0, 2);
            d1 += __shfl_xor_sync(0xffffffffu, d1, 1);
            d1 += __shfl_xor_sync(0xffffffffu, d1, 2);
            denomAcc[mt][0] += d0;
            denomAcc[mt][1] += d1;
        }

        // ---- O += P @ V^T ----
        #pragma unroll
        for (int ks = 0; ks < 4; ks++) {
            uint32_t kof = (uint32_t)(ks * 16 + lhalf * 8) * 2;
            uint32_t bvh[8][2], bvl[8][2];
            #pragma unroll
            for (int p = 0; p < 4; p++) {
                uint32_t bb = vBase + (uint32_t)((p * 16 + lrow) * APAD) * 2 + kof;
                LDSM4(bvh[2*p][0], bvh[2*p+1][0], bvh[2*p][1], bvh[2*p+1][1], bb);
                LDSM4(bvl[2*p][0], bvl[2*p+1][0], bvl[2*p][1], bvl[2*p+1][1], bb + loK);
            }
            #pragma unroll
            for (int mt = 0; mt < 2; mt++) {
                uint32_t ah4[4] = { ph[mt][2*ks][0], ph[mt][2*ks][1],
                                    ph[mt][2*ks+1][0], ph[mt][2*ks+1][1] };
                uint32_t al4[4] = { pl[mt][2*ks][0], pl[mt][2*ks][1],
                                    pl[mt][2*ks+1][0], pl[mt][2*ks+1][1] };
                #pragma unroll
                for (int nt = 0; nt < 8; nt++) {
                    mma_bf16(o[mt][nt], ah4, bvh[nt]);
                    mma_bf16(o[mt][nt], ah4, bvl[nt]);
                    mma_bf16(o[mt][nt], al4, bvh[nt]);
                }
            }
        }
    }

    // ---- epilogue ----
    #pragma unroll
    for (int mt = 0; mt < 2; mt++) {
        #pragma unroll
        for (int half = 0; half < 2; half++) {
            float inv = 1.f / denomAcc[mt][half];
            int tokout = b * LL + n * 256 + wid * 32 + mt * 16 + quad + half * 8;
            size_t rowb = (size_t)tokout * DD + h * 64;
            #pragma unroll
            for (int nt = 0; nt < 8; nt++) {
                float v0 = o[mt][nt][half * 2 + 0] * inv;
                float v1 = o[mt][nt][half * 2 + 1] * inv;
                __nv_bfloat16 h0, l0, h1, l1;
                split2(v0, h0, l0);
                split2(v1, h1, l1);
                int col = nt * 8 + tq * 2;
                *(uint32_t*)&oh[rowb + col] = packbf(h0, h1);
                *(uint32_t*)&ol[rowb + col] = packbf(l0, l1);
            }
        }
    }
}

// ---------------- gating ----------------
__global__ void gate_kernel(const float* __restrict__ X, const float* __restrict__ Wg,
                            const float* __restrict__ bg) {
    int tok = blockIdx.x;
    int tid = threadIdx.x;
    int warp = tid >> 5, lane = tid & 31;
    const float* xr = X + (size_t)tok * DD;
    float part = 0.f;
    for (int d = lane; d < DD; d += 32) part += xr[d] * Wg[d * EE + warp];
    #pragma unroll
    for (int o = 16; o > 0; o >>= 1) part += __shfl_down_sync(0xffffffffu, part, o);
    __shared__ float logits[EE];
    if (lane == 0) logits[warp] = part + bg[warp];
    __syncthreads();
    if (tid == 0) {
        float l[EE], m = -3.4e38f;
        #pragma unroll
        for (int e = 0; e < EE; e++) { l[e] = logits[e]; m = fmaxf(m, l[e]); }
        float p[EE], s = 0.f;
        #pragma unroll
        for (int e = 0; e < EE; e++) { p[e] = __expf(l[e] - m); s += p[e]; }
        float invs = 1.f / s, ent = 0.f;
        #pragma unroll
        for (int e = 0; e < EE; e++) {
            p[e] *= invs;
            ent -= p[e] * logf(p[e] + 1e-8f);
        }
        atomicAdd(&g_entsum, ent);
        int i1 = 0;
        #pragma unroll
        for (int e = 1; e < EE; e++) if (p[e] > p[i1]) i1 = e;
        int i2 = (i1 == 0) ? 1 : 0;
        #pragma unroll
        for (int e = 0; e < EE; e++) if (e != i1 && p[e] > p[i2]) i2 = e;
        int s1 = atomicAdd(&g_ecount[i1], 1);
        g_etok[i1 * NTOK + s1] = tok; g_ewt[i1 * NTOK + s1] = p[i1];
        int s2 = atomicAdd(&g_ecount[i2], 1);
        g_etok[i2 * NTOK + s2] = tok; g_ewt[i2 * NTOK + s2] = p[i2];
    }
}

// ---------------- aux scalar ----------------
__global__ void aux_kernel(float* __restrict__ out, long long out_size) {
    if (threadIdx.x == 0 && blockIdx.x == 0) {
        float pen = 0.f;
        #pragma unroll
        for (int e = 0; e < EE; e++) {
            float usage = (float)g_ecount[e] / ((float)NTOK + 1e-8f);
            pen += fmaxf(usage - 0.4f, 0.f);
        }
        float ent = g_entsum / (float)NTOK;
        float aux = 0.05f * ent + pen;
        long long total = (long long)NTOK * HID;
        if (out_size > total) out[total] = aux;
    }
}

// ---------------- launch ----------------
extern "C" void kernel_launch(void* const* d_in, const int* in_sizes, int n_in,
                              void* d_out, int out_size) {
    const float* x     = (const float*)d_in[0];
    const float* Wq    = (const float*)d_in[1];
    const float* bq    = (const float*)d_in[2];
    const float* Wk    = (const float*)d_in[3];
    const float* bk    = (const float*)d_in[4];
    const float* Wv    = (const float*)d_in[5];
    const float* bv    = (const float*)d_in[6];
    const float* Wo    = (const float*)d_in[7];
    const float* bo    = (const float*)d_in[8];
    const float* ln1_g = (const float*)d_in[9];
    const float* ln1_b = (const float*)d_in[10];
    const float* ln2_g = (const float*)d_in[11];
    const float* ln2_b = (const float*)d_in[12];
    const float* Wg    = (const float*)d_in[13];
    const float* bg    = (const float*)d_in[14];
    const float* We    = (const float*)d_in[15];
    const float* be    = (const float*)d_in[16];
    float* out = (float*)d_out;

    __nv_bfloat16 *ln1h, *ln1l, *atth, *attl, *ln2h, *ln2l;
    __nv_bfloat16 *wqkvh, *wqkvl, *woth, *wotl, *weth, *wetl;
    float *qkv, *ln2f, *bqkv;
    cudaGetSymbolAddress((void**)&ln1h, g_ln1h);
    cudaGetSymbolAddress((void**)&ln1l, g_ln1l);
    cudaGetSymbolAddress((void**)&qkv,  g_qkv);
    cudaGetSymbolAddress((void**)&atth, g_atth);
    cudaGetSymbolAddress((void**)&attl, g_attl);
    cudaGetSymbolAddress((void**)&ln2f, g_ln2f);
    cudaGetSymbolAddress((void**)&ln2h, g_ln2h);
    cudaGetSymbolAddress((void**)&ln2l, g_ln2l);
    cudaGetSymbolAddress((void**)&wqkvh, g_wqkvh);
    cudaGetSymbolAddress((void**)&wqkvl, g_wqkvl);
    cudaGetSymbolAddress((void**)&woth, g_woth);
    cudaGetSymbolAddress((void**)&wotl, g_wotl);
    cudaGetSymbolAddress((void**)&weth, g_weth);
    cudaGetSymbolAddress((void**)&wetl, g_wetl);
    cudaGetSymbolAddress((void**)&bqkv, g_bqkv);

    const int ASM = (256*2 + 64*2 + 64*2) * APAD * 2;   // 110592
    cudaFuncSetAttribute(attn_kernel, cudaFuncAttributeMaxDynamicSharedMemorySize, ASM);
    cudaFuncSetAttribute(tc_gemm<0>, cudaFuncAttributeMaxDynamicSharedMemorySize, GSMEM);
    cudaFuncSetAttribute(tc_gemm<2>, cudaFuncAttributeMaxDynamicSharedMemorySize, GSMEM);
    cudaFuncSetAttribute(tc_gemm<3>, cudaFuncAttributeMaxDynamicSharedMemorySize, GSMEM);

    zero_kernel<<<1, 32>>>();

    dim3 tb(32, 8);
    transpose_kernel<<<dim3(32, 32), tb>>>(Wq, wqkvh, wqkvl, DD, DD, 0, 0, 0);
    transpose_kernel<<<dim3(4, 32),  tb>>>(Wk, wqkvh, wqkvl, DD, KVD, 0, 0, DD);
    transpose_kernel<<<dim3(4, 32),  tb>>>(Wv, wqkvh, wqkvl, DD, KVD, 0, 0, DD + KVD);
    transpose_kernel<<<dim3(32, 32), tb>>>(Wo, woth, wotl, DD, DD, 0, 0, 0);
    transpose_kernel<<<dim3(32, 32, EE), tb>>>(We, weth, wetl, DD, HID,
                                               (size_t)DD * HID, (size_t)DD * HID, 0);
    bqkv_kernel<<<(QKVC + 255) / 256, 256>>>(bq, bk, bv);

    ln_kernel<<<NTOK, 256>>>(x, ln1_g, ln1_b, ln1h, ln1l, nullptr);

    tc_gemm<0><<<dim3(10, 64), 128, GSMEM>>>(ln1h, ln1l, wqkvh, wqkvl, bqkv, nullptr,
                                             qkv, QKVC);

    attn_kernel<<<dim3(NWIN, HH, BB), 256, ASM>>>(qkv, atth, attl);

    // out = x + attn@Wo + bo  (h lives only in d_out)
    tc_gemm<2><<<dim3(8, 64), 128, GSMEM>>>(atth, attl, woth, wotl, bo, x, out, DD);

    ln_kernel<<<NTOK, 256>>>(out, ln2_g, ln2_b, ln2h, ln2l, ln2f);
    gate_kernel<<<NTOK, 256>>>(ln2f, Wg, bg);

    tc_gemm<3><<<dim3(8, 64, EE), 128, GSMEM>>>(ln2h, ln2l, weth, wetl, be, nullptr,
                                                out, HID);

    aux_kernel<<<1, 32>>>(out, (long long)out_size);
}

// round 8
// speedup vs baseline: 1.0403x; 1.0403x over previous
#include <cuda_runtime.h>
#include <cuda_bf16.h>
#include <math.h>
#include <stdint.h>

// Problem constants
#define BB 2
#define LL 4096
#define DD 1024
#define HH 16
#define GG 2
#define HD 64
#define KVD 128
#define KVC 256
#define QKVC 1280        // Q(1024) | K(128) | V(128)
#define EE 8
#define HID 1024
#define NTOK (BB*LL)     // 8192
#define NWIN 16
#define WIN 256
#define TCK 32           // K-chunk (32 bf16 columns per stage)
#define NCH (DD/TCK)     // 32 chunks
#define BSTR 40          // padded smem row stride (80B = 5x16B odd -> ldmatrix conflict-free)
#define TILE (128*BSTR)
#define TILEB (TILE*2)
#define BUFB (4*TILEB)   // one stage = Ah|Al|Bh|Bl = 40960 bytes
#define GSMEM (2*BUFB)   // 81920 bytes -> 2 CTAs/SM
#define APAD 72          // attention smem row stride (144B = 9x16B odd)

// ---------------- scratch (static device globals) ----------------
__device__ __nv_bfloat16 g_ln1h[NTOK*DD];
__device__ __nv_bfloat16 g_ln1l[NTOK*DD];
__device__ float         g_qkv [NTOK*QKVC];
__device__ __nv_bfloat16 g_atth[NTOK*DD];
__device__ __nv_bfloat16 g_attl[NTOK*DD];
__device__ __nv_bfloat16 g_ln2h[NTOK*DD];
__device__ __nv_bfloat16 g_ln2l[NTOK*DD];
__device__ __nv_bfloat16 g_wqkvh[QKVC*DD], g_wqkvl[QKVC*DD];
__device__ __nv_bfloat16 g_woth[DD*DD],  g_wotl[DD*DD];
__device__ __nv_bfloat16 g_weth[EE*DD*HID], g_wetl[EE*DD*HID];
__device__ float g_bqkv[QKVC];
__device__ int   g_ecount[EE];
__device__ float g_entsum;
__device__ int   g_etok[EE*NTOK];
__device__ float g_ewt [EE*NTOK];

// ---------------- helpers ----------------
__device__ __forceinline__ uint32_t su32(const void* p) {
    uint32_t r;
    asm("{ .reg .u64 t; cvta.to.shared.u64 t, %1; cvt.u32.u64 %0, t; }" : "=r"(r) : "l"(p));
    return r;
}
__device__ __forceinline__ void split2(float x, __nv_bfloat16& h, __nv_bfloat16& l) {
    h = __float2bfloat16_rn(x);
    l = __float2bfloat16_rn(x - __bfloat162float(h));
}
#define CP16(dst, src) asm volatile("cp.async.cg.shared.global [%0], [%1], 16;" :: "r"(dst), "l"(src))
#define CP_COMMIT()    asm volatile("cp.async.commit_group;" ::: "memory")
#define CP_WAIT0()     asm volatile("cp.async.wait_group 0;" ::: "memory")
#define CP_WAIT1()     asm volatile("cp.async.wait_group 1;" ::: "memory")

#define LDSM4(r0, r1, r2, r3, addr) \
    asm volatile("ldmatrix.sync.aligned.m8n8.x4.shared.b16 {%0,%1,%2,%3}, [%4];" \
                 : "=r"(r0), "=r"(r1), "=r"(r2), "=r"(r3) : "r"(addr))

__device__ __forceinline__ void mma_bf16(float* c, const uint32_t* a, const uint32_t* b) {
    asm volatile(
        "mma.sync.aligned.m16n8k16.row.col.f32.bf16.bf16.f32 "
        "{%0,%1,%2,%3}, {%4,%5,%6,%7}, {%8,%9}, {%0,%1,%2,%3};"
        : "+f"(c[0]), "+f"(c[1]), "+f"(c[2]), "+f"(c[3])
        : "r"(a[0]), "r"(a[1]), "r"(a[2]), "r"(a[3]), "r"(b[0]), "r"(b[1]));
}
__device__ __forceinline__ uint32_t packbf(__nv_bfloat16 lo, __nv_bfloat16 hi) {
    return (uint32_t)__bfloat16_as_ushort(lo) | ((uint32_t)__bfloat16_as_ushort(hi) << 16);
}

// ---------------- zero bookkeeping ----------------
__global__ void zero_kernel() {
    int t = threadIdx.x;
    if (t < EE) g_ecount[t] = 0;
    if (t == EE) g_entsum = 0.f;
}

// ---------------- fused weight transpose + bf16 split (one launch) --------
// blocks: [0,1024) Wq | [1024,1152) Wk | [1152,1280) Wv | [1280,2304) Wo |
//         [2304,10496) We (1024 per expert)
__global__ void __launch_bounds__(256)
transpose_all(const float* __restrict__ Wq, const float* __restrict__ Wk,
              const float* __restrict__ Wv, const float* __restrict__ Wo,
              const float* __restrict__ We) {
    __shared__ float t[32][33];
    int bid = blockIdx.x;
    const float* src;
    __nv_bfloat16 *dh, *dl;
    int cols, rowOff, bx, by;
    size_t dstOff = 0;
    if (bid < 1024) {
        src = Wq; dh = g_wqkvh; dl = g_wqkvl; cols = DD; rowOff = 0;
        bx = bid & 31; by = bid >> 5;
    } else if (bid < 1152) {
        int r = bid - 1024;
        src = Wk; dh = g_wqkvh; dl = g_wqkvl; cols = KVD; rowOff = DD;
        bx = r & 3; by = r >> 2;
    } else if (bid < 1280) {
        int r = bid - 1152;
        src = Wv; dh = g_wqkvh; dl = g_wqkvl; cols = KVD; rowOff = DD + KVD;
        bx = r & 3; by = r >> 2;
    } else if (bid < 2304) {
        int r = bid - 1280;
        src = Wo; dh = g_woth; dl = g_wotl; cols = DD; rowOff = 0;
        bx = r & 31; by = r >> 5;
    } else {
        int r = bid - 2304;
        int e = r >> 10; r &= 1023;
        src = We + (size_t)e * DD * HID;
        dh = g_weth; dl = g_wetl; dstOff = (size_t)e * DD * HID;
        cols = HID; rowOff = 0;
        bx = r & 31; by = r >> 5;
    }
    int c0 = bx * 32, r0 = by * 32;
    int tx = threadIdx.x, ty = threadIdx.y;
    #pragma unroll
    for (int i = 0; i < 32; i += 8)
        t[ty + i][tx] = src[(size_t)(r0 + ty + i) * cols + c0 + tx];
    __syncthreads();
    #pragma unroll
    for (int i = 0; i < 32; i += 8) {
        __nv_bfloat16 h, l;
        split2(t[tx][ty + i], h, l);
        size_t o = dstOff + (size_t)(c0 + ty + i + rowOff) * DD + r0 + tx;
        dh[o] = h;
        dl[o] = l;
    }
}

__global__ void bqkv_kernel(const float* __restrict__ bq, const float* __restrict__ bk,
                            const float* __restrict__ bv) {
    int t = threadIdx.x + blockIdx.x * 256;
    if (t < DD) g_bqkv[t] = bq[t];
    else if (t < DD + KVD) g_bqkv[t] = bk[t - DD];
    else if (t < QKVC) g_bqkv[t] = bv[t - DD - KVD];
}

// ---------------- LayerNorm (split-bf16 output) ----------
__global__ void ln_kernel(const float* __restrict__ x, const float* __restrict__ g,
                          const float* __restrict__ b,
                          __nv_bfloat16* __restrict__ yh, __nv_bfloat16* __restrict__ yl) {
    int row = blockIdx.x;
    const float4* xr = (const float4*)(x + (size_t)row * DD);
    int tid = threadIdx.x;
    float4 v = xr[tid];
    float s  = v.x + v.y + v.z + v.w;
    float ss = v.x*v.x + v.y*v.y + v.z*v.z + v.w*v.w;
    #pragma unroll
    for (int o = 16; o > 0; o >>= 1) {
        s  += __shfl_down_sync(0xffffffffu, s,  o);
        ss += __shfl_down_sync(0xffffffffu, ss, o);
    }
    __shared__ float sh_s[8], sh_ss[8];
    __shared__ float s_mean, s_rstd;
    int warp = tid >> 5, lane = tid & 31;
    if (lane == 0) { sh_s[warp] = s; sh_ss[warp] = ss; }
    __syncthreads();
    if (tid == 0) {
        float S = 0.f, SS = 0.f;
        #pragma unroll
        for (int i = 0; i < 8; i++) { S += sh_s[i]; SS += sh_ss[i]; }
        float mean = S / (float)DD;
        float var  = SS / (float)DD - mean * mean;
        s_mean = mean;
        s_rstd = rsqrtf(var + 1e-5f);
    }
    __syncthreads();
    float mean = s_mean, rstd = s_rstd;
    float4 gg = ((const float4*)g)[tid];
    float4 bb = ((const float4*)b)[tid];
    float o[4];
    o[0] = (v.x - mean) * rstd * gg.x + bb.x;
    o[1] = (v.y - mean) * rstd * gg.y + bb.y;
    o[2] = (v.z - mean) * rstd * gg.z + bb.z;
    o[3] = (v.w - mean) * rstd * gg.w + bb.w;
    size_t base = (size_t)row * DD + tid * 4;
    __nv_bfloat16 hh[4], ll[4];
    #pragma unroll
    for (int i = 0; i < 4; i++) split2(o[i], hh[i], ll[i]);
    *(uint2*)&yh[base] = *(uint2*)hh;
    *(uint2*)&yl[base] = *(uint2*)ll;
}

// ---------------- LN2 + MoE gate fused ----------------
// Same LN as above, plus: logits = ln_out @ Wg + bg computed from registers,
// softmax / entropy / top-2 routing done in-block (thread 0 tail).
__global__ void ln2_gate_kernel(const float* __restrict__ x, const float* __restrict__ g,
                                const float* __restrict__ b,
                                const float* __restrict__ Wg, const float* __restrict__ bg,
                                __nv_bfloat16* __restrict__ yh, __nv_bfloat16* __restrict__ yl) {
    int row = blockIdx.x;
    const float4* xr = (const float4*)(x + (size_t)row * DD);
    int tid = threadIdx.x;
    float4 v = xr[tid];
    float s  = v.x + v.y + v.z + v.w;
    float ss = v.x*v.x + v.y*v.y + v.z*v.z + v.w*v.w;
    #pragma unroll
    for (int o = 16; o > 0; o >>= 1) {
        s  += __shfl_down_sync(0xffffffffu, s,  o);
        ss += __shfl_down_sync(0xffffffffu, ss, o);
    }
    __shared__ float sh_s[8], sh_ss[8];
    __shared__ float s_mean, s_rstd;
    __shared__ float red[8][8];
    int warp = tid >> 5, lane = tid & 31;
    if (lane == 0) { sh_s[warp] = s; sh_ss[warp] = ss; }
    __syncthreads();
    if (tid == 0) {
        float S = 0.f, SS = 0.f;
        #pragma unroll
        for (int i = 0; i < 8; i++) { S += sh_s[i]; SS += sh_ss[i]; }
        float mean = S / (float)DD;
        float var  = SS / (float)DD - mean * mean;
        s_mean = mean;
        s_rstd = rsqrtf(var + 1e-5f);
    }
    __syncthreads();
    float mean = s_mean, rstd = s_rstd;
    float4 gg = ((const float4*)g)[tid];
    float4 bb = ((const float4*)b)[tid];
    float o[4];
    o[0] = (v.x - mean) * rstd * gg.x + bb.x;
    o[1] = (v.y - mean) * rstd * gg.y + bb.y;
    o[2] = (v.z - mean) * rstd * gg.z + bb.z;
    o[3] = (v.w - mean) * rstd * gg.w + bb.w;
    size_t base = (size_t)row * DD + tid * 4;
    __nv_bfloat16 hh[4], ll[4];
    #pragma unroll
    for (int i = 0; i < 4; i++) split2(o[i], hh[i], ll[i]);
    *(uint2*)&yh[base] = *(uint2*)hh;
    *(uint2*)&yl[base] = *(uint2*)ll;

    // ---- gating: logits from in-register LN output ----
    float pr[EE];
    #pragma unroll
    for (int e = 0; e < EE; e++) pr[e] = 0.f;
    #pragma unroll
    for (int i = 0; i < 4; i++) {
        float4 w0 = ((const float4*)Wg)[(tid * 4 + i) * 2];
        float4 w1 = ((const float4*)Wg)[(tid * 4 + i) * 2 + 1];
        pr[0] += o[i] * w0.x; pr[1] += o[i] * w0.y;
        pr[2] += o[i] * w0.z; pr[3] += o[i] * w0.w;
        pr[4] += o[i] * w1.x; pr[5] += o[i] * w1.y;
        pr[6] += o[i] * w1.z; pr[7] += o[i] * w1.w;
    }
    #pragma unroll
    for (int off = 16; off > 0; off >>= 1)
        #pragma unroll
        for (int e = 0; e < EE; e++)
            pr[e] += __shfl_down_sync(0xffffffffu, pr[e], off);
    if (lane == 0)
        #pragma unroll
        for (int e = 0; e < EE; e++) red[warp][e] = pr[e];
    __syncthreads();
    if (tid == 0) {
        float l[EE], m = -3.4e38f;
        #pragma unroll
        for (int e = 0; e < EE; e++) {
            float sum = bg[e];
            #pragma unroll
            for (int w = 0; w < 8; w++) sum += red[w][e];
            l[e] = sum;
            m = fmaxf(m, sum);
        }
        float p[EE], sm = 0.f;
        #pragma unroll
        for (int e = 0; e < EE; e++) { p[e] = __expf(l[e] - m); sm += p[e]; }
        float invs = 1.f / sm, ent = 0.f;
        #pragma unroll
        for (int e = 0; e < EE; e++) {
            p[e] *= invs;
            ent -= p[e] * logf(p[e] + 1e-8f);
        }
        atomicAdd(&g_entsum, ent);
        int i1 = 0;
        #pragma unroll
        for (int e = 1; e < EE; e++) if (p[e] > p[i1]) i1 = e;
        int i2 = (i1 == 0) ? 1 : 0;
        #pragma unroll
        for (int e = 0; e < EE; e++) if (e != i1 && p[e] > p[i2]) i2 = e;
        int s1 = atomicAdd(&g_ecount[i1], 1);
        g_etok[i1 * NTOK + s1] = row; g_ewt[i1 * NTOK + s1] = p[i1];
        int s2 = atomicAdd(&g_ecount[i2], 1);
        g_etok[i2 * NTOK + s2] = row; g_ewt[i2 * NTOK + s2] = p[i2];
    }
}

// ---------------- bf16x3 mma.sync GEMM (round-6 config: 256 thr, 2Mx4N) ----
// Tile 128x128, K = DD in 32 chunks of 32. 8 warps, warp tile 64x32,
// 3 split passes (hh, hl, lh). 2-stage cp.async, 2 CTA/SM.
// MODE 0: C = acc + bias
// MODE 2: C = acc + bias + resid
// MODE 3: MoE gathered rows; atomicAdd(C[tok*ldc+c], wt*(acc + bias[c]))
template<int MODE>
__global__ void __launch_bounds__(256)
tc_gemm(const __nv_bfloat16* __restrict__ Ah, const __nv_bfloat16* __restrict__ Al,
        const __nv_bfloat16* __restrict__ Bh, const __nv_bfloat16* __restrict__ Bl,
        const float* __restrict__ bias, const float* __restrict__ resid,
        float* __restrict__ C, int ldc) {
    __shared__ int   stok[128];
    __shared__ float swt[128];
    extern __shared__ __nv_bfloat16 smb[];

    int row0 = blockIdx.y * 128;
    int col0 = blockIdx.x * 128;
    int tid = threadIdx.x, wid = tid >> 5, lane = tid & 31;
    int quad = lane >> 2, tq = lane & 3;
    int wm = wid & 1, wn = wid >> 1;

    if (MODE == 3) {
        int e = blockIdx.z;
        int cnt = g_ecount[e];
        if (row0 >= cnt) return;
        Bh   += (size_t)e * DD * HID;
        Bl   += (size_t)e * DD * HID;
        bias += (size_t)e * HID;
        if (tid < 128) {
            int r = row0 + tid;
            if (r < cnt) { stok[tid] = g_etok[e * NTOK + r]; swt[tid] = g_ewt[e * NTOK + r]; }
            else         { stok[tid] = -1; swt[tid] = 0.f; }
        }
        __syncthreads();
    }

    int crow = tid >> 2;
    int seg  = tid & 3;
    const __nv_bfloat16 *sa_h[2], *sa_l[2], *sb_h[2], *sb_l[2];
    uint32_t doff[2];
    #pragma unroll
    for (int i = 0; i < 2; i++) {
        int r = crow + 64 * i;
        int tok;
        if (MODE == 3) { tok = stok[r]; if (tok < 0) tok = 0; }
        else           tok = row0 + r;
        sa_h[i] = Ah + (size_t)tok * DD + seg * 8;
        sa_l[i] = Al + (size_t)tok * DD + seg * 8;
        sb_h[i] = Bh + (size_t)(col0 + r) * DD + seg * 8;
        sb_l[i] = Bl + (size_t)(col0 + r) * DD + seg * 8;
        doff[i] = (uint32_t)(r * (BSTR * 2) + seg * 16);
    }
    uint32_t sbase = su32(smb);

    int lrow = lane & 15, lhalf = lane >> 4;
    uint32_t aLane = (uint32_t)(((wm * 64 + lrow) * BSTR + lhalf * 8) * 2);
    uint32_t bLane = (uint32_t)(((wn * 32 + lrow) * BSTR + lhalf * 8) * 2);

    float acc[4][4][4];
    #pragma unroll
    for (int mt = 0; mt < 4; mt++)
        #pragma unroll
        for (int nt = 0; nt < 4; nt++)
            #pragma unroll
            for (int i = 0; i < 4; i++) acc[mt][nt][i] = 0.f;

    #pragma unroll
    for (int i = 0; i < 2; i++) {
        CP16(sbase + 0 * TILEB + doff[i], sa_h[i]);
        CP16(sbase + 1 * TILEB + doff[i], sa_l[i]);
        CP16(sbase + 2 * TILEB + doff[i], sb_h[i]);
        CP16(sbase + 3 * TILEB + doff[i], sb_l[i]);
    }
    CP_COMMIT();

    for (int c = 0; c < NCH; c++) {
        int b = c & 1, nb = b ^ 1;
        if (c + 1 < NCH) {
            int k0 = (c + 1) * TCK;
            uint32_t base = sbase + (nb ? BUFB : 0u);
            #pragma unroll
            for (int i = 0; i < 2; i++) {
                CP16(base + 0 * TILEB + doff[i], sa_h[i] + k0);
                CP16(base + 1 * TILEB + doff[i], sa_l[i] + k0);
                CP16(base + 2 * TILEB + doff[i], sb_h[i] + k0);
                CP16(base + 3 * TILEB + doff[i], sb_l[i] + k0);
            }
            CP_COMMIT();
            CP_WAIT1();
        } else {
            CP_WAIT0();
        }
        __syncthreads();

        uint32_t sb = sbase + (b ? BUFB : 0u);
        #pragma unroll
        for (int kk = 0; kk < 2; kk++) {
            uint32_t kof = kk * 16 * 2;
            uint32_t bh[4][2], bl[4][2];
            uint32_t bb0 = sb + 2 * TILEB + bLane + kof;
            LDSM4(bh[0][0], bh[1][0], bh[0][1], bh[1][1], bb0);
            LDSM4(bh[2][0], bh[3][0], bh[2][1], bh[3][1], bb0 + 16 * BSTR * 2);
            uint32_t bb1 = sb + 3 * TILEB + bLane + kof;
            LDSM4(bl[0][0], bl[1][0], bl[0][1], bl[1][1], bb1);
            LDSM4(bl[2][0], bl[3][0], bl[2][1], bl[3][1], bb1 + 16 * BSTR * 2);
            #pragma unroll
            for (int mt = 0; mt < 4; mt++) {
                uint32_t ah[4], al[4];
                uint32_t aa = sb + aLane + kof + mt * 16 * BSTR * 2;
                LDSM4(ah[0], ah[1], ah[2], ah[3], aa);
                LDSM4(al[0], al[1], al[2], al[3], aa + TILEB);
                #pragma unroll
                for (int nt = 0; nt < 4; nt++) {
                    mma_bf16(acc[mt][nt], ah, bh[nt]);
                    mma_bf16(acc[mt][nt], ah, bl[nt]);
                    mma_bf16(acc[mt][nt], al, bh[nt]);
                }
            }
        }
        __syncthreads();
    }

    #pragma unroll
    for (int mt = 0; mt < 4; mt++) {
        #pragma unroll
        for (int half = 0; half < 2; half++) {
            int lr = wm * 64 + mt * 16 + quad + half * 8;
            int r = row0 + lr;
            #pragma unroll
            for (int nt = 0; nt < 4; nt++) {
                int col = col0 + wn * 32 + nt * 8 + tq * 2;
                float v0 = acc[mt][nt][half * 2 + 0] + bias[col];
                float v1 = acc[mt][nt][half * 2 + 1] + bias[col + 1];
                if (MODE == 0) {
                    *(float2*)&C[(size_t)r * ldc + col] = make_float2(v0, v1);
                } else if (MODE == 2) {
                    size_t o = (size_t)r * ldc + col;
                    float2 rr = *(const float2*)&resid[o];
                    *(float2*)&C[o] = make_float2(v0 + rr.x, v1 + rr.y);
                } else {
                    int tok = stok[lr];
                    if (tok >= 0) {
                        float w = swt[lr];
                        atomicAdd(&C[(size_t)tok * ldc + col],     w * v0);
                        atomicAdd(&C[(size_t)tok * ldc + col + 1], w * v1);
                    }
                }
            }
        }
    }
}

// ---------------- tensor-core attention (bf16x3, single-pass softmax) ------
__global__ void __launch_bounds__(256)
attn_kernel(const float* __restrict__ qkv,
            __nv_bfloat16* __restrict__ oh, __nv_bfloat16* __restrict__ ol) {
    extern __shared__ __nv_bfloat16 sma[];
    __nv_bfloat16* Qh = sma;                  // 256 x APAD
    __nv_bfloat16* Ql = Qh + 256 * APAD;
    __nv_bfloat16* Kh = Ql + 256 * APAD;      // 64 x APAD
    __nv_bfloat16* Kl = Kh + 64 * APAD;
    __nv_bfloat16* Vh = Kl + 64 * APAD;       // transposed: [dim][key] 64 x APAD
    __nv_bfloat16* Vl = Vh + 64 * APAD;

    int n = blockIdx.x, h = blockIdx.y, b = blockIdx.z;
    int g = h & (GG - 1);
    int base = b * LL + n * 128;
    int tid = threadIdx.x, wid = tid >> 5, lane = tid & 31;
    int quad = lane >> 2, tq = lane & 3;
    int lrow = lane & 15, lhalf = lane >> 4;

    {
        const float4* qp = (const float4*)(qkv + (size_t)(base + tid) * QKVC + h * 64);
        #pragma unroll
        for (int c = 0; c < 16; c++) {
            float4 q4 = qp[c];
            float v[4] = {q4.x * 0.125f, q4.y * 0.125f, q4.z * 0.125f, q4.w * 0.125f};
            __nv_bfloat16 hh[4], ll[4];
            #pragma unroll
            for (int i = 0; i < 4; i++) split2(v[i], hh[i], ll[i]);
            *(uint2*)&Qh[tid * APAD + c * 4] = *(uint2*)hh;
            *(uint2*)&Ql[tid * APAD + c * 4] = *(uint2*)ll;
        }
    }

    float o[2][8][4];
    #pragma unroll
    for (int mt = 0; mt < 2; mt++)
        #pragma unroll
        for (int nt = 0; nt < 8; nt++)
            #pragma unroll
            for (int i = 0; i < 4; i++) o[mt][nt][i] = 0.f;
    float denomAcc[2][2] = {{0.f, 0.f}, {0.f, 0.f}};

    uint32_t qBase = su32(Qh), kBase = su32(Kh), vBase = su32(Vh);
    uint32_t loQ = (uint32_t)(256 * APAD * 2);
    uint32_t loK = (uint32_t)(64 * APAD * 2);

    for (int kt = 0; kt < 4; kt++) {
        __syncthreads();
        {
            int r = tid >> 2, sgi = tid & 3;
            const float* kp = qkv + (size_t)(base + kt * 64 + r) * QKVC + DD + g * 64 + sgi * 16;
            #pragma unroll
            for (int c4 = 0; c4 < 4; c4++) {
                float4 kk = *(const float4*)(kp + c4 * 4);
                float kv4[4] = {kk.x, kk.y, kk.z, kk.w};
                __nv_bfloat16 hh[4], ll[4];
                #pragma unroll
                for (int e = 0; e < 4; e++) split2(kv4[e], hh[e], ll[e]);
                *(uint2*)&Kh[r * APAD + sgi * 16 + c4 * 4] = *(uint2*)hh;
                *(uint2*)&Kl[r * APAD + sgi * 16 + c4 * 4] = *(uint2*)ll;
                float4 vv = *(const float4*)(kp + KVD + c4 * 4);
                float va[4] = {vv.x, vv.y, vv.z, vv.w};
                #pragma unroll
                for (int e = 0; e < 4; e++) {
                    __nv_bfloat16 vh_, vl_;
                    split2(va[e], vh_, vl_);
                    int d = sgi * 16 + c4 * 4 + e;
                    Vh[d * APAD + r] = vh_;
                    Vl[d * APAD + r] = vl_;
                }
            }
        }
        __syncthreads();

        float s[2][8][4];
        #pragma unroll
        for (int mt = 0; mt < 2; mt++)
            #pragma unroll
            for (int nt = 0; nt < 8; nt++)
                #pragma unroll
                for (int i = 0; i < 4; i++) s[mt][nt][i] = 0.f;

        #pragma unroll
        for (int ks = 0; ks < 4; ks++) {
            uint32_t kof = (uint32_t)(ks * 16 + lhalf * 8) * 2;
            uint32_t ah[2][4], al[2][4];
            #pragma unroll
            for (int mt = 0; mt < 2; mt++) {
                uint32_t aa = qBase + (uint32_t)((wid * 32 + mt * 16 + lrow) * APAD) * 2 + kof;
                LDSM4(ah[mt][0], ah[mt][1], ah[mt][2], ah[mt][3], aa);
                LDSM4(al[mt][0], al[mt][1], al[mt][2], al[mt][3], aa + loQ);
            }
            uint32_t bh[8][2], bl[8][2];
            #pragma unroll
            for (int p = 0; p < 4; p++) {
                uint32_t bb = kBase + (uint32_t)((p * 16 + lrow) * APAD) * 2 + kof;
                LDSM4(bh[2*p][0], bh[2*p+1][0], bh[2*p][1], bh[2*p+1][1], bb);
                LDSM4(bl[2*p][0], bl[2*p+1][0], bl[2*p][1], bl[2*p+1][1], bb + loK);
            }
            #pragma unroll
            for (int mt = 0; mt < 2; mt++)
                #pragma unroll
                for (int nt = 0; nt < 8; nt++) {
                    mma_bf16(s[mt][nt], ah[mt], bh[nt]);
                    mma_bf16(s[mt][nt], ah[mt], bl[nt]);
                    mma_bf16(s[mt][nt], al[mt], bh[nt]);
                }
        }

        uint32_t ph[2][8][2], pl[2][8][2];
        #pragma unroll
        for (int mt = 0; mt < 2; mt++) {
            float d0 = 0.f, d1 = 0.f;
            #pragma unroll
            for (int nt = 0; nt < 8; nt++) {
                float p0 = __expf(fminf(s[mt][nt][0], 75.f));
                float p1 = __expf(fminf(s[mt][nt][1], 75.f));
                float p2 = __expf(fminf(s[mt][nt][2], 75.f));
                float p3 = __expf(fminf(s[mt][nt][3], 75.f));
                d0 += p0 + p1;
                d1 += p2 + p3;
                __nv_bfloat16 h0, l0, h1, l1, h2, l2, h3, l3;
                split2(p0, h0, l0); split2(p1, h1, l1);
                split2(p2, h2, l2); split2(p3, h3, l3);
                ph[mt][nt][0] = packbf(h0, h1);
                ph[mt][nt][1] = packbf(h2, h3);
                pl[mt][nt][0] = packbf(l0, l1);
                pl[mt][nt][1] = packbf(l2, l3);
            }
            d0 += __shfl_xor_sync(0xffffffffu, d0, 1);
            d0 += __shfl_xor_sync(0xffffffffu, d0, 2);
            d1 += __shfl_xor_sync(0xffffffffu, d1, 1);
            d1 += __shfl_xor_sync(0xffffffffu, d1, 2);
            denomAcc[mt][0] += d0;
            denomAcc[mt][1] += d1;
        }

        #pragma unroll
        for (int ks = 0; ks < 4; ks++) {
            uint32_t kof = (uint32_t)(ks * 16 + lhalf * 8) * 2;
            uint32_t bvh[8][2], bvl[8][2];
            #pragma unroll
            for (int p = 0; p < 4; p++) {
                uint32_t bb = vBase + (uint32_t)((p * 16 + lrow) * APAD) * 2 + kof;
                LDSM4(bvh[2*p][0], bvh[2*p+1][0], bvh[2*p][1], bvh[2*p+1][1], bb);
                LDSM4(bvl[2*p][0], bvl[2*p+1][0], bvl[2*p][1], bvl[2*p+1][1], bb + loK);
            }
            #pragma unroll
            for (int mt = 0; mt < 2; mt++) {
                uint32_t ah4[4] = { ph[mt][2*ks][0], ph[mt][2*ks][1],
                                    ph[mt][2*ks+1][0], ph[mt][2*ks+1][1] };
                uint32_t al4[4] = { pl[mt][2*ks][0], pl[mt][2*ks][1],
                                    pl[mt][2*ks+1][0], pl[mt][2*ks+1][1] };
                #pragma unroll
                for (int nt = 0; nt < 8; nt++) {
                    mma_bf16(o[mt][nt], ah4, bvh[nt]);
                    mma_bf16(o[mt][nt], ah4, bvl[nt]);
                    mma_bf16(o[mt][nt], al4, bvh[nt]);
                }
            }
        }
    }

    #pragma unroll
    for (int mt = 0; mt < 2; mt++) {
        #pragma unroll
        for (int half = 0; half < 2; half++) {
            float inv = 1.f / denomAcc[mt][half];
            int tokout = b * LL + n * 256 + wid * 32 + mt * 16 + quad + half * 8;
            size_t rowb = (size_t)tokout * DD + h * 64;
            #pragma unroll
            for (int nt = 0; nt < 8; nt++) {
                float v0 = o[mt][nt][half * 2 + 0] * inv;
                float v1 = o[mt][nt][half * 2 + 1] * inv;
                __nv_bfloat16 h0, l0, h1, l1;
                split2(v0, h0, l0);
                split2(v1, h1, l1);
                int col = nt * 8 + tq * 2;
                *(uint32_t*)&oh[rowb + col] = packbf(h0, h1);
                *(uint32_t*)&ol[rowb + col] = packbf(l0, l1);
            }
        }
    }
}

// ---------------- aux scalar ----------------
__global__ void aux_kernel(float* __restrict__ out, long long out_size) {
    if (threadIdx.x == 0 && blockIdx.x == 0) {
        float pen = 0.f;
        #pragma unroll
        for (int e = 0; e < EE; e++) {
            float usage = (float)g_ecount[e] / ((float)NTOK + 1e-8f);
            pen += fmaxf(usage - 0.4f, 0.f);
        }
        float ent = g_entsum / (float)NTOK;
        float aux = 0.05f * ent + pen;
        long long total = (long long)NTOK * HID;
        if (out_size > total) out[total] = aux;
    }
}

// ---------------- launch ----------------
extern "C" void kernel_launch(void* const* d_in, const int* in_sizes, int n_in,
                              void* d_out, int out_size) {
    const float* x     = (const float*)d_in[0];
    const float* Wq    = (const float*)d_in[1];
    const float* bq    = (const float*)d_in[2];
    const float* Wk    = (const float*)d_in[3];
    const float* bk    = (const float*)d_in[4];
    const float* Wv    = (const float*)d_in[5];
    const float* bv    = (const float*)d_in[6];
    const float* Wo    = (const float*)d_in[7];
    const float* bo    = (const float*)d_in[8];
    const float* ln1_g = (const float*)d_in[9];
    const float* ln1_b = (const float*)d_in[10];
    const float* ln2_g = (const float*)d_in[11];
    const float* ln2_b = (const float*)d_in[12];
    const float* Wg    = (const float*)d_in[13];
    const float* bg    = (const float*)d_in[14];
    const float* We    = (const float*)d_in[15];
    const float* be    = (const float*)d_in[16];
    float* out = (float*)d_out;

    __nv_bfloat16 *ln1h, *ln1l, *atth, *attl, *ln2h, *ln2l;
    __nv_bfloat16 *wqkvh, *wqkvl, *woth, *wotl, *weth, *wetl;
    float *qkv, *bqkv;
    cudaGetSymbolAddress((void**)&ln1h, g_ln1h);
    cudaGetSymbolAddress((void**)&ln1l, g_ln1l);
    cudaGetSymbolAddress((void**)&qkv,  g_qkv);
    cudaGetSymbolAddress((void**)&atth, g_atth);
    cudaGetSymbolAddress((void**)&attl, g_attl);
    cudaGetSymbolAddress((void**)&ln2h, g_ln2h);
    cudaGetSymbolAddress((void**)&ln2l, g_ln2l);
    cudaGetSymbolAddress((void**)&wqkvh, g_wqkvh);
    cudaGetSymbolAddress((void**)&wqkvl, g_wqkvl);
    cudaGetSymbolAddress((void**)&woth, g_woth);
    cudaGetSymbolAddress((void**)&wotl, g_wotl);
    cudaGetSymbolAddress((void**)&weth, g_weth);
    cudaGetSymbolAddress((void**)&wetl, g_wetl);
    cudaGetSymbolAddress((void**)&bqkv, g_bqkv);

    const int ASM = (256*2 + 64*2 + 64*2) * APAD * 2;   // 110592
    cudaFuncSetAttribute(attn_kernel, cudaFuncAttributeMaxDynamicSharedMemorySize, ASM);
    cudaFuncSetAttribute(tc_gemm<0>, cudaFuncAttributeMaxDynamicSharedMemorySize, GSMEM);
    cudaFuncSetAttribute(tc_gemm<2>, cudaFuncAttributeMaxDynamicSharedMemorySize, GSMEM);
    cudaFuncSetAttribute(tc_gemm<3>, cudaFuncAttributeMaxDynamicSharedMemorySize, GSMEM);

    zero_kernel<<<1, 32>>>();

    transpose_all<<<10496, dim3(32, 8)>>>(Wq, Wk, Wv, Wo, We);
    bqkv_kernel<<<(QKVC + 255) / 256, 256>>>(bq, bk, bv);

    ln_kernel<<<NTOK, 256>>>(x, ln1_g, ln1_b, ln1h, ln1l);

    tc_gemm<0><<<dim3(10, 64), 256, GSMEM>>>(ln1h, ln1l, wqkvh, wqkvl, bqkv, nullptr,
                                             qkv, QKVC);

    attn_kernel<<<dim3(NWIN, HH, BB), 256, ASM>>>(qkv, atth, attl);

    // out = x + attn@Wo + bo
    tc_gemm<2><<<dim3(8, 64), 256, GSMEM>>>(atth, attl, woth, wotl, bo, x, out, DD);

    ln2_gate_kernel<<<NTOK, 256>>>(out, ln2_g, ln2_b, Wg, bg, ln2h, ln2l);

    tc_gemm<3><<<dim3(8, 64, EE), 256, GSMEM>>>(ln2h, ln2l, weth, wetl, be, nullptr,
                                                out, HID);

    aux_kernel<<<1, 32>>>(out, (long long)out_size);
}

// round 9
// speedup vs baseline: 1.2476x; 1.1992x over previous
#include <cuda_runtime.h>
#include <cuda_fp16.h>
#include <math.h>
#include <stdint.h>

// Problem constants
#define BB 2
#define LL 4096
#define DD 1024
#define HH 16
#define GG 2
#define HD 64
#define KVD 128
#define KVC 256
#define QKVC 1280        // Q(1024) | K(128) | V(128)
#define EE 8
#define HID 1024
#define NTOK (BB*LL)     // 8192
#define NWIN 16
#define WIN 256
#define TCK 32           // K-chunk (32 fp16 columns per stage)
#define NCH (DD/TCK)     // 32 chunks
#define BSTR 40          // padded smem row stride (80B = 5x16B odd -> ldmatrix conflict-free)
#define TILE (128*BSTR)
#define TILEB (TILE*2)
#define BUFB (3*TILEB)   // one stage = Ah|Bh|Bl = 30720 bytes
#define GSMEM (2*BUFB)   // 61440 bytes -> 2 CTAs/SM with headroom
#define APAD 72          // attention smem row stride (144B = 9x16B odd)

// ---------------- scratch (static device globals) ----------------
__device__ __half g_ln1 [NTOK*DD];
__device__ float  g_qkv [NTOK*QKVC];
__device__ __half g_att [NTOK*DD];
__device__ __half g_ln2 [NTOK*DD];
__device__ __half g_wqkvh[QKVC*DD], g_wqkvl[QKVC*DD];
__device__ __half g_woth[DD*DD],  g_wotl[DD*DD];
__device__ __half g_weth[EE*DD*HID], g_wetl[EE*DD*HID];
__device__ float g_bqkv[QKVC];
__device__ int   g_ecount[EE];
__device__ float g_entsum;
__device__ int   g_etok[EE*NTOK];
__device__ float g_ewt [EE*NTOK];

// ---------------- helpers ----------------
__device__ __forceinline__ uint32_t su32(const void* p) {
    uint32_t r;
    asm("{ .reg .u64 t; cvta.to.shared.u64 t, %1; cvt.u32.u64 %0, t; }" : "=r"(r) : "l"(p));
    return r;
}
__device__ __forceinline__ void split2h(float x, __half& h, __half& l) {
    h = __float2half_rn(x);
    l = __float2half_rn(x - __half2float(h));
}
#define CP16(dst, src) asm volatile("cp.async.cg.shared.global [%0], [%1], 16;" :: "r"(dst), "l"(src))
#define CP_COMMIT()    asm volatile("cp.async.commit_group;" ::: "memory")
#define CP_WAIT0()     asm volatile("cp.async.wait_group 0;" ::: "memory")
#define CP_WAIT1()     asm volatile("cp.async.wait_group 1;" ::: "memory")

#define LDSM4(r0, r1, r2, r3, addr) \
    asm volatile("ldmatrix.sync.aligned.m8n8.x4.shared.b16 {%0,%1,%2,%3}, [%4];" \
                 : "=r"(r0), "=r"(r1), "=r"(r2), "=r"(r3) : "r"(addr))

__device__ __forceinline__ void mma_f16(float* c, const uint32_t* a, const uint32_t* b) {
    asm volatile(
        "mma.sync.aligned.m16n8k16.row.col.f32.f16.f16.f32 "
        "{%0,%1,%2,%3}, {%4,%5,%6,%7}, {%8,%9}, {%0,%1,%2,%3};"
        : "+f"(c[0]), "+f"(c[1]), "+f"(c[2]), "+f"(c[3])
        : "r"(a[0]), "r"(a[1]), "r"(a[2]), "r"(a[3]), "r"(b[0]), "r"(b[1]));
}
__device__ __forceinline__ uint32_t packh(__half lo, __half hi) {
    return (uint32_t)__half_as_ushort(lo) | ((uint32_t)__half_as_ushort(hi) << 16);
}

// ---------------- zero bookkeeping ----------------
__global__ void zero_kernel() {
    int t = threadIdx.x;
    if (t < EE) g_ecount[t] = 0;
    if (t == EE) g_entsum = 0.f;
}

// ---------------- fused weight transpose + fp16 split (one launch) --------
// blocks: [0,1024) Wq | [1024,1152) Wk | [1152,1280) Wv | [1280,2304) Wo |
//         [2304,10496) We (1024 per expert)
__global__ void __launch_bounds__(256)
transpose_all(const float* __restrict__ Wq, const float* __restrict__ Wk,
              const float* __restrict__ Wv, const float* __restrict__ Wo,
              const float* __restrict__ We) {
    __shared__ float t[32][33];
    int bid = blockIdx.x;
    const float* src;
    __half *dh, *dl;
    int cols, rowOff, bx, by;
    size_t dstOff = 0;
    if (bid < 1024) {
        src = Wq; dh = g_wqkvh; dl = g_wqkvl; cols = DD; rowOff = 0;
        bx = bid & 31; by = bid >> 5;
    } else if (bid < 1152) {
        int r = bid - 1024;
        src = Wk; dh = g_wqkvh; dl = g_wqkvl; cols = KVD; rowOff = DD;
        bx = r & 3; by = r >> 2;
    } else if (bid < 1280) {
        int r = bid - 1152;
        src = Wv; dh = g_wqkvh; dl = g_wqkvl; cols = KVD; rowOff = DD + KVD;
        bx = r & 3; by = r >> 2;
    } else if (bid < 2304) {
        int r = bid - 1280;
        src = Wo; dh = g_woth; dl = g_wotl; cols = DD; rowOff = 0;
        bx = r & 31; by = r >> 5;
    } else {
        int r = bid - 2304;
        int e = r >> 10; r &= 1023;
        src = We + (size_t)e * DD * HID;
        dh = g_weth; dl = g_wetl; dstOff = (size_t)e * DD * HID;
        cols = HID; rowOff = 0;
        bx = r & 31; by = r >> 5;
    }
    int c0 = bx * 32, r0 = by * 32;
    int tx = threadIdx.x, ty = threadIdx.y;
    #pragma unroll
    for (int i = 0; i < 32; i += 8)
        t[ty + i][tx] = src[(size_t)(r0 + ty + i) * cols + c0 + tx];
    __syncthreads();
    #pragma unroll
    for (int i = 0; i < 32; i += 8) {
        __half h, l;
        split2h(t[tx][ty + i], h, l);
        size_t o = dstOff + (size_t)(c0 + ty + i + rowOff) * DD + r0 + tx;
        dh[o] = h;
        dl[o] = l;
    }
}

__global__ void bqkv_kernel(const float* __restrict__ bq, const float* __restrict__ bk,
                            const float* __restrict__ bv) {
    int t = threadIdx.x + blockIdx.x * 256;
    if (t < DD) g_bqkv[t] = bq[t];
    else if (t < DD + KVD) g_bqkv[t] = bk[t - DD];
    else if (t < QKVC) g_bqkv[t] = bv[t - DD - KVD];
}

// ---------------- LayerNorm (fp16 output) ----------
__global__ void ln_kernel(const float* __restrict__ x, const float* __restrict__ g,
                          const float* __restrict__ b, __half* __restrict__ y) {
    int row = blockIdx.x;
    const float4* xr = (const float4*)(x + (size_t)row * DD);
    int tid = threadIdx.x;
    float4 v = xr[tid];
    float s  = v.x + v.y + v.z + v.w;
    float ss = v.x*v.x + v.y*v.y + v.z*v.z + v.w*v.w;
    #pragma unroll
    for (int o = 16; o > 0; o >>= 1) {
        s  += __shfl_down_sync(0xffffffffu, s,  o);
        ss += __shfl_down_sync(0xffffffffu, ss, o);
    }
    __shared__ float sh_s[8], sh_ss[8];
    __shared__ float s_mean, s_rstd;
    int warp = tid >> 5, lane = tid & 31;
    if (lane == 0) { sh_s[warp] = s; sh_ss[warp] = ss; }
    __syncthreads();
    if (tid == 0) {
        float S = 0.f, SS = 0.f;
        #pragma unroll
        for (int i = 0; i < 8; i++) { S += sh_s[i]; SS += sh_ss[i]; }
        float mean = S / (float)DD;
        float var  = SS / (float)DD - mean * mean;
        s_mean = mean;
        s_rstd = rsqrtf(var + 1e-5f);
    }
    __syncthreads();
    float mean = s_mean, rstd = s_rstd;
    float4 gg = ((const float4*)g)[tid];
    float4 bb = ((const float4*)b)[tid];
    float o[4];
    o[0] = (v.x - mean) * rstd * gg.x + bb.x;
    o[1] = (v.y - mean) * rstd * gg.y + bb.y;
    o[2] = (v.z - mean) * rstd * gg.z + bb.z;
    o[3] = (v.w - mean) * rstd * gg.w + bb.w;
    size_t base = (size_t)row * DD + tid * 4;
    uint32_t p0 = packh(__float2half_rn(o[0]), __float2half_rn(o[1]));
    uint32_t p1 = packh(__float2half_rn(o[2]), __float2half_rn(o[3]));
    *(uint2*)&y[base] = make_uint2(p0, p1);
}

// ---------------- LN2 + MoE gate fused ----------------
__global__ void ln2_gate_kernel(const float* __restrict__ x, const float* __restrict__ g,
                                const float* __restrict__ b,
                                const float* __restrict__ Wg, const float* __restrict__ bg,
                                __half* __restrict__ y) {
    int row = blockIdx.x;
    const float4* xr = (const float4*)(x + (size_t)row * DD);
    int tid = threadIdx.x;
    float4 v = xr[tid];
    float s  = v.x + v.y + v.z + v.w;
    float ss = v.x*v.x + v.y*v.y + v.z*v.z + v.w*v.w;
    #pragma unroll
    for (int o = 16; o > 0; o >>= 1) {
        s  += __shfl_down_sync(0xffffffffu, s,  o);
        ss += __shfl_down_sync(0xffffffffu, ss, o);
    }
    __shared__ float sh_s[8], sh_ss[8];
    __shared__ float s_mean, s_rstd;
    __shared__ float red[8][8];
    int warp = tid >> 5, lane = tid & 31;
    if (lane == 0) { sh_s[warp] = s; sh_ss[warp] = ss; }
    __syncthreads();
    if (tid == 0) {
        float S = 0.f, SS = 0.f;
        #pragma unroll
        for (int i = 0; i < 8; i++) { S += sh_s[i]; SS += sh_ss[i]; }
        float mean = S / (float)DD;
        float var  = SS / (float)DD - mean * mean;
        s_mean = mean;
        s_rstd = rsqrtf(var + 1e-5f);
    }
    __syncthreads();
    float mean = s_mean, rstd = s_rstd;
    float4 gg = ((const float4*)g)[tid];
    float4 bb = ((const float4*)b)[tid];
    float o[4];
    o[0] = (v.x - mean) * rstd * gg.x + bb.x;
    o[1] = (v.y - mean) * rstd * gg.y + bb.y;
    o[2] = (v.z - mean) * rstd * gg.z + bb.z;
    o[3] = (v.w - mean) * rstd * gg.w + bb.w;
    size_t base = (size_t)row * DD + tid * 4;
    uint32_t p0 = packh(__float2half_rn(o[0]), __float2half_rn(o[1]));
    uint32_t p1 = packh(__float2half_rn(o[2]), __float2half_rn(o[3]));
    *(uint2*)&y[base] = make_uint2(p0, p1);

    // ---- gating from in-register LN output ----
    float pr[EE];
    #pragma unroll
    for (int e = 0; e < EE; e++) pr[e] = 0.f;
    #pragma unroll
    for (int i = 0; i < 4; i++) {
        float4 w0 = ((const float4*)Wg)[(tid * 4 + i) * 2];
        float4 w1 = ((const float4*)Wg)[(tid * 4 + i) * 2 + 1];
        pr[0] += o[i] * w0.x; pr[1] += o[i] * w0.y;
        pr[2] += o[i] * w0.z; pr[3] += o[i] * w0.w;
        pr[4] += o[i] * w1.x; pr[5] += o[i] * w1.y;
        pr[6] += o[i] * w1.z; pr[7] += o[i] * w1.w;
    }
    #pragma unroll
    for (int off = 16; off > 0; off >>= 1)
        #pragma unroll
        for (int e = 0; e < EE; e++)
            pr[e] += __shfl_down_sync(0xffffffffu, pr[e], off);
    if (lane == 0)
        #pragma unroll
        for (int e = 0; e < EE; e++) red[warp][e] = pr[e];
    __syncthreads();
    if (tid == 0) {
        float l[EE], m = -3.4e38f;
        #pragma unroll
        for (int e = 0; e < EE; e++) {
            float sum = bg[e];
            #pragma unroll
            for (int w = 0; w < 8; w++) sum += red[w][e];
            l[e] = sum;
            m = fmaxf(m, sum);
        }
        float p[EE], sm = 0.f;
        #pragma unroll
        for (int e = 0; e < EE; e++) { p[e] = __expf(l[e] - m); sm += p[e]; }
        float invs = 1.f / sm, ent = 0.f;
        #pragma unroll
        for (int e = 0; e < EE; e++) {
            p[e] *= invs;
            ent -= p[e] * logf(p[e] + 1e-8f);
        }
        atomicAdd(&g_entsum, ent);
        int i1 = 0;
        #pragma unroll
        for (int e = 1; e < EE; e++) if (p[e] > p[i1]) i1 = e;
        int i2 = (i1 == 0) ? 1 : 0;
        #pragma unroll
        for (int e = 0; e < EE; e++) if (e != i1 && p[e] > p[i2]) i2 = e;
        int s1 = atomicAdd(&g_ecount[i1], 1);
        g_etok[i1 * NTOK + s1] = row; g_ewt[i1 * NTOK + s1] = p[i1];
        int s2 = atomicAdd(&g_ecount[i2], 1);
        g_etok[i2 * NTOK + s2] = row; g_ewt[i2 * NTOK + s2] = p[i2];
    }
}

// ---------------- fp16x2 mma.sync GEMM (256 thr, 2Mx4N, 2-pass) ----------
// A single-fp16, B split (Bh, Bl). acc = A*Bh + A*Bl. 2-stage cp.async.
// MODE 0: C = acc + bias
// MODE 2: C = acc + bias + resid
// MODE 3: MoE gathered rows; atomicAdd(C[tok*ldc+c], wt*(acc + bias[c]))
template<int MODE>
__global__ void __launch_bounds__(256)
tc_gemm(const __half* __restrict__ A,
        const __half* __restrict__ Bh, const __half* __restrict__ Bl,
        const float* __restrict__ bias, const float* __restrict__ resid,
        float* __restrict__ C, int ldc) {
    __shared__ int   stok[128];
    __shared__ float swt[128];
    extern __shared__ __half smb[];

    int row0 = blockIdx.y * 128;
    int col0 = blockIdx.x * 128;
    int tid = threadIdx.x, wid = tid >> 5, lane = tid & 31;
    int quad = lane >> 2, tq = lane & 3;
    int wm = wid & 1, wn = wid >> 1;

    if (MODE == 3) {
        int e = blockIdx.z;
        int cnt = g_ecount[e];
        if (row0 >= cnt) return;
        Bh   += (size_t)e * DD * HID;
        Bl   += (size_t)e * DD * HID;
        bias += (size_t)e * HID;
        if (tid < 128) {
            int r = row0 + tid;
            if (r < cnt) { stok[tid] = g_etok[e * NTOK + r]; swt[tid] = g_ewt[e * NTOK + r]; }
            else         { stok[tid] = -1; swt[tid] = 0.f; }
        }
        __syncthreads();
    }

    int crow = tid >> 2;
    int seg  = tid & 3;
    const __half *sa[2], *sbh[2], *sbl[2];
    uint32_t doff[2];
    #pragma unroll
    for (int i = 0; i < 2; i++) {
        int r = crow + 64 * i;
        int tok;
        if (MODE == 3) { tok = stok[r]; if (tok < 0) tok = 0; }
        else           tok = row0 + r;
        sa[i]  = A  + (size_t)tok * DD + seg * 8;
        sbh[i] = Bh + (size_t)(col0 + r) * DD + seg * 8;
        sbl[i] = Bl + (size_t)(col0 + r) * DD + seg * 8;
        doff[i] = (uint32_t)(r * (BSTR * 2) + seg * 16);
    }
    uint32_t sbase = su32(smb);

    int lrow = lane & 15, lhalf = lane >> 4;
    uint32_t aLane = (uint32_t)(((wm * 64 + lrow) * BSTR + lhalf * 8) * 2);
    uint32_t bLane = (uint32_t)(((wn * 32 + lrow) * BSTR + lhalf * 8) * 2);

    float acc[4][4][4];
    #pragma unroll
    for (int mt = 0; mt < 4; mt++)
        #pragma unroll
        for (int nt = 0; nt < 4; nt++)
            #pragma unroll
            for (int i = 0; i < 4; i++) acc[mt][nt][i] = 0.f;

    #pragma unroll
    for (int i = 0; i < 2; i++) {
        CP16(sbase + 0 * TILEB + doff[i], sa[i]);
        CP16(sbase + 1 * TILEB + doff[i], sbh[i]);
        CP16(sbase + 2 * TILEB + doff[i], sbl[i]);
    }
    CP_COMMIT();

    for (int c = 0; c < NCH; c++) {
        int b = c & 1, nb = b ^ 1;
        if (c + 1 < NCH) {
            int k0 = (c + 1) * TCK;
            uint32_t base = sbase + (nb ? BUFB : 0u);
            #pragma unroll
            for (int i = 0; i < 2; i++) {
                CP16(base + 0 * TILEB + doff[i], sa[i] + k0);
                CP16(base + 1 * TILEB + doff[i], sbh[i] + k0);
                CP16(base + 2 * TILEB + doff[i], sbl[i] + k0);
            }
            CP_COMMIT();
            CP_WAIT1();
        } else {
            CP_WAIT0();
        }
        __syncthreads();

        uint32_t sb = sbase + (b ? BUFB : 0u);
        #pragma unroll
        for (int kk = 0; kk < 2; kk++) {
            uint32_t kof = kk * 16 * 2;
            uint32_t bh[4][2], bl[4][2];
            uint32_t bb0 = sb + 1 * TILEB + bLane + kof;
            LDSM4(bh[0][0], bh[1][0], bh[0][1], bh[1][1], bb0);
            LDSM4(bh[2][0], bh[3][0], bh[2][1], bh[3][1], bb0 + 16 * BSTR * 2);
            uint32_t bb1 = sb + 2 * TILEB + bLane + kof;
            LDSM4(bl[0][0], bl[1][0], bl[0][1], bl[1][1], bb1);
            LDSM4(bl[2][0], bl[3][0], bl[2][1], bl[3][1], bb1 + 16 * BSTR * 2);
            #pragma unroll
            for (int mt = 0; mt < 4; mt++) {
                uint32_t ah[4];
                uint32_t aa = sb + aLane + kof + mt * 16 * BSTR * 2;
                LDSM4(ah[0], ah[1], ah[2], ah[3], aa);
                #pragma unroll
                for (int nt = 0; nt < 4; nt++) {
                    mma_f16(acc[mt][nt], ah, bh[nt]);
                    mma_f16(acc[mt][nt], ah, bl[nt]);
                }
            }
        }
        __syncthreads();
    }

    #pragma unroll
    for (int mt = 0; mt < 4; mt++) {
        #pragma unroll
        for (int half = 0; half < 2; half++) {
            int lr = wm * 64 + mt * 16 + quad + half * 8;
            int r = row0 + lr;
            #pragma unroll
            for (int nt = 0; nt < 4; nt++) {
                int col = col0 + wn * 32 + nt * 8 + tq * 2;
                float v0 = acc[mt][nt][half * 2 + 0] + bias[col];
                float v1 = acc[mt][nt][half * 2 + 1] + bias[col + 1];
                if (MODE == 0) {
                    *(float2*)&C[(size_t)r * ldc + col] = make_float2(v0, v1);
                } else if (MODE == 2) {
                    size_t o = (size_t)r * ldc + col;
                    float2 rr = *(const float2*)&resid[o];
                    *(float2*)&C[o] = make_float2(v0 + rr.x, v1 + rr.y);
                } else {
                    int tok = stok[lr];
                    if (tok >= 0) {
                        float w = swt[lr];
                        atomicAdd(&C[(size_t)tok * ldc + col],     w * v0);
                        atomicAdd(&C[(size_t)tok * ldc + col + 1], w * v1);
                    }
                }
            }
        }
    }
}

// ---------------- tensor-core attention (fp16x2, single-pass softmax) ------
// Q, P: fp16 hi only (A side). K, V: fp16 split (B side). 2 mma passes.
__global__ void __launch_bounds__(256)
attn_kernel(const float* __restrict__ qkv, __half* __restrict__ oatt) {
    extern __shared__ __half sma[];
    __half* Qh = sma;                  // 256 x APAD
    __half* Kh = Qh + 256 * APAD;      // 64 x APAD
    __half* Kl = Kh + 64 * APAD;
    __half* Vh = Kl + 64 * APAD;       // transposed: [dim][key]
    __half* Vl = Vh + 64 * APAD;

    int n = blockIdx.x, h = blockIdx.y, b = blockIdx.z;
    int g = h & (GG - 1);
    int base = b * LL + n * 128;
    int tid = threadIdx.x, wid = tid >> 5, lane = tid & 31;
    int quad = lane >> 2, tq = lane & 3;
    int lrow = lane & 15, lhalf = lane >> 4;

    // load Q (scaled by 1/sqrt(HD)), fp16
    {
        const float4* qp = (const float4*)(qkv + (size_t)(base + tid) * QKVC + h * 64);
        #pragma unroll
        for (int c = 0; c < 16; c++) {
            float4 q4 = qp[c];
            uint32_t p0 = packh(__float2half_rn(q4.x * 0.125f), __float2half_rn(q4.y * 0.125f));
            uint32_t p1 = packh(__float2half_rn(q4.z * 0.125f), __float2half_rn(q4.w * 0.125f));
            *(uint2*)&Qh[tid * APAD + c * 4] = make_uint2(p0, p1);
        }
    }

    float o[2][8][4];
    #pragma unroll
    for (int mt = 0; mt < 2; mt++)
        #pragma unroll
        for (int nt = 0; nt < 8; nt++)
            #pragma unroll
            for (int i = 0; i < 4; i++) o[mt][nt][i] = 0.f;
    float denomAcc[2][2] = {{0.f, 0.f}, {0.f, 0.f}};

    uint32_t qBase = su32(Qh), kBase = su32(Kh), vBase = su32(Vh);
    uint32_t loK = (uint32_t)(64 * APAD * 2);

    for (int kt = 0; kt < 4; kt++) {
        __syncthreads();
        {
            int r = tid >> 2, sgi = tid & 3;
            const float* kp = qkv + (size_t)(base + kt * 64 + r) * QKVC + DD + g * 64 + sgi * 16;
            #pragma unroll
            for (int c4 = 0; c4 < 4; c4++) {
                float4 kk = *(const float4*)(kp + c4 * 4);
                float kv4[4] = {kk.x, kk.y, kk.z, kk.w};
                __half hh[4], ll[4];
                #pragma unroll
                for (int e = 0; e < 4; e++) split2h(kv4[e], hh[e], ll[e]);
                *(uint2*)&Kh[r * APAD + sgi * 16 + c4 * 4] = *(uint2*)hh;
                *(uint2*)&Kl[r * APAD + sgi * 16 + c4 * 4] = *(uint2*)ll;
                float4 vv = *(const float4*)(kp + KVD + c4 * 4);
                float va[4] = {vv.x, vv.y, vv.z, vv.w};
                #pragma unroll
                for (int e = 0; e < 4; e++) {
                    __half vh_, vl_;
                    split2h(va[e], vh_, vl_);
                    int d = sgi * 16 + c4 * 4 + e;
                    Vh[d * APAD + r] = vh_;
                    Vl[d * APAD + r] = vl_;
                }
            }
        }
        __syncthreads();

        // ---- S = Q @ K^T (2-pass) ----
        float s[2][8][4];
        #pragma unroll
        for (int mt = 0; mt < 2; mt++)
            #pragma unroll
            for (int nt = 0; nt < 8; nt++)
                #pragma unroll
                for (int i = 0; i < 4; i++) s[mt][nt][i] = 0.f;

        #pragma unroll
        for (int ks = 0; ks < 4; ks++) {
            uint32_t kof = (uint32_t)(ks * 16 + lhalf * 8) * 2;
            uint32_t ah[2][4];
            #pragma unroll
            for (int mt = 0; mt < 2; mt++) {
                uint32_t aa = qBase + (uint32_t)((wid * 32 + mt * 16 + lrow) * APAD) * 2 + kof;
                LDSM4(ah[mt][0], ah[mt][1], ah[mt][2], ah[mt][3], aa);
            }
            uint32_t bh[8][2], bl[8][2];
            #pragma unroll
            for (int p = 0; p < 4; p++) {
                uint32_t bb = kBase + (uint32_t)((p * 16 + lrow) * APAD) * 2 + kof;
                LDSM4(bh[2*p][0], bh[2*p+1][0], bh[2*p][1], bh[2*p+1][1], bb);
                LDSM4(bl[2*p][0], bl[2*p+1][0], bl[2*p][1], bl[2*p+1][1], bb + loK);
            }
            #pragma unroll
            for (int mt = 0; mt < 2; mt++)
                #pragma unroll
                for (int nt = 0; nt < 8; nt++) {
                    mma_f16(s[mt][nt], ah[mt], bh[nt]);
                    mma_f16(s[mt][nt], ah[mt], bl[nt]);
                }
        }

        // ---- exp, denominators, pack P (fp16) ----
        uint32_t ph[2][8][2];
        #pragma unroll
        for (int mt = 0; mt < 2; mt++) {
            float d0 = 0.f, d1 = 0.f;
            #pragma unroll
            for (int nt = 0; nt < 8; nt++) {
                float p0 = __expf(fminf(s[mt][nt][0], 75.f));
                float p1 = __expf(fminf(s[mt][nt][1], 75.f));
                float p2 = __expf(fminf(s[mt][nt][2], 75.f));
                float p3 = __expf(fminf(s[mt][nt][3], 75.f));
                d0 += p0 + p1;
                d1 += p2 + p3;
                ph[mt][nt][0] = packh(__float2half_rn(p0), __float2half_rn(p1));
                ph[mt][nt][1] = packh(__float2half_rn(p2), __float2half_rn(p3));
            }
            d0 += __shfl_xor_sync(0xffffffffu, d0, 1);
            d0 += __shfl_xor_sync(0xffffffffu, d0, 2);
            d1 += __shfl_xor_sync(0xffffffffu, d1, 1);
            d1 += __shfl_xor_sync(0xffffffffu, d1, 2);
            denomAcc[mt][0] += d0;
            denomAcc[mt][1] += d1;
        }

        // ---- O += P @ V^T (2-pass) ----
        #pragma unroll
        for (int ks = 0; ks < 4; ks++) {
            uint32_t kof = (uint32_t)(ks * 16 + lhalf * 8) * 2;
            uint32_t bvh[8][2], bvl[8][2];
            #pragma unroll
            for (int p = 0; p < 4; p++) {
                uint32_t bb = vBase + (uint32_t)((p * 16 + lrow) * APAD) * 2 + kof;
                LDSM4(bvh[2*p][0], bvh[2*p+1][0], bvh[2*p][1], bvh[2*p+1][1], bb);
                LDSM4(bvl[2*p][0], bvl[2*p+1][0], bvl[2*p][1], bvl[2*p+1][1], bb + loK);
            }
            #pragma unroll
            for (int mt = 0; mt < 2; mt++) {
                uint32_t ah4[4] = { ph[mt][2*ks][0], ph[mt][2*ks][1],
                                    ph[mt][2*ks+1][0], ph[mt][2*ks+1][1] };
                #pragma unroll
                for (int nt = 0; nt < 8; nt++) {
                    mma_f16(o[mt][nt], ah4, bvh[nt]);
                    mma_f16(o[mt][nt], ah4, bvl[nt]);
                }
            }
        }
    }

    // ---- epilogue ----
    #pragma unroll
    for (int mt = 0; mt < 2; mt++) {
        #pragma unroll
        for (int half = 0; half < 2; half++) {
            float inv = 1.f / denomAcc[mt][half];
            int tokout = b * LL + n * 256 + wid * 32 + mt * 16 + quad + half * 8;
            size_t rowb = (size_t)tokout * DD + h * 64;
            #pragma unroll
            for (int nt = 0; nt < 8; nt++) {
                float v0 = o[mt][nt][half * 2 + 0] * inv;
                float v1 = o[mt][nt][half * 2 + 1] * inv;
                int col = nt * 8 + tq * 2;
                *(uint32_t*)&oatt[rowb + col] = packh(__float2half_rn(v0), __float2half_rn(v1));
            }
        }
    }
}

// ---------------- aux scalar ----------------
__global__ void aux_kernel(float* __restrict__ out, long long out_size) {
    if (threadIdx.x == 0 && blockIdx.x == 0) {
        float pen = 0.f;
        #pragma unroll
        for (int e = 0; e < EE; e++) {
            float usage = (float)g_ecount[e] / ((float)NTOK + 1e-8f);
            pen += fmaxf(usage - 0.4f, 0.f);
        }
        float ent = g_entsum / (float)NTOK;
        float aux = 0.05f * ent + pen;
        long long total = (long long)NTOK * HID;
        if (out_size > total) out[total] = aux;
    }
}

// ---------------- launch ----------------
extern "C" void kernel_launch(void* const* d_in, const int* in_sizes, int n_in,
                              void* d_out, int out_size) {
    const float* x     = (const float*)d_in[0];
    const float* Wq    = (const float*)d_in[1];
    const float* bq    = (const float*)d_in[2];
    const float* Wk    = (const float*)d_in[3];
    const float* bk    = (const float*)d_in[4];
    const float* Wv    = (const float*)d_in[5];
    const float* bv    = (const float*)d_in[6];
    const float* Wo    = (const float*)d_in[7];
    const float* bo    = (const float*)d_in[8];
    const float* ln1_g = (const float*)d_in[9];
    const float* ln1_b = (const float*)d_in[10];
    const float* ln2_g = (const float*)d_in[11];
    const float* ln2_b = (const float*)d_in[12];
    const float* Wg    = (const float*)d_in[13];
    const float* bg    = (const float*)d_in[14];
    const float* We    = (const float*)d_in[15];
    const float* be    = (const float*)d_in[16];
    float* out = (float*)d_out;

    __half *ln1, *att, *ln2, *wqkvh, *wqkvl, *woth, *wotl, *weth, *wetl;
    float *qkv, *bqkv;
    cudaGetSymbolAddress((void**)&ln1,  g_ln1);
    cudaGetSymbolAddress((void**)&qkv,  g_qkv);
    cudaGetSymbolAddress((void**)&att,  g_att);
    cudaGetSymbolAddress((void**)&ln2,  g_ln2);
    cudaGetSymbolAddress((void**)&wqkvh, g_wqkvh);
    cudaGetSymbolAddress((void**)&wqkvl, g_wqkvl);
    cudaGetSymbolAddress((void**)&woth, g_woth);
    cudaGetSymbolAddress((void**)&wotl, g_wotl);
    cudaGetSymbolAddress((void**)&weth, g_weth);
    cudaGetSymbolAddress((void**)&wetl, g_wetl);
    cudaGetSymbolAddress((void**)&bqkv, g_bqkv);

    const int ASM = (256 + 4 * 64) * APAD * 2;   // 73728
    cudaFuncSetAttribute(attn_kernel, cudaFuncAttributeMaxDynamicSharedMemorySize, ASM);
    cudaFuncSetAttribute(tc_gemm<0>, cudaFuncAttributeMaxDynamicSharedMemorySize, GSMEM);
    cudaFuncSetAttribute(tc_gemm<2>, cudaFuncAttributeMaxDynamicSharedMemorySize, GSMEM);
    cudaFuncSetAttribute(tc_gemm<3>, cudaFuncAttributeMaxDynamicSharedMemorySize, GSMEM);

    zero_kernel<<<1, 32>>>();

    transpose_all<<<10496, dim3(32, 8)>>>(Wq, Wk, Wv, Wo, We);
    bqkv_kernel<<<(QKVC + 255) / 256, 256>>>(bq, bk, bv);

    ln_kernel<<<NTOK, 256>>>(x, ln1_g, ln1_b, ln1);

    tc_gemm<0><<<dim3(10, 64), 256, GSMEM>>>(ln1, wqkvh, wqkvl, bqkv, nullptr, qkv, QKVC);

    attn_kernel<<<dim3(NWIN, HH, BB), 256, ASM>>>(qkv, att);

    // out = x + attn@Wo + bo
    tc_gemm<2><<<dim3(8, 64), 256, GSMEM>>>(att, woth, wotl, bo, x, out, DD);

    ln2_gate_kernel<<<NTOK, 256>>>(out, ln2_g, ln2_b, Wg, bg, ln2);

    tc_gemm<3><<<dim3(8, 64, EE), 256, GSMEM>>>(ln2, weth, wetl, be, nullptr, out, HID);

    aux_kernel<<<1, 32>>>(out, (long long)out_size);
}

// round 10
// speedup vs baseline: 1.3840x; 1.1094x over previous
#include <cuda_runtime.h>
#include <cuda_fp16.h>
#include <math.h>
#include <stdint.h>

// Problem constants
#define BB 2
#define LL 4096
#define DD 1024
#define HH 16
#define GG 2
#define HD 64
#define KVD 128
#define KVC 256
#define QKVC 1280        // Q(1024) | K(128) | V(128)
#define EE 8
#define HID 1024
#define NTOK (BB*LL)     // 8192
#define NWIN 16
#define WIN 256
#define TCK 32           // K-chunk (32 fp16 columns per stage)
#define NCH (DD/TCK)     // 32 chunks
#define BSTR 40          // padded smem row stride (80B, ldmatrix conflict-free)
#define TILE (128*BSTR)
#define TILEB (TILE*2)
#define BUFB (3*TILEB)   // one stage = A|Bh|Bl = 30720 bytes
#define NSTAGE 3
#define GSMEM (NSTAGE*BUFB)  // 92160 -> still 2 CTAs/SM
#define APAD 72          // attention smem row stride

// ---------------- scratch (static device globals) ----------------
__device__ __half g_ln1 [NTOK*DD];
__device__ float  g_qkv [NTOK*QKVC];
__device__ __half g_att [NTOK*DD];
__device__ __half g_ln2 [NTOK*DD];
__device__ __half g_wqkvh[QKVC*DD], g_wqkvl[QKVC*DD];
__device__ __half g_woth[DD*DD],  g_wotl[DD*DD];
__device__ __half g_weth[EE*DD*HID], g_wetl[EE*DD*HID];
__device__ __half g_ksph[BB*NWIN*GG*256*64], g_kspl[BB*NWIN*GG*256*64];
__device__ __half g_vsph[BB*NWIN*GG*64*256], g_vspl[BB*NWIN*GG*64*256];
__device__ float  g_moe [2*NTOK*HID];
__device__ float g_bqkv[QKVC];
__device__ int   g_ecount[EE];
__device__ float g_entsum;
__device__ int   g_etok[EE*NTOK];   // tok*2 + slot
__device__ float g_ewt [EE*NTOK];

// ---------------- helpers ----------------
__device__ __forceinline__ uint32_t su32(const void* p) {
    uint32_t r;
    asm("{ .reg .u64 t; cvta.to.shared.u64 t, %1; cvt.u32.u64 %0, t; }" : "=r"(r) : "l"(p));
    return r;
}
__device__ __forceinline__ void split2h(float x, __half& h, __half& l) {
    h = __float2half_rn(x);
    l = __float2half_rn(x - __half2float(h));
}
#define CP16(dst, src) asm volatile("cp.async.cg.shared.global [%0], [%1], 16;" :: "r"(dst), "l"(src))
#define CP_COMMIT()    asm volatile("cp.async.commit_group;" ::: "memory")
#define CP_WAIT0()     asm volatile("cp.async.wait_group 0;" ::: "memory")
#define CP_WAIT1()     asm volatile("cp.async.wait_group 1;" ::: "memory")

#define LDSM4(r0, r1, r2, r3, addr) \
    asm volatile("ldmatrix.sync.aligned.m8n8.x4.shared.b16 {%0,%1,%2,%3}, [%4];" \
                 : "=r"(r0), "=r"(r1), "=r"(r2), "=r"(r3) : "r"(addr))

__device__ __forceinline__ void mma_f16(float* c, const uint32_t* a, const uint32_t* b) {
    asm volatile(
        "mma.sync.aligned.m16n8k16.row.col.f32.f16.f16.f32 "
        "{%0,%1,%2,%3}, {%4,%5,%6,%7}, {%8,%9}, {%0,%1,%2,%3};"
        : "+f"(c[0]), "+f"(c[1]), "+f"(c[2]), "+f"(c[3])
        : "r"(a[0]), "r"(a[1]), "r"(a[2]), "r"(a[3]), "r"(b[0]), "r"(b[1]));
}
__device__ __forceinline__ uint32_t packh(__half lo, __half hi) {
    return (uint32_t)__half_as_ushort(lo) | ((uint32_t)__half_as_ushort(hi) << 16);
}

// ---------------- zero bookkeeping ----------------
__global__ void zero_kernel() {
    int t = threadIdx.x;
    if (t < EE) g_ecount[t] = 0;
    if (t == EE) g_entsum = 0.f;
}

// ---------------- fused weight transpose + fp16 split (one launch) --------
__global__ void __launch_bounds__(256)
transpose_all(const float* __restrict__ Wq, const float* __restrict__ Wk,
              const float* __restrict__ Wv, const float* __restrict__ Wo,
              const float* __restrict__ We) {
    __shared__ float t[32][33];
    int bid = blockIdx.x;
    const float* src;
    __half *dh, *dl;
    int cols, rowOff, bx, by;
    size_t dstOff = 0;
    if (bid < 1024) {
        src = Wq; dh = g_wqkvh; dl = g_wqkvl; cols = DD; rowOff = 0;
        bx = bid & 31; by = bid >> 5;
    } else if (bid < 1152) {
        int r = bid - 1024;
        src = Wk; dh = g_wqkvh; dl = g_wqkvl; cols = KVD; rowOff = DD;
        bx = r & 3; by = r >> 2;
    } else if (bid < 1280) {
        int r = bid - 1152;
        src = Wv; dh = g_wqkvh; dl = g_wqkvl; cols = KVD; rowOff = DD + KVD;
        bx = r & 3; by = r >> 2;
    } else if (bid < 2304) {
        int r = bid - 1280;
        src = Wo; dh = g_woth; dl = g_wotl; cols = DD; rowOff = 0;
        bx = r & 31; by = r >> 5;
    } else {
        int r = bid - 2304;
        int e = r >> 10; r &= 1023;
        src = We + (size_t)e * DD * HID;
        dh = g_weth; dl = g_wetl; dstOff = (size_t)e * DD * HID;
        cols = HID; rowOff = 0;
        bx = r & 31; by = r >> 5;
    }
    int c0 = bx * 32, r0 = by * 32;
    int tx = threadIdx.x, ty = threadIdx.y;
    #pragma unroll
    for (int i = 0; i < 32; i += 8)
        t[ty + i][tx] = src[(size_t)(r0 + ty + i) * cols + c0 + tx];
    __syncthreads();
    #pragma unroll
    for (int i = 0; i < 32; i += 8) {
        __half h, l;
        split2h(t[tx][ty + i], h, l);
        size_t o = dstOff + (size_t)(c0 + ty + i + rowOff) * DD + r0 + tx;
        dh[o] = h;
        dl[o] = l;
    }
}

__global__ void bqkv_kernel(const float* __restrict__ bq, const float* __restrict__ bk,
                            const float* __restrict__ bv) {
    int t = threadIdx.x + blockIdx.x * 256;
    if (t < DD) g_bqkv[t] = bq[t];
    else if (t < DD + KVD) g_bqkv[t] = bk[t - DD];
    else if (t < QKVC) g_bqkv[t] = bv[t - DD - KVD];
}

// ---------------- LayerNorm (fp16 output) ----------
__global__ void ln_kernel(const float* __restrict__ x, const float* __restrict__ g,
                          const float* __restrict__ b, __half* __restrict__ y) {
    int row = blockIdx.x;
    const float4* xr = (const float4*)(x + (size_t)row * DD);
    int tid = threadIdx.x;
    float4 v = xr[tid];
    float s  = v.x + v.y + v.z + v.w;
    float ss = v.x*v.x + v.y*v.y + v.z*v.z + v.w*v.w;
    #pragma unroll
    for (int o = 16; o > 0; o >>= 1) {
        s  += __shfl_down_sync(0xffffffffu, s,  o);
        ss += __shfl_down_sync(0xffffffffu, ss, o);
    }
    __shared__ float sh_s[8], sh_ss[8];
    __shared__ float s_mean, s_rstd;
    int warp = tid >> 5, lane = tid & 31;
    if (lane == 0) { sh_s[warp] = s; sh_ss[warp] = ss; }
    __syncthreads();
    if (tid == 0) {
        float S = 0.f, SS = 0.f;
        #pragma unroll
        for (int i = 0; i < 8; i++) { S += sh_s[i]; SS += sh_ss[i]; }
        float mean = S / (float)DD;
        float var  = SS / (float)DD - mean * mean;
        s_mean = mean;
        s_rstd = rsqrtf(var + 1e-5f);
    }
    __syncthreads();
    float mean = s_mean, rstd = s_rstd;
    float4 gg = ((const float4*)g)[tid];
    float4 bb = ((const float4*)b)[tid];
    float o[4];
    o[0] = (v.x - mean) * rstd * gg.x + bb.x;
    o[1] = (v.y - mean) * rstd * gg.y + bb.y;
    o[2] = (v.z - mean) * rstd * gg.z + bb.z;
    o[3] = (v.w - mean) * rstd * gg.w + bb.w;
    size_t base = (size_t)row * DD + tid * 4;
    uint32_t p0 = packh(__float2half_rn(o[0]), __float2half_rn(o[1]));
    uint32_t p1 = packh(__float2half_rn(o[2]), __float2half_rn(o[3]));
    *(uint2*)&y[base] = make_uint2(p0, p1);
}

// ---------------- LN2 + MoE gate fused ----------------
__global__ void ln2_gate_kernel(const float* __restrict__ x, const float* __restrict__ g,
                                const float* __restrict__ b,
                                const float* __restrict__ Wg, const float* __restrict__ bg,
                                __half* __restrict__ y) {
    int row = blockIdx.x;
    const float4* xr = (const float4*)(x + (size_t)row * DD);
    int tid = threadIdx.x;
    float4 v = xr[tid];
    float s  = v.x + v.y + v.z + v.w;
    float ss = v.x*v.x + v.y*v.y + v.z*v.z + v.w*v.w;
    #pragma unroll
    for (int o = 16; o > 0; o >>= 1) {
        s  += __shfl_down_sync(0xffffffffu, s,  o);
        ss += __shfl_down_sync(0xffffffffu, ss, o);
    }
    __shared__ float sh_s[8], sh_ss[8];
    __shared__ float s_mean, s_rstd;
    __shared__ float red[8][8];
    int warp = tid >> 5, lane = tid & 31;
    if (lane == 0) { sh_s[warp] = s; sh_ss[warp] = ss; }
    __syncthreads();
    if (tid == 0) {
        float S = 0.f, SS = 0.f;
        #pragma unroll
        for (int i = 0; i < 8; i++) { S += sh_s[i]; SS += sh_ss[i]; }
        float mean = S / (float)DD;
        float var  = SS / (float)DD - mean * mean;
        s_mean = mean;
        s_rstd = rsqrtf(var + 1e-5f);
    }
    __syncthreads();
    float mean = s_mean, rstd = s_rstd;
    float4 gg = ((const float4*)g)[tid];
    float4 bb = ((const float4*)b)[tid];
    float o[4];
    o[0] = (v.x - mean) * rstd * gg.x + bb.x;
    o[1] = (v.y - mean) * rstd * gg.y + bb.y;
    o[2] = (v.z - mean) * rstd * gg.z + bb.z;
    o[3] = (v.w - mean) * rstd * gg.w + bb.w;
    size_t base = (size_t)row * DD + tid * 4;
    uint32_t p0 = packh(__float2half_rn(o[0]), __float2half_rn(o[1]));
    uint32_t p1 = packh(__float2half_rn(o[2]), __float2half_rn(o[3]));
    *(uint2*)&y[base] = make_uint2(p0, p1);

    // ---- gating from in-register LN output ----
    float pr[EE];
    #pragma unroll
    for (int e = 0; e < EE; e++) pr[e] = 0.f;
    #pragma unroll
    for (int i = 0; i < 4; i++) {
        float4 w0 = ((const float4*)Wg)[(tid * 4 + i) * 2];
        float4 w1 = ((const float4*)Wg)[(tid * 4 + i) * 2 + 1];
        pr[0] += o[i] * w0.x; pr[1] += o[i] * w0.y;
        pr[2] += o[i] * w0.z; pr[3] += o[i] * w0.w;
        pr[4] += o[i] * w1.x; pr[5] += o[i] * w1.y;
        pr[6] += o[i] * w1.z; pr[7] += o[i] * w1.w;
    }
    #pragma unroll
    for (int off = 16; off > 0; off >>= 1)
        #pragma unroll
        for (int e = 0; e < EE; e++)
            pr[e] += __shfl_down_sync(0xffffffffu, pr[e], off);
    if (lane == 0)
        #pragma unroll
        for (int e = 0; e < EE; e++) red[warp][e] = pr[e];
    __syncthreads();
    if (tid == 0) {
        float l[EE], m = -3.4e38f;
        #pragma unroll
        for (int e = 0; e < EE; e++) {
            float sum = bg[e];
            #pragma unroll
            for (int w = 0; w < 8; w++) sum += red[w][e];
            l[e] = sum;
            m = fmaxf(m, sum);
        }
        float p[EE], sm = 0.f;
        #pragma unroll
        for (int e = 0; e < EE; e++) { p[e] = __expf(l[e] - m); sm += p[e]; }
        float invs = 1.f / sm, ent = 0.f;
        #pragma unroll
        for (int e = 0; e < EE; e++) {
            p[e] *= invs;
            ent -= p[e] * logf(p[e] + 1e-8f);
        }
        atomicAdd(&g_entsum, ent);
        int i1 = 0;
        #pragma unroll
        for (int e = 1; e < EE; e++) if (p[e] > p[i1]) i1 = e;
        int i2 = (i1 == 0) ? 1 : 0;
        #pragma unroll
        for (int e = 0; e < EE; e++) if (e != i1 && p[e] > p[i2]) i2 = e;
        int s1 = atomicAdd(&g_ecount[i1], 1);
        g_etok[i1 * NTOK + s1] = row * 2 + 0; g_ewt[i1 * NTOK + s1] = p[i1];
        int s2 = atomicAdd(&g_ecount[i2], 1);
        g_etok[i2 * NTOK + s2] = row * 2 + 1; g_ewt[i2 * NTOK + s2] = p[i2];
    }
}

// ---------------- fp16x2 mma.sync GEMM (3-stage cp.async, 2 CTA/SM) ------
// A single-fp16, B split (Bh, Bl). acc = A*Bh + A*Bl.
// MODE 0: C = acc + bias
// MODE 2: C = acc + bias + resid
// MODE 3: MoE gathered rows; store w*(acc+bias) to g_moe[slot][tok]
template<int MODE>
__global__ void __launch_bounds__(256)
tc_gemm(const __half* __restrict__ A,
        const __half* __restrict__ Bh, const __half* __restrict__ Bl,
        const float* __restrict__ bias, const float* __restrict__ resid,
        float* __restrict__ C, int ldc) {
    __shared__ int   stok[128];
    __shared__ float swt[128];
    extern __shared__ __half smb[];

    int row0 = blockIdx.y * 128;
    int col0 = blockIdx.x * 128;
    int tid = threadIdx.x, wid = tid >> 5, lane = tid & 31;
    int quad = lane >> 2, tq = lane & 3;
    int wm = wid & 1, wn = wid >> 1;

    if (MODE == 3) {
        int e = blockIdx.z;
        int cnt = g_ecount[e];
        if (row0 >= cnt) return;
        Bh   += (size_t)e * DD * HID;
        Bl   += (size_t)e * DD * HID;
        bias += (size_t)e * HID;
        if (tid < 128) {
            int r = row0 + tid;
            if (r < cnt) { stok[tid] = g_etok[e * NTOK + r]; swt[tid] = g_ewt[e * NTOK + r]; }
            else         { stok[tid] = -1; swt[tid] = 0.f; }
        }
        __syncthreads();
    }

    int crow = tid >> 2;
    int seg  = tid & 3;
    const __half *sa[2], *sbh[2], *sbl[2];
    uint32_t doff[2];
    #pragma unroll
    for (int i = 0; i < 2; i++) {
        int r = crow + 64 * i;
        int tok;
        if (MODE == 3) { int t2 = stok[r]; tok = (t2 < 0) ? 0 : (t2 >> 1); }
        else           tok = row0 + r;
        sa[i]  = A  + (size_t)tok * DD + seg * 8;
        sbh[i] = Bh + (size_t)(col0 + r) * DD + seg * 8;
        sbl[i] = Bl + (size_t)(col0 + r) * DD + seg * 8;
        doff[i] = (uint32_t)(r * (BSTR * 2) + seg * 16);
    }
    uint32_t sbase = su32(smb);

    int lrow = lane & 15, lhalf = lane >> 4;
    uint32_t aLane = (uint32_t)(((wm * 64 + lrow) * BSTR + lhalf * 8) * 2);
    uint32_t bLane = (uint32_t)(((wn * 32 + lrow) * BSTR + lhalf * 8) * 2);

    float acc[4][4][4];
    #pragma unroll
    for (int mt = 0; mt < 4; mt++)
        #pragma unroll
        for (int nt = 0; nt < 4; nt++)
            #pragma unroll
            for (int i = 0; i < 4; i++) acc[mt][nt][i] = 0.f;

    // prologue: chunks 0,1 into stages 0,1
    #pragma unroll
    for (int pc = 0; pc < 2; pc++) {
        uint32_t base = sbase + pc * BUFB;
        int k0 = pc * TCK;
        #pragma unroll
        for (int i = 0; i < 2; i++) {
            CP16(base + 0 * TILEB + doff[i], sa[i] + k0);
            CP16(base + 1 * TILEB + doff[i], sbh[i] + k0);
            CP16(base + 2 * TILEB + doff[i], sbl[i] + k0);
        }
        CP_COMMIT();
    }

    int stage = 0;
    for (int c = 0; c < NCH; c++) {
        if (c == NCH - 1) CP_WAIT0(); else CP_WAIT1();
        __syncthreads();
        if (c + 2 < NCH) {
            int nst = stage + 2; if (nst >= NSTAGE) nst -= NSTAGE;
            uint32_t base = sbase + nst * BUFB;
            int k0 = (c + 2) * TCK;
            #pragma unroll
            for (int i = 0; i < 2; i++) {
                CP16(base + 0 * TILEB + doff[i], sa[i] + k0);
                CP16(base + 1 * TILEB + doff[i], sbh[i] + k0);
                CP16(base + 2 * TILEB + doff[i], sbl[i] + k0);
            }
            CP_COMMIT();
        }

        uint32_t sb = sbase + stage * BUFB;
        #pragma unroll
        for (int kk = 0; kk < 2; kk++) {
            uint32_t kof = kk * 16 * 2;
            uint32_t bh[4][2], bl[4][2];
            uint32_t bb0 = sb + 1 * TILEB + bLane + kof;
            LDSM4(bh[0][0], bh[1][0], bh[0][1], bh[1][1], bb0);
            LDSM4(bh[2][0], bh[3][0], bh[2][1], bh[3][1], bb0 + 16 * BSTR * 2);
            uint32_t bb1 = sb + 2 * TILEB + bLane + kof;
            LDSM4(bl[0][0], bl[1][0], bl[0][1], bl[1][1], bb1);
            LDSM4(bl[2][0], bl[3][0], bl[2][1], bl[3][1], bb1 + 16 * BSTR * 2);
            #pragma unroll
            for (int mt = 0; mt < 4; mt++) {
                uint32_t ah[4];
                uint32_t aa = sb + aLane + kof + mt * 16 * BSTR * 2;
                LDSM4(ah[0], ah[1], ah[2], ah[3], aa);
                #pragma unroll
                for (int nt = 0; nt < 4; nt++) {
                    mma_f16(acc[mt][nt], ah, bh[nt]);
                    mma_f16(acc[mt][nt], ah, bl[nt]);
                }
            }
        }
        stage++; if (stage >= NSTAGE) stage = 0;
    }

    #pragma unroll
    for (int mt = 0; mt < 4; mt++) {
        #pragma unroll
        for (int half = 0; half < 2; half++) {
            int lr = wm * 64 + mt * 16 + quad + half * 8;
            int r = row0 + lr;
            #pragma unroll
            for (int nt = 0; nt < 4; nt++) {
                int col = col0 + wn * 32 + nt * 8 + tq * 2;
                float v0 = acc[mt][nt][half * 2 + 0] + bias[col];
                float v1 = acc[mt][nt][half * 2 + 1] + bias[col + 1];
                if (MODE == 0) {
                    *(float2*)&C[(size_t)r * ldc + col] = make_float2(v0, v1);
                } else if (MODE == 2) {
                    size_t o = (size_t)r * ldc + col;
                    float2 rr = *(const float2*)&resid[o];
                    *(float2*)&C[o] = make_float2(v0 + rr.x, v1 + rr.y);
                } else {
                    int t2 = stok[lr];
                    if (t2 >= 0) {
                        int tok = t2 >> 1, slot = t2 & 1;
                        float w = swt[lr];
                        size_t o = ((size_t)slot * NTOK + tok) * HID + col;
                        *(float2*)&g_moe[o] = make_float2(w * v0, w * v1);
                    }
                }
            }
        }
    }
}

// ---------------- K/V pre-split (once per window/group/batch) --------------
// K: [tile][key 256][dim 64] split fp16. V transposed: [tile][dim 64][key 256].
__global__ void __launch_bounds__(256)
kvsplit_kernel(const float* __restrict__ qkv) {
    int n = blockIdx.x, g = blockIdx.y, b = blockIdx.z;
    int key = threadIdx.x;
    int base = b * LL + n * 128;
    const float* kp = qkv + (size_t)(base + key) * QKVC + DD + g * 64;
    size_t tileid = ((size_t)b * NWIN + n) * GG + g;
    __half* kh = g_ksph + (tileid * 256 + key) * 64;
    __half* kl = g_kspl + (tileid * 256 + key) * 64;
    size_t vb = tileid * 64 * 256 + key;
    #pragma unroll
    for (int d = 0; d < 64; d += 4) {
        float4 kk = *(const float4*)(kp + d);
        float ka[4] = {kk.x, kk.y, kk.z, kk.w};
        __half hh[4], ll[4];
        #pragma unroll
        for (int e = 0; e < 4; e++) split2h(ka[e], hh[e], ll[e]);
        *(uint2*)&kh[d] = *(uint2*)hh;
        *(uint2*)&kl[d] = *(uint2*)ll;
        float4 vv = *(const float4*)(kp + KVD + d);
        float va[4] = {vv.x, vv.y, vv.z, vv.w};
        #pragma unroll
        for (int e = 0; e < 4; e++) {
            __half vh_, vl_;
            split2h(va[e], vh_, vl_);
            g_vsph[vb + (size_t)(d + e) * 256] = vh_;
            g_vspl[vb + (size_t)(d + e) * 256] = vl_;
        }
    }
}

// ---------------- tensor-core attention (fp16x2, pre-split K/V) ------------
__global__ void __launch_bounds__(256)
attn_kernel(const float* __restrict__ qkv, __half* __restrict__ oatt) {
    extern __shared__ __half sma[];
    __half* Qh = sma;                  // 256 x APAD
    __half* Kh = Qh + 256 * APAD;      // 64 x APAD
    __half* Kl = Kh + 64 * APAD;
    __half* Vh = Kl + 64 * APAD;       // [dim][key]
    __half* Vl = Vh + 64 * APAD;

    int n = blockIdx.x, h = blockIdx.y, b = blockIdx.z;
    int g = h & (GG - 1);
    int base = b * LL + n * 128;
    int tid = threadIdx.x, wid = tid >> 5, lane = tid & 31;
    int quad = lane >> 2, tq = lane & 3;
    int lrow = lane & 15, lhalf = lane >> 4;
    size_t tileid = ((size_t)b * NWIN + n) * GG + g;

    // load Q (scaled), fp16
    {
        const float4* qp = (const float4*)(qkv + (size_t)(base + tid) * QKVC + h * 64);
        #pragma unroll
        for (int c = 0; c < 16; c++) {
            float4 q4 = qp[c];
            uint32_t p0 = packh(__float2half_rn(q4.x * 0.125f), __float2half_rn(q4.y * 0.125f));
            uint32_t p1 = packh(__float2half_rn(q4.z * 0.125f), __float2half_rn(q4.w * 0.125f));
            *(uint2*)&Qh[tid * APAD + c * 4] = make_uint2(p0, p1);
        }
    }

    float o[2][8][4];
    #pragma unroll
    for (int mt = 0; mt < 2; mt++)
        #pragma unroll
        for (int nt = 0; nt < 8; nt++)
            #pragma unroll
            for (int i = 0; i < 4; i++) o[mt][nt][i] = 0.f;
    float denomAcc[2][2] = {{0.f, 0.f}, {0.f, 0.f}};

    uint32_t qBase = su32(Qh), kBase = su32(Kh), vBase = su32(Vh);
    uint32_t loK = (uint32_t)(64 * APAD * 2);

    int trow = tid >> 2, tseg = tid & 3;
    const __half* ksrc_h = g_ksph + (tileid * 256 + trow) * 64;
    const __half* ksrc_l = g_kspl + (tileid * 256 + trow) * 64;
    const __half* vsrc_h = g_vsph + (tileid * 64 + trow) * 256;
    const __half* vsrc_l = g_vspl + (tileid * 64 + trow) * 256;
    uint32_t kdst = (uint32_t)(trow * APAD) * 2;

    for (int kt = 0; kt < 4; kt++) {
        __syncthreads();   // all readers done with previous tile (covers Q store too)
        // cp.async K tile (64 keys x 64 dims) + V tile (64 dims x 64 keys)
        #pragma unroll
        for (int s2 = 0; s2 < 2; s2++) {
            int sg = tseg + s2 * 4;
            CP16(kBase + kdst + sg * 16,        ksrc_h + (size_t)kt * 64 * 64 + sg * 8);
            CP16(kBase + loK + kdst + sg * 16,  ksrc_l + (size_t)kt * 64 * 64 + sg * 8);
            CP16(vBase + kdst + sg * 16,        vsrc_h + kt * 64 + sg * 8);
            CP16(vBase + loK + kdst + sg * 16,  vsrc_l + kt * 64 + sg * 8);
        }
        CP_COMMIT();
        CP_WAIT0();
        __syncthreads();

        // ---- S = Q @ K^T (2-pass) ----
        float s[2][8][4];
        #pragma unroll
        for (int mt = 0; mt < 2; mt++)
            #pragma unroll
            for (int nt = 0; nt < 8; nt++)
                #pragma unroll
                for (int i = 0; i < 4; i++) s[mt][nt][i] = 0.f;

        #pragma unroll
        for (int ks = 0; ks < 4; ks++) {
            uint32_t kof = (uint32_t)(ks * 16 + lhalf * 8) * 2;
            uint32_t ah[2][4];
            #pragma unroll
            for (int mt = 0; mt < 2; mt++) {
                uint32_t aa = qBase + (uint32_t)((wid * 32 + mt * 16 + lrow) * APAD) * 2 + kof;
                LDSM4(ah[mt][0], ah[mt][1], ah[mt][2], ah[mt][3], aa);
            }
            uint32_t bh[8][2], bl[8][2];
            #pragma unroll
            for (int p = 0; p < 4; p++) {
                uint32_t bb = kBase + (uint32_t)((p * 16 + lrow) * APAD) * 2 + kof;
                LDSM4(bh[2*p][0], bh[2*p+1][0], bh[2*p][1], bh[2*p+1][1], bb);
                LDSM4(bl[2*p][0], bl[2*p+1][0], bl[2*p][1], bl[2*p+1][1], bb + loK);
            }
            #pragma unroll
            for (int mt = 0; mt < 2; mt++)
                #pragma unroll
                for (int nt = 0; nt < 8; nt++) {
                    mma_f16(s[mt][nt], ah[mt], bh[nt]);
                    mma_f16(s[mt][nt], ah[mt], bl[nt]);
                }
        }

        // ---- exp, denominators, pack P (fp16) ----
        uint32_t ph[2][8][2];
        #pragma unroll
        for (int mt = 0; mt < 2; mt++) {
            float d0 = 0.f, d1 = 0.f;
            #pragma unroll
            for (int nt = 0; nt < 8; nt++) {
                float p0 = __expf(fminf(s[mt][nt][0], 75.f));
                float p1 = __expf(fminf(s[mt][nt][1], 75.f));
                float p2 = __expf(fminf(s[mt][nt][2], 75.f));
                float p3 = __expf(fminf(s[mt][nt][3], 75.f));
                d0 += p0 + p1;
                d1 += p2 + p3;
                ph[mt][nt][0] = packh(__float2half_rn(p0), __float2half_rn(p1));
                ph[mt][nt][1] = packh(__float2half_rn(p2), __float2half_rn(p3));
            }
            d0 += __shfl_xor_sync(0xffffffffu, d0, 1);
            d0 += __shfl_xor_sync(0xffffffffu, d0, 2);
            d1 += __shfl_xor_sync(0xffffffffu, d1, 1);
            d1 += __shfl_xor_sync(0xffffffffu, d1, 2);
            denomAcc[mt][0] += d0;
            denomAcc[mt][1] += d1;
        }

        // ---- O += P @ V^T (2-pass) ----
        #pragma unroll
        for (int ks = 0; ks < 4; ks++) {
            uint32_t kof = (uint32_t)(ks * 16 + lhalf * 8) * 2;
            uint32_t bvh[8][2], bvl[8][2];
            #pragma unroll
            for (int p = 0; p < 4; p++) {
                uint32_t bb = vBase + (uint32_t)((p * 16 + lrow) * APAD) * 2 + kof;
                LDSM4(bvh[2*p][0], bvh[2*p+1][0], bvh[2*p][1], bvh[2*p+1][1], bb);
                LDSM4(bvl[2*p][0], bvl[2*p+1][0], bvl[2*p][1], bvl[2*p+1][1], bb + loK);
            }
            #pragma unroll
            for (int mt = 0; mt < 2; mt++) {
                uint32_t ah4[4] = { ph[mt][2*ks][0], ph[mt][2*ks][1],
                                    ph[mt][2*ks+1][0], ph[mt][2*ks+1][1] };
                #pragma unroll
                for (int nt = 0; nt < 8; nt++) {
                    mma_f16(o[mt][nt], ah4, bvh[nt]);
                    mma_f16(o[mt][nt], ah4, bvl[nt]);
                }
            }
        }
    }

    // ---- epilogue ----
    #pragma unroll
    for (int mt = 0; mt < 2; mt++) {
        #pragma unroll
        for (int half = 0; half < 2; half++) {
            float inv = 1.f / denomAcc[mt][half];
            int tokout = b * LL + n * 256 + wid * 32 + mt * 16 + quad + half * 8;
            size_t rowb = (size_t)tokout * DD + h * 64;
            #pragma unroll
            for (int nt = 0; nt < 8; nt++) {
                float v0 = o[mt][nt][half * 2 + 0] * inv;
                float v1 = o[mt][nt][half * 2 + 1] * inv;
                int col = nt * 8 + tq * 2;
                *(uint32_t*)&oatt[rowb + col] = packh(__float2half_rn(v0), __float2half_rn(v1));
            }
        }
    }
}

// ---------------- MoE combine: out += moe0 + moe1 ----------------
__global__ void __launch_bounds__(256)
combine_kernel(float* __restrict__ out) {
    size_t i = ((size_t)blockIdx.x * 256 + threadIdx.x) * 4;
    float4 a  = *(float4*)&out[i];
    float4 m0 = *(const float4*)&g_moe[i];
    float4 m1 = *(const float4*)&g_moe[(size_t)NTOK * HID + i];
    a.x += m0.x + m1.x;
    a.y += m0.y + m1.y;
    a.z += m0.z + m1.z;
    a.w += m0.w + m1.w;
    *(float4*)&out[i] = a;
}

// ---------------- aux scalar ----------------
__global__ void aux_kernel(float* __restrict__ out, long long out_size) {
    if (threadIdx.x == 0 && blockIdx.x == 0) {
        float pen = 0.f;
        #pragma unroll
        for (int e = 0; e < EE; e++) {
            float usage = (float)g_ecount[e] / ((float)NTOK + 1e-8f);
            pen += fmaxf(usage - 0.4f, 0.f);
        }
        float ent = g_entsum / (float)NTOK;
        float aux = 0.05f * ent + pen;
        long long total = (long long)NTOK * HID;
        if (out_size > total) out[total] = aux;
    }
}

// ---------------- launch ----------------
extern "C" void kernel_launch(void* const* d_in, const int* in_sizes, int n_in,
                              void* d_out, int out_size) {
    const float* x     = (const float*)d_in[0];
    const float* Wq    = (const float*)d_in[1];
    const float* bq    = (const float*)d_in[2];
    const float* Wk    = (const float*)d_in[3];
    const float* bk    = (const float*)d_in[4];
    const float* Wv    = (const float*)d_in[5];
    const float* bv    = (const float*)d_in[6];
    const float* Wo    = (const float*)d_in[7];
    const float* bo    = (const float*)d_in[8];
    const float* ln1_g = (const float*)d_in[9];
    const float* ln1_b = (const float*)d_in[10];
    const float* ln2_g = (const float*)d_in[11];
    const float* ln2_b = (const float*)d_in[12];
    const float* Wg    = (const float*)d_in[13];
    const float* bg    = (const float*)d_in[14];
    const float* We    = (const float*)d_in[15];
    const float* be    = (const float*)d_in[16];
    float* out = (float*)d_out;

    __half *ln1, *att, *ln2, *wqkvh, *wqkvl, *woth, *wotl, *weth, *wetl;
    float *qkv, *bqkv;
    cudaGetSymbolAddress((void**)&ln1,  g_ln1);
    cudaGetSymbolAddress((void**)&qkv,  g_qkv);
    cudaGetSymbolAddress((void**)&att,  g_att);
    cudaGetSymbolAddress((void**)&ln2,  g_ln2);
    cudaGetSymbolAddress((void**)&wqkvh, g_wqkvh);
    cudaGetSymbolAddress((void**)&wqkvl, g_wqkvl);
    cudaGetSymbolAddress((void**)&woth, g_woth);
    cudaGetSymbolAddress((void**)&wotl, g_wotl);
    cudaGetSymbolAddress((void**)&weth, g_weth);
    cudaGetSymbolAddress((void**)&wetl, g_wetl);
    cudaGetSymbolAddress((void**)&bqkv, g_bqkv);

    const int ASM = (256 + 4 * 64) * APAD * 2;   // 73728
    cudaFuncSetAttribute(attn_kernel, cudaFuncAttributeMaxDynamicSharedMemorySize, ASM);
    cudaFuncSetAttribute(tc_gemm<0>, cudaFuncAttributeMaxDynamicSharedMemorySize, GSMEM);
    cudaFuncSetAttribute(tc_gemm<2>, cudaFuncAttributeMaxDynamicSharedMemorySize, GSMEM);
    cudaFuncSetAttribute(tc_gemm<3>, cudaFuncAttributeMaxDynamicSharedMemorySize, GSMEM);

    zero_kernel<<<1, 32>>>();

    transpose_all<<<10496, dim3(32, 8)>>>(Wq, Wk, Wv, Wo, We);
    bqkv_kernel<<<(QKVC + 255) / 256, 256>>>(bq, bk, bv);

    ln_kernel<<<NTOK, 256>>>(x, ln1_g, ln1_b, ln1);

    tc_gemm<0><<<dim3(10, 64), 256, GSMEM>>>(ln1, wqkvh, wqkvl, bqkv, nullptr, qkv, QKVC);

    kvsplit_kernel<<<dim3(NWIN, GG, BB), 256>>>(qkv);
    attn_kernel<<<dim3(NWIN, HH, BB), 256, ASM>>>(qkv, att);

    // out = x + attn@Wo + bo
    tc_gemm<2><<<dim3(8, 64), 256, GSMEM>>>(att, woth, wotl, bo, x, out, DD);

    ln2_gate_kernel<<<NTOK, 256>>>(out, ln2_g, ln2_b, Wg, bg, ln2);

    tc_gemm<3><<<dim3(8, 64, EE), 256, GSMEM>>>(ln2, weth, wetl, be, nullptr, nullptr, HID);

    combine_kernel<<<NTOK * HID / 1024, 256>>>(out);

    aux_kernel<<<1, 32>>>(out, (long long)out_size);
}

// round 11
// speedup vs baseline: 2.0061x; 1.4495x over previous
#include <cuda_runtime.h>
#include <cuda_fp16.h>
#include <math.h>
#include <stdint.h>

// Problem constants
#define BB 2
#define LL 4096
#define DD 1024
#define HH 16
#define GG 2
#define HD 64
#define KVD 128
#define KVC 256
#define QKVC 1280        // Q(1024) | K(128) | V(128)
#define EE 8
#define HID 1024
#define NTOK (BB*LL)     // 8192
#define NWIN 16
#define WIN 256
#define TCK 32           // K-chunk (32 fp16 columns per stage)
#define NCH (DD/TCK)     // 32 chunks
#define BSTR 40          // padded smem row stride (80B, ldmatrix conflict-free)
#define TILE (128*BSTR)
#define TILEB (TILE*2)   // 10240 bytes
#define BUFB (2*TILEB)   // one stage = A|B = 20480 bytes
#define NSTAGE 4
#define GSMEM (NSTAGE*BUFB)  // 81920 -> 2 CTAs/SM
#define APAD 72          // attention smem row stride

// ---------------- scratch (static device globals) ----------------
__device__ __half g_ln1 [NTOK*DD];
__device__ float  g_qkv [NTOK*QKVC];
__device__ __half g_att [NTOK*DD];
__device__ __half g_ln2 [NTOK*DD];
__device__ __half g_wqkv[QKVC*DD];
__device__ __half g_wot [DD*DD];
__device__ __half g_wet [EE*DD*HID];
__device__ __half g_ksp [BB*NWIN*GG*256*64];
__device__ __half g_vsp [BB*NWIN*GG*64*256];
__device__ float  g_moe [2*NTOK*HID];
__device__ float g_bqkv[QKVC];
__device__ int   g_ecount[EE];
__device__ float g_entsum;
__device__ int   g_etok[EE*NTOK];   // tok*2 + slot
__device__ float g_ewt [EE*NTOK];

// ---------------- helpers ----------------
__device__ __forceinline__ uint32_t su32(const void* p) {
    uint32_t r;
    asm("{ .reg .u64 t; cvta.to.shared.u64 t, %1; cvt.u32.u64 %0, t; }" : "=r"(r) : "l"(p));
    return r;
}
#define CP16(dst, src) asm volatile("cp.async.cg.shared.global [%0], [%1], 16;" :: "r"(dst), "l"(src))
#define CP_COMMIT()    asm volatile("cp.async.commit_group;" ::: "memory")
#define CP_WAIT0()     asm volatile("cp.async.wait_group 0;" ::: "memory")
#define CP_WAIT1()     asm volatile("cp.async.wait_group 1;" ::: "memory")
#define CP_WAIT2()     asm volatile("cp.async.wait_group 2;" ::: "memory")

#define LDSM4(r0, r1, r2, r3, addr) \
    asm volatile("ldmatrix.sync.aligned.m8n8.x4.shared.b16 {%0,%1,%2,%3}, [%4];" \
                 : "=r"(r0), "=r"(r1), "=r"(r2), "=r"(r3) : "r"(addr))

__device__ __forceinline__ void mma_f16(float* c, const uint32_t* a, const uint32_t* b) {
    asm volatile(
        "mma.sync.aligned.m16n8k16.row.col.f32.f16.f16.f32 "
        "{%0,%1,%2,%3}, {%4,%5,%6,%7}, {%8,%9}, {%0,%1,%2,%3};"
        : "+f"(c[0]), "+f"(c[1]), "+f"(c[2]), "+f"(c[3])
        : "r"(a[0]), "r"(a[1]), "r"(a[2]), "r"(a[3]), "r"(b[0]), "r"(b[1]));
}
__device__ __forceinline__ uint32_t packh(__half lo, __half hi) {
    return (uint32_t)__half_as_ushort(lo) | ((uint32_t)__half_as_ushort(hi) << 16);
}

// ---------------- zero bookkeeping ----------------
__global__ void zero_kernel() {
    int t = threadIdx.x;
    if (t < EE) g_ecount[t] = 0;
    if (t == EE) g_entsum = 0.f;
}

// ---------------- fused weight transpose + fp16 convert (one launch) ------
// blocks: [0,1024) Wq | [1024,1152) Wk | [1152,1280) Wv | [1280,2304) Wo |
//         [2304,10496) We (1024 per expert)
__global__ void __launch_bounds__(256)
transpose_all(const float* __restrict__ Wq, const float* __restrict__ Wk,
              const float* __restrict__ Wv, const float* __restrict__ Wo,
              const float* __restrict__ We) {
    __shared__ float t[32][33];
    int bid = blockIdx.x;
    const float* src;
    __half* dh;
    int cols, rowOff, bx, by;
    size_t dstOff = 0;
    if (bid < 1024) {
        src = Wq; dh = g_wqkv; cols = DD; rowOff = 0;
        bx = bid & 31; by = bid >> 5;
    } else if (bid < 1152) {
        int r = bid - 1024;
        src = Wk; dh = g_wqkv; cols = KVD; rowOff = DD;
        bx = r & 3; by = r >> 2;
    } else if (bid < 1280) {
        int r = bid - 1152;
        src = Wv; dh = g_wqkv; cols = KVD; rowOff = DD + KVD;
        bx = r & 3; by = r >> 2;
    } else if (bid < 2304) {
        int r = bid - 1280;
        src = Wo; dh = g_wot; cols = DD; rowOff = 0;
        bx = r & 31; by = r >> 5;
    } else {
        int r = bid - 2304;
        int e = r >> 10; r &= 1023;
        src = We + (size_t)e * DD * HID;
        dh = g_wet; dstOff = (size_t)e * DD * HID;
        cols = HID; rowOff = 0;
        bx = r & 31; by = r >> 5;
    }
    int c0 = bx * 32, r0 = by * 32;
    int tx = threadIdx.x, ty = threadIdx.y;
    #pragma unroll
    for (int i = 0; i < 32; i += 8)
        t[ty + i][tx] = src[(size_t)(r0 + ty + i) * cols + c0 + tx];
    __syncthreads();
    #pragma unroll
    for (int i = 0; i < 32; i += 8) {
        size_t o = dstOff + (size_t)(c0 + ty + i + rowOff) * DD + r0 + tx;
        dh[o] = __float2half_rn(t[tx][ty + i]);
    }
}

__global__ void bqkv_kernel(const float* __restrict__ bq, const float* __restrict__ bk,
                            const float* __restrict__ bv) {
    int t = threadIdx.x + blockIdx.x * 256;
    if (t < DD) g_bqkv[t] = bq[t];
    else if (t < DD + KVD) g_bqkv[t] = bk[t - DD];
    else if (t < QKVC) g_bqkv[t] = bv[t - DD - KVD];
}

// ---------------- LayerNorm (fp16 output) ----------
__global__ void ln_kernel(const float* __restrict__ x, const float* __restrict__ g,
                          const float* __restrict__ b, __half* __restrict__ y) {
    int row = blockIdx.x;
    const float4* xr = (const float4*)(x + (size_t)row * DD);
    int tid = threadIdx.x;
    float4 v = xr[tid];
    float s  = v.x + v.y + v.z + v.w;
    float ss = v.x*v.x + v.y*v.y + v.z*v.z + v.w*v.w;
    #pragma unroll
    for (int o = 16; o > 0; o >>= 1) {
        s  += __shfl_down_sync(0xffffffffu, s,  o);
        ss += __shfl_down_sync(0xffffffffu, ss, o);
    }
    __shared__ float sh_s[8], sh_ss[8];
    __shared__ float s_mean, s_rstd;
    int warp = tid >> 5, lane = tid & 31;
    if (lane == 0) { sh_s[warp] = s; sh_ss[warp] = ss; }
    __syncthreads();
    if (tid == 0) {
        float S = 0.f, SS = 0.f;
        #pragma unroll
        for (int i = 0; i < 8; i++) { S += sh_s[i]; SS += sh_ss[i]; }
        float mean = S / (float)DD;
        float var  = SS / (float)DD - mean * mean;
        s_mean = mean;
        s_rstd = rsqrtf(var + 1e-5f);
    }
    __syncthreads();
    float mean = s_mean, rstd = s_rstd;
    float4 gg = ((const float4*)g)[tid];
    float4 bb = ((const float4*)b)[tid];
    float o[4];
    o[0] = (v.x - mean) * rstd * gg.x + bb.x;
    o[1] = (v.y - mean) * rstd * gg.y + bb.y;
    o[2] = (v.z - mean) * rstd * gg.z + bb.z;
    o[3] = (v.w - mean) * rstd * gg.w + bb.w;
    size_t base = (size_t)row * DD + tid * 4;
    uint32_t p0 = packh(__float2half_rn(o[0]), __float2half_rn(o[1]));
    uint32_t p1 = packh(__float2half_rn(o[2]), __float2half_rn(o[3]));
    *(uint2*)&y[base] = make_uint2(p0, p1);
}

// ---------------- LN2 + MoE gate fused ----------------
__global__ void ln2_gate_kernel(const float* __restrict__ x, const float* __restrict__ g,
                                const float* __restrict__ b,
                                const float* __restrict__ Wg, const float* __restrict__ bg,
                                __half* __restrict__ y) {
    int row = blockIdx.x;
    const float4* xr = (const float4*)(x + (size_t)row * DD);
    int tid = threadIdx.x;
    float4 v = xr[tid];
    float s  = v.x + v.y + v.z + v.w;
    float ss = v.x*v.x + v.y*v.y + v.z*v.z + v.w*v.w;
    #pragma unroll
    for (int o = 16; o > 0; o >>= 1) {
        s  += __shfl_down_sync(0xffffffffu, s,  o);
        ss += __shfl_down_sync(0xffffffffu, ss, o);
    }
    __shared__ float sh_s[8], sh_ss[8];
    __shared__ float s_mean, s_rstd;
    __shared__ float red[8][8];
    int warp = tid >> 5, lane = tid & 31;
    if (lane == 0) { sh_s[warp] = s; sh_ss[warp] = ss; }
    __syncthreads();
    if (tid == 0) {
        float S = 0.f, SS = 0.f;
        #pragma unroll
        for (int i = 0; i < 8; i++) { S += sh_s[i]; SS += sh_ss[i]; }
        float mean = S / (float)DD;
        float var  = SS / (float)DD - mean * mean;
        s_mean = mean;
        s_rstd = rsqrtf(var + 1e-5f);
    }
    __syncthreads();
    float mean = s_mean, rstd = s_rstd;
    float4 gg = ((const float4*)g)[tid];
    float4 bb = ((const float4*)b)[tid];
    float o[4];
    o[0] = (v.x - mean) * rstd * gg.x + bb.x;
    o[1] = (v.y - mean) * rstd * gg.y + bb.y;
    o[2] = (v.z - mean) * rstd * gg.z + bb.z;
    o[3] = (v.w - mean) * rstd * gg.w + bb.w;
    size_t base = (size_t)row * DD + tid * 4;
    uint32_t p0 = packh(__float2half_rn(o[0]), __float2half_rn(o[1]));
    uint32_t p1 = packh(__float2half_rn(o[2]), __float2half_rn(o[3]));
    *(uint2*)&y[base] = make_uint2(p0, p1);

    // ---- gating from in-register LN output ----
    float pr[EE];
    #pragma unroll
    for (int e = 0; e < EE; e++) pr[e] = 0.f;
    #pragma unroll
    for (int i = 0; i < 4; i++) {
        float4 w0 = ((const float4*)Wg)[(tid * 4 + i) * 2];
        float4 w1 = ((const float4*)Wg)[(tid * 4 + i) * 2 + 1];
        pr[0] += o[i] * w0.x; pr[1] += o[i] * w0.y;
        pr[2] += o[i] * w0.z; pr[3] += o[i] * w0.w;
        pr[4] += o[i] * w1.x; pr[5] += o[i] * w1.y;
        pr[6] += o[i] * w1.z; pr[7] += o[i] * w1.w;
    }
    #pragma unroll
    for (int off = 16; off > 0; off >>= 1)
        #pragma unroll
        for (int e = 0; e < EE; e++)
            pr[e] += __shfl_down_sync(0xffffffffu, pr[e], off);
    if (lane == 0)
        #pragma unroll
        for (int e = 0; e < EE; e++) red[warp][e] = pr[e];
    __syncthreads();
    if (tid == 0) {
        float l[EE], m = -3.4e38f;
        #pragma unroll
        for (int e = 0; e < EE; e++) {
            float sum = bg[e];
            #pragma unroll
            for (int w = 0; w < 8; w++) sum += red[w][e];
            l[e] = sum;
            m = fmaxf(m, sum);
        }
        float p[EE], sm = 0.f;
        #pragma unroll
        for (int e = 0; e < EE; e++) { p[e] = __expf(l[e] - m); sm += p[e]; }
        float invs = 1.f / sm, ent = 0.f;
        #pragma unroll
        for (int e = 0; e < EE; e++) {
            p[e] *= invs;
            ent -= p[e] * logf(p[e] + 1e-8f);
        }
        atomicAdd(&g_entsum, ent);
        int i1 = 0;
        #pragma unroll
        for (int e = 1; e < EE; e++) if (p[e] > p[i1]) i1 = e;
        int i2 = (i1 == 0) ? 1 : 0;
        #pragma unroll
        for (int e = 0; e < EE; e++) if (e != i1 && p[e] > p[i2]) i2 = e;
        int s1 = atomicAdd(&g_ecount[i1], 1);
        g_etok[i1 * NTOK + s1] = row * 2 + 0; g_ewt[i1 * NTOK + s1] = p[i1];
        int s2 = atomicAdd(&g_ecount[i2], 1);
        g_etok[i2 * NTOK + s2] = row * 2 + 1; g_ewt[i2 * NTOK + s2] = p[i2];
    }
}

// ---------------- fp16 single-pass mma.sync GEMM (4-stage, 2 CTA/SM) ------
// MODE 0: C = acc + bias
// MODE 2: C = acc + bias + resid
// MODE 3: MoE gathered rows; store w*(acc+bias) to g_moe[slot][tok]
template<int MODE>
__global__ void __launch_bounds__(256)
tc_gemm(const __half* __restrict__ A, const __half* __restrict__ B,
        const float* __restrict__ bias, const float* __restrict__ resid,
        float* __restrict__ C, int ldc) {
    __shared__ int   stok[128];
    __shared__ float swt[128];
    extern __shared__ __half smb[];

    int row0 = blockIdx.y * 128;
    int col0 = blockIdx.x * 128;
    int tid = threadIdx.x, wid = tid >> 5, lane = tid & 31;
    int quad = lane >> 2, tq = lane & 3;
    int wm = wid & 1, wn = wid >> 1;

    if (MODE == 3) {
        int e = blockIdx.z;
        int cnt = g_ecount[e];
        if (row0 >= cnt) return;
        B    += (size_t)e * DD * HID;
        bias += (size_t)e * HID;
        if (tid < 128) {
            int r = row0 + tid;
            if (r < cnt) { stok[tid] = g_etok[e * NTOK + r]; swt[tid] = g_ewt[e * NTOK + r]; }
            else         { stok[tid] = -1; swt[tid] = 0.f; }
        }
        __syncthreads();
    }

    int crow = tid >> 2;
    int seg  = tid & 3;
    const __half *sa[2], *sb[2];
    uint32_t doff[2];
    #pragma unroll
    for (int i = 0; i < 2; i++) {
        int r = crow + 64 * i;
        int tok;
        if (MODE == 3) { int t2 = stok[r]; tok = (t2 < 0) ? 0 : (t2 >> 1); }
        else           tok = row0 + r;
        sa[i] = A + (size_t)tok * DD + seg * 8;
        sb[i] = B + (size_t)(col0 + r) * DD + seg * 8;
        doff[i] = (uint32_t)(r * (BSTR * 2) + seg * 16);
    }
    uint32_t sbase = su32(smb);

    int lrow = lane & 15, lhalf = lane >> 4;
    uint32_t aLane = (uint32_t)(((wm * 64 + lrow) * BSTR + lhalf * 8) * 2);
    uint32_t bLane = (uint32_t)(((wn * 32 + lrow) * BSTR + lhalf * 8) * 2);

    float acc[4][4][4];
    #pragma unroll
    for (int mt = 0; mt < 4; mt++)
        #pragma unroll
        for (int nt = 0; nt < 4; nt++)
            #pragma unroll
            for (int i = 0; i < 4; i++) acc[mt][nt][i] = 0.f;

    // prologue: chunks 0,1,2 into stages 0,1,2
    #pragma unroll
    for (int pc = 0; pc < 3; pc++) {
        uint32_t base = sbase + pc * BUFB;
        int k0 = pc * TCK;
        #pragma unroll
        for (int i = 0; i < 2; i++) {
            CP16(base + 0 * TILEB + doff[i], sa[i] + k0);
            CP16(base + 1 * TILEB + doff[i], sb[i] + k0);
        }
        CP_COMMIT();
    }

    for (int c = 0; c < NCH; c++) {
        if (c == NCH - 1) CP_WAIT0();
        else if (c == NCH - 2) CP_WAIT1();
        else CP_WAIT2();
        __syncthreads();
        if (c + 3 < NCH) {
            uint32_t base = sbase + ((c + 3) & 3) * BUFB;
            int k0 = (c + 3) * TCK;
            #pragma unroll
            for (int i = 0; i < 2; i++) {
                CP16(base + 0 * TILEB + doff[i], sa[i] + k0);
                CP16(base + 1 * TILEB + doff[i], sb[i] + k0);
            }
            CP_COMMIT();
        }

        uint32_t sbuf = sbase + (c & 3) * BUFB;
        #pragma unroll
        for (int kk = 0; kk < 2; kk++) {
            uint32_t kof = kk * 16 * 2;
            uint32_t bh[4][2];
            uint32_t bb0 = sbuf + 1 * TILEB + bLane + kof;
            LDSM4(bh[0][0], bh[1][0], bh[0][1], bh[1][1], bb0);
            LDSM4(bh[2][0], bh[3][0], bh[2][1], bh[3][1], bb0 + 16 * BSTR * 2);
            #pragma unroll
            for (int mt = 0; mt < 4; mt++) {
                uint32_t ah[4];
                uint32_t aa = sbuf + aLane + kof + mt * 16 * BSTR * 2;
                LDSM4(ah[0], ah[1], ah[2], ah[3], aa);
                #pragma unroll
                for (int nt = 0; nt < 4; nt++)
                    mma_f16(acc[mt][nt], ah, bh[nt]);
            }
        }
    }

    #pragma unroll
    for (int mt = 0; mt < 4; mt++) {
        #pragma unroll
        for (int half = 0; half < 2; half++) {
            int lr = wm * 64 + mt * 16 + quad + half * 8;
            int r = row0 + lr;
            #pragma unroll
            for (int nt = 0; nt < 4; nt++) {
                int col = col0 + wn * 32 + nt * 8 + tq * 2;
                float v0 = acc[mt][nt][half * 2 + 0] + bias[col];
                float v1 = acc[mt][nt][half * 2 + 1] + bias[col + 1];
                if (MODE == 0) {
                    *(float2*)&C[(size_t)r * ldc + col] = make_float2(v0, v1);
                } else if (MODE == 2) {
                    size_t o = (size_t)r * ldc + col;
                    float2 rr = *(const float2*)&resid[o];
                    *(float2*)&C[o] = make_float2(v0 + rr.x, v1 + rr.y);
                } else {
                    int t2 = stok[lr];
                    if (t2 >= 0) {
                        int tok = t2 >> 1, slot = t2 & 1;
                        float w = swt[lr];
                        size_t o = ((size_t)slot * NTOK + tok) * HID + col;
                        *(float2*)&g_moe[o] = make_float2(w * v0, w * v1);
                    }
                }
            }
        }
    }
}

// ---------------- K/V pre-convert (once per window/group/batch) -----------
// K: [tile][key 256][dim 64] fp16. V transposed: [tile][dim 64][key 256].
__global__ void __launch_bounds__(256)
kvsplit_kernel(const float* __restrict__ qkv) {
    int n = blockIdx.x, g = blockIdx.y, b = blockIdx.z;
    int key = threadIdx.x;
    int base = b * LL + n * 128;
    const float* kp = qkv + (size_t)(base + key) * QKVC + DD + g * 64;
    size_t tileid = ((size_t)b * NWIN + n) * GG + g;
    __half* kh = g_ksp + (tileid * 256 + key) * 64;
    size_t vb = tileid * 64 * 256 + key;
    #pragma unroll
    for (int d = 0; d < 64; d += 4) {
        float4 kk = *(const float4*)(kp + d);
        uint32_t p0 = packh(__float2half_rn(kk.x), __float2half_rn(kk.y));
        uint32_t p1 = packh(__float2half_rn(kk.z), __float2half_rn(kk.w));
        *(uint2*)&kh[d] = make_uint2(p0, p1);
        float4 vv = *(const float4*)(kp + KVD + d);
        float va[4] = {vv.x, vv.y, vv.z, vv.w};
        #pragma unroll
        for (int e = 0; e < 4; e++)
            g_vsp[vb + (size_t)(d + e) * 256] = __float2half_rn(va[e]);
    }
}

// ---------------- tensor-core attention (fp16 single-pass) -----------------
__global__ void __launch_bounds__(256)
attn_kernel(const float* __restrict__ qkv, __half* __restrict__ oatt) {
    extern __shared__ __half sma[];
    __half* Qh = sma;                  // 256 x APAD
    __half* Kh = Qh + 256 * APAD;      // 64 x APAD
    __half* Vh = Kh + 64 * APAD;       // [dim][key]

    int n = blockIdx.x, h = blockIdx.y, b = blockIdx.z;
    int g = h & (GG - 1);
    int base = b * LL + n * 128;
    int tid = threadIdx.x, wid = tid >> 5, lane = tid & 31;
    int quad = lane >> 2, tq = lane & 3;
    int lrow = lane & 15, lhalf = lane >> 4;
    size_t tileid = ((size_t)b * NWIN + n) * GG + g;

    // load Q (scaled), fp16
    {
        const float4* qp = (const float4*)(qkv + (size_t)(base + tid) * QKVC + h * 64);
        #pragma unroll
        for (int c = 0; c < 16; c++) {
            float4 q4 = qp[c];
            uint32_t p0 = packh(__float2half_rn(q4.x * 0.125f), __float2half_rn(q4.y * 0.125f));
            uint32_t p1 = packh(__float2half_rn(q4.z * 0.125f), __float2half_rn(q4.w * 0.125f));
            *(uint2*)&Qh[tid * APAD + c * 4] = make_uint2(p0, p1);
        }
    }

    float o[2][8][4];
    #pragma unroll
    for (int mt = 0; mt < 2; mt++)
        #pragma unroll
        for (int nt = 0; nt < 8; nt++)
            #pragma unroll
            for (int i = 0; i < 4; i++) o[mt][nt][i] = 0.f;
    float denomAcc[2][2] = {{0.f, 0.f}, {0.f, 0.f}};

    uint32_t qBase = su32(Qh), kBase = su32(Kh), vBase = su32(Vh);

    int trow = tid >> 2, tseg = tid & 3;
    const __half* ksrc = g_ksp + (tileid * 256 + trow) * 64;
    const __half* vsrc = g_vsp + (tileid * 64 + trow) * 256;
    uint32_t kdst = (uint32_t)(trow * APAD) * 2;

    for (int kt = 0; kt < 4; kt++) {
        __syncthreads();
        #pragma unroll
        for (int s2 = 0; s2 < 2; s2++) {
            int sg = tseg + s2 * 4;
            CP16(kBase + kdst + sg * 16, ksrc + (size_t)kt * 64 * 64 + sg * 8);
            CP16(vBase + kdst + sg * 16, vsrc + kt * 64 + sg * 8);
        }
        CP_COMMIT();
        CP_WAIT0();
        __syncthreads();

        // ---- S = Q @ K^T ----
        float s[2][8][4];
        #pragma unroll
        for (int mt = 0; mt < 2; mt++)
            #pragma unroll
            for (int nt = 0; nt < 8; nt++)
                #pragma unroll
                for (int i = 0; i < 4; i++) s[mt][nt][i] = 0.f;

        #pragma unroll
        for (int ks = 0; ks < 4; ks++) {
            uint32_t kof = (uint32_t)(ks * 16 + lhalf * 8) * 2;
            uint32_t ah[2][4];
            #pragma unroll
            for (int mt = 0; mt < 2; mt++) {
                uint32_t aa = qBase + (uint32_t)((wid * 32 + mt * 16 + lrow) * APAD) * 2 + kof;
                LDSM4(ah[mt][0], ah[mt][1], ah[mt][2], ah[mt][3], aa);
            }
            uint32_t bh[8][2];
            #pragma unroll
            for (int p = 0; p < 4; p++) {
                uint32_t bb = kBase + (uint32_t)((p * 16 + lrow) * APAD) * 2 + kof;
                LDSM4(bh[2*p][0], bh[2*p+1][0], bh[2*p][1], bh[2*p+1][1], bb);
            }
            #pragma unroll
            for (int mt = 0; mt < 2; mt++)
                #pragma unroll
                for (int nt = 0; nt < 8; nt++)
                    mma_f16(s[mt][nt], ah[mt], bh[nt]);
        }

        // ---- exp, denominators, pack P (fp16) ----
        uint32_t ph[2][8][2];
        #pragma unroll
        for (int mt = 0; mt < 2; mt++) {
            float d0 = 0.f, d1 = 0.f;
            #pragma unroll
            for (int nt = 0; nt < 8; nt++) {
                float p0 = __expf(fminf(s[mt][nt][0], 75.f));
                float p1 = __expf(fminf(s[mt][nt][1], 75.f));
                float p2 = __expf(fminf(s[mt][nt][2], 75.f));
                float p3 = __expf(fminf(s[mt][nt][3], 75.f));
                d0 += p0 + p1;
                d1 += p2 + p3;
                ph[mt][nt][0] = packh(__float2half_rn(p0), __float2half_rn(p1));
                ph[mt][nt][1] = packh(__float2half_rn(p2), __float2half_rn(p3));
            }
            d0 += __shfl_xor_sync(0xffffffffu, d0, 1);
            d0 += __shfl_xor_sync(0xffffffffu, d0, 2);
            d1 += __shfl_xor_sync(0xffffffffu, d1, 1);
            d1 += __shfl_xor_sync(0xffffffffu, d1, 2);
            denomAcc[mt][0] += d0;
            denomAcc[mt][1] += d1;
        }

        // ---- O += P @ V^T ----
        #pragma unroll
        for (int ks = 0; ks < 4; ks++) {
            uint32_t kof = (uint32_t)(ks * 16 + lhalf * 8) * 2;
            uint32_t bvh[8][2];
            #pragma unroll
            for (int p = 0; p < 4; p++) {
                uint32_t bb = vBase + (uint32_t)((p * 16 + lrow) * APAD) * 2 + kof;
                LDSM4(bvh[2*p][0], bvh[2*p+1][0], bvh[2*p][1], bvh[2*p+1][1], bb);
            }
            #pragma unroll
            for (int mt = 0; mt < 2; mt++) {
                uint32_t ah4[4] = { ph[mt][2*ks][0], ph[mt][2*ks][1],
                                    ph[mt][2*ks+1][0], ph[mt][2*ks+1][1] };
                #pragma unroll
                for (int nt = 0; nt < 8; nt++)
                    mma_f16(o[mt][nt], ah4, bvh[nt]);
            }
        }
    }

    // ---- epilogue ----
    #pragma unroll
    for (int mt = 0; mt < 2; mt++) {
        #pragma unroll
        for (int half = 0; half < 2; half++) {
            float inv = 1.f / denomAcc[mt][half];
            int tokout = b * LL + n * 256 + wid * 32 + mt * 16 + quad + half * 8;
            size_t rowb = (size_t)tokout * DD + h * 64;
            #pragma unroll
            for (int nt = 0; nt < 8; nt++) {
                float v0 = o[mt][nt][half * 2 + 0] * inv;
                float v1 = o[mt][nt][half * 2 + 1] * inv;
                int col = nt * 8 + tq * 2;
                *(uint32_t*)&oatt[rowb + col] = packh(__float2half_rn(v0), __float2half_rn(v1));
            }
        }
    }
}

// ---------------- MoE combine: out += moe0 + moe1 ----------------
__global__ void __launch_bounds__(256)
combine_kernel(float* __restrict__ out) {
    size_t i = ((size_t)blockIdx.x * 256 + threadIdx.x) * 4;
    float4 a  = *(float4*)&out[i];
    float4 m0 = *(const float4*)&g_moe[i];
    float4 m1 = *(const float4*)&g_moe[(size_t)NTOK * HID + i];
    a.x += m0.x + m1.x;
    a.y += m0.y + m1.y;
    a.z += m0.z + m1.z;
    a.w += m0.w + m1.w;
    *(float4*)&out[i] = a;
}

// ---------------- aux scalar ----------------
__global__ void aux_kernel(float* __restrict__ out, long long out_size) {
    if (threadIdx.x == 0 && blockIdx.x == 0) {
        float pen = 0.f;
        #pragma unroll
        for (int e = 0; e < EE; e++) {
            float usage = (float)g_ecount[e] / ((float)NTOK + 1e-8f);
            pen += fmaxf(usage - 0.4f, 0.f);
        }
        float ent = g_entsum / (float)NTOK;
        float aux = 0.05f * ent + pen;
        long long total = (long long)NTOK * HID;
        if (out_size > total) out[total] = aux;
    }
}

// ---------------- launch ----------------
extern "C" void kernel_launch(void* const* d_in, const int* in_sizes, int n_in,
                              void* d_out, int out_size) {
    const float* x     = (const float*)d_in[0];
    const float* Wq    = (const float*)d_in[1];
    const float* bq    = (const float*)d_in[2];
    const float* Wk    = (const float*)d_in[3];
    const float* bk    = (const float*)d_in[4];
    const float* Wv    = (const float*)d_in[5];
    const float* bv    = (const float*)d_in[6];
    const float* Wo    = (const float*)d_in[7];
    const float* bo    = (const float*)d_in[8];
    const float* ln1_g = (const float*)d_in[9];
    const float* ln1_b = (const float*)d_in[10];
    const float* ln2_g = (const float*)d_in[11];
    const float* ln2_b = (const float*)d_in[12];
    const float* Wg    = (const float*)d_in[13];
    const float* bg    = (const float*)d_in[14];
    const float* We    = (const float*)d_in[15];
    const float* be    = (const float*)d_in[16];
    float* out = (float*)d_out;

    __half *ln1, *att, *ln2, *wqkv, *wot, *wet;
    float *qkv, *bqkv;
    cudaGetSymbolAddress((void**)&ln1,  g_ln1);
    cudaGetSymbolAddress((void**)&qkv,  g_qkv);
    cudaGetSymbolAddress((void**)&att,  g_att);
    cudaGetSymbolAddress((void**)&ln2,  g_ln2);
    cudaGetSymbolAddress((void**)&wqkv, g_wqkv);
    cudaGetSymbolAddress((void**)&wot,  g_wot);
    cudaGetSymbolAddress((void**)&wet,  g_wet);
    cudaGetSymbolAddress((void**)&bqkv, g_bqkv);

    const int ASM = (256 + 64 + 64) * APAD * 2;   // 55296
    cudaFuncSetAttribute(attn_kernel, cudaFuncAttributeMaxDynamicSharedMemorySize, ASM);
    cudaFuncSetAttribute(tc_gemm<0>, cudaFuncAttributeMaxDynamicSharedMemorySize, GSMEM);
    cudaFuncSetAttribute(tc_gemm<2>, cudaFuncAttributeMaxDynamicSharedMemorySize, GSMEM);
    cudaFuncSetAttribute(tc_gemm<3>, cudaFuncAttributeMaxDynamicSharedMemorySize, GSMEM);

    zero_kernel<<<1, 32>>>();

    transpose_all<<<10496, dim3(32, 8)>>>(Wq, Wk, Wv, Wo, We);
    bqkv_kernel<<<(QKVC + 255) / 256, 256>>>(bq, bk, bv);

    ln_kernel<<<NTOK, 256>>>(x, ln1_g, ln1_b, ln1);

    tc_gemm<0><<<dim3(10, 64), 256, GSMEM>>>(ln1, wqkv, bqkv, nullptr, qkv, QKVC);

    kvsplit_kernel<<<dim3(NWIN, GG, BB), 256>>>(qkv);
    attn_kernel<<<dim3(NWIN, HH, BB), 256, ASM>>>(qkv, att);

    // out = x + attn@Wo + bo
    tc_gemm<2><<<dim3(8, 64), 256, GSMEM>>>(att, wot, bo, x, out, DD);

    ln2_gate_kernel<<<NTOK, 256>>>(out, ln2_g, ln2_b, Wg, bg, ln2);

    tc_gemm<3><<<dim3(8, 64, EE), 256, GSMEM>>>(ln2, wet, be, nullptr, nullptr, HID);

    combine_kernel<<<NTOK * HID / 1024, 256>>>(out);

    aux_kernel<<<1, 32>>>(out, (long long)out_size);
}

// round 12
// speedup vs baseline: 2.0379x; 1.0159x over previous
#include <cuda_runtime.h>
#include <cuda_fp16.h>
#include <math.h>
#include <stdint.h>

// Problem constants
#define BB 2
#define LL 4096
#define DD 1024
#define HH 16
#define GG 2
#define HD 64
#define KVD 128
#define KVC 256
#define QKVC 1280        // Q(1024) | K(128) | V(128)
#define EE 8
#define HID 1024
#define NTOK (BB*LL)     // 8192
#define NWIN 16
#define WIN 256
#define TCK 32           // K-chunk (32 fp16 columns per stage)
#define NCH (DD/TCK)     // 32 chunks
#define BSTR 40          // padded smem row stride (80B, ldmatrix conflict-free)
#define TILE (128*BSTR)
#define TILEB (TILE*2)   // 10240 bytes
#define BUFB (2*TILEB)   // one stage = A|B = 20480 bytes
#define NSTAGE 4
#define GSMEM (NSTAGE*BUFB)  // 81920 -> 2 CTAs/SM
#define APAD 72          // attention smem row stride

// ---------------- scratch (static device globals) ----------------
__device__ __half g_ln1 [NTOK*DD];
__device__ __half g_qh  [NTOK*DD];      // Q, pre-scaled by 1/8, fp16
__device__ float  g_kvf [NTOK*KVC];     // K|V compact fp32
__device__ __half g_att [NTOK*DD];
__device__ __half g_ln2 [NTOK*DD];
__device__ __half g_wqkv[QKVC*DD];
__device__ __half g_wot [DD*DD];
__device__ __half g_wet [EE*DD*HID];
__device__ __half g_ksp [BB*NWIN*GG*256*64];
__device__ __half g_vsp [BB*NWIN*GG*64*256];
__device__ __half g_moe [2*NTOK*HID];
__device__ float g_bqkv[QKVC];
__device__ int   g_ecount[EE];
__device__ float g_entsum;
__device__ int   g_etok[EE*NTOK];   // tok*2 + slot
__device__ float g_ewt [EE*NTOK];

// ---------------- helpers ----------------
__device__ __forceinline__ uint32_t su32(const void* p) {
    uint32_t r;
    asm("{ .reg .u64 t; cvta.to.shared.u64 t, %1; cvt.u32.u64 %0, t; }" : "=r"(r) : "l"(p));
    return r;
}
#define CP16(dst, src) asm volatile("cp.async.cg.shared.global [%0], [%1], 16;" :: "r"(dst), "l"(src))
#define CP_COMMIT()    asm volatile("cp.async.commit_group;" ::: "memory")
#define CP_WAIT0()     asm volatile("cp.async.wait_group 0;" ::: "memory")
#define CP_WAIT1()     asm volatile("cp.async.wait_group 1;" ::: "memory")
#define CP_WAIT2()     asm volatile("cp.async.wait_group 2;" ::: "memory")

#define LDSM4(r0, r1, r2, r3, addr) \
    asm volatile("ldmatrix.sync.aligned.m8n8.x4.shared.b16 {%0,%1,%2,%3}, [%4];" \
                 : "=r"(r0), "=r"(r1), "=r"(r2), "=r"(r3) : "r"(addr))

__device__ __forceinline__ void mma_f16(float* c, const uint32_t* a, const uint32_t* b) {
    asm volatile(
        "mma.sync.aligned.m16n8k16.row.col.f32.f16.f16.f32 "
        "{%0,%1,%2,%3}, {%4,%5,%6,%7}, {%8,%9}, {%0,%1,%2,%3};"
        : "+f"(c[0]), "+f"(c[1]), "+f"(c[2]), "+f"(c[3])
        : "r"(a[0]), "r"(a[1]), "r"(a[2]), "r"(a[3]), "r"(b[0]), "r"(b[1]));
}
__device__ __forceinline__ uint32_t packh(__half lo, __half hi) {
    return (uint32_t)__half_as_ushort(lo) | ((uint32_t)__half_as_ushort(hi) << 16);
}

// ---------------- zero bookkeeping ----------------
__global__ void zero_kernel() {
    int t = threadIdx.x;
    if (t < EE) g_ecount[t] = 0;
    if (t == EE) g_entsum = 0.f;
}

// ---------------- fused weight transpose + fp16 convert (one launch) ------
__global__ void __launch_bounds__(256)
transpose_all(const float* __restrict__ Wq, const float* __restrict__ Wk,
              const float* __restrict__ Wv, const float* __restrict__ Wo,
              const float* __restrict__ We) {
    __shared__ float t[32][33];
    int bid = blockIdx.x;
    const float* src;
    __half* dh;
    int cols, rowOff, bx, by;
    size_t dstOff = 0;
    if (bid < 1024) {
        src = Wq; dh = g_wqkv; cols = DD; rowOff = 0;
        bx = bid & 31; by = bid >> 5;
    } else if (bid < 1152) {
        int r = bid - 1024;
        src = Wk; dh = g_wqkv; cols = KVD; rowOff = DD;
        bx = r & 3; by = r >> 2;
    } else if (bid < 1280) {
        int r = bid - 1152;
        src = Wv; dh = g_wqkv; cols = KVD; rowOff = DD + KVD;
        bx = r & 3; by = r >> 2;
    } else if (bid < 2304) {
        int r = bid - 1280;
        src = Wo; dh = g_wot; cols = DD; rowOff = 0;
        bx = r & 31; by = r >> 5;
    } else {
        int r = bid - 2304;
        int e = r >> 10; r &= 1023;
        src = We + (size_t)e * DD * HID;
        dh = g_wet; dstOff = (size_t)e * DD * HID;
        cols = HID; rowOff = 0;
        bx = r & 31; by = r >> 5;
    }
    int c0 = bx * 32, r0 = by * 32;
    int tx = threadIdx.x, ty = threadIdx.y;
    #pragma unroll
    for (int i = 0; i < 32; i += 8)
        t[ty + i][tx] = src[(size_t)(r0 + ty + i) * cols + c0 + tx];
    __syncthreads();
    #pragma unroll
    for (int i = 0; i < 32; i += 8) {
        size_t o = dstOff + (size_t)(c0 + ty + i + rowOff) * DD + r0 + tx;
        dh[o] = __float2half_rn(t[tx][ty + i]);
    }
}

__global__ void bqkv_kernel(const float* __restrict__ bq, const float* __restrict__ bk,
                            const float* __restrict__ bv) {
    int t = threadIdx.x + blockIdx.x * 256;
    if (t < DD) g_bqkv[t] = bq[t];
    else if (t < DD + KVD) g_bqkv[t] = bk[t - DD];
    else if (t < QKVC) g_bqkv[t] = bv[t - DD - KVD];
}

// ---------------- LayerNorm (fp16 output) ----------
__global__ void ln_kernel(const float* __restrict__ x, const float* __restrict__ g,
                          const float* __restrict__ b, __half* __restrict__ y) {
    int row = blockIdx.x;
    const float4* xr = (const float4*)(x + (size_t)row * DD);
    int tid = threadIdx.x;
    float4 v = xr[tid];
    float s  = v.x + v.y + v.z + v.w;
    float ss = v.x*v.x + v.y*v.y + v.z*v.z + v.w*v.w;
    #pragma unroll
    for (int o = 16; o > 0; o >>= 1) {
        s  += __shfl_down_sync(0xffffffffu, s,  o);
        ss += __shfl_down_sync(0xffffffffu, ss, o);
    }
    __shared__ float sh_s[8], sh_ss[8];
    __shared__ float s_mean, s_rstd;
    int warp = tid >> 5, lane = tid & 31;
    if (lane == 0) { sh_s[warp] = s; sh_ss[warp] = ss; }
    __syncthreads();
    if (tid == 0) {
        float S = 0.f, SS = 0.f;
        #pragma unroll
        for (int i = 0; i < 8; i++) { S += sh_s[i]; SS += sh_ss[i]; }
        float mean = S / (float)DD;
        float var  = SS / (float)DD - mean * mean;
        s_mean = mean;
        s_rstd = rsqrtf(var + 1e-5f);
    }
    __syncthreads();
    float mean = s_mean, rstd = s_rstd;
    float4 gg = ((const float4*)g)[tid];
    float4 bb = ((const float4*)b)[tid];
    float o[4];
    o[0] = (v.x - mean) * rstd * gg.x + bb.x;
    o[1] = (v.y - mean) * rstd * gg.y + bb.y;
    o[2] = (v.z - mean) * rstd * gg.z + bb.z;
    o[3] = (v.w - mean) * rstd * gg.w + bb.w;
    size_t base = (size_t)row * DD + tid * 4;
    uint32_t p0 = packh(__float2half_rn(o[0]), __float2half_rn(o[1]));
    uint32_t p1 = packh(__float2half_rn(o[2]), __float2half_rn(o[3]));
    *(uint2*)&y[base] = make_uint2(p0, p1);
}

// ---------------- LN2 + MoE gate fused ----------------
__global__ void ln2_gate_kernel(const float* __restrict__ x, const float* __restrict__ g,
                                const float* __restrict__ b,
                                const float* __restrict__ Wg, const float* __restrict__ bg,
                                __half* __restrict__ y) {
    int row = blockIdx.x;
    const float4* xr = (const float4*)(x + (size_t)row * DD);
    int tid = threadIdx.x;
    float4 v = xr[tid];
    float s  = v.x + v.y + v.z + v.w;
    float ss = v.x*v.x + v.y*v.y + v.z*v.z + v.w*v.w;
    #pragma unroll
    for (int o = 16; o > 0; o >>= 1) {
        s  += __shfl_down_sync(0xffffffffu, s,  o);
        ss += __shfl_down_sync(0xffffffffu, ss, o);
    }
    __shared__ float sh_s[8], sh_ss[8];
    __shared__ float s_mean, s_rstd;
    __shared__ float red[8][8];
    int warp = tid >> 5, lane = tid & 31;
    if (lane == 0) { sh_s[warp] = s; sh_ss[warp] = ss; }
    __syncthreads();
    if (tid == 0) {
        float S = 0.f, SS = 0.f;
        #pragma unroll
        for (int i = 0; i < 8; i++) { S += sh_s[i]; SS += sh_ss[i]; }
        float mean = S / (float)DD;
        float var  = SS / (float)DD - mean * mean;
        s_mean = mean;
        s_rstd = rsqrtf(var + 1e-5f);
    }
    __syncthreads();
    float mean = s_mean, rstd = s_rstd;
    float4 gg = ((const float4*)g)[tid];
    float4 bb = ((const float4*)b)[tid];
    float o[4];
    o[0] = (v.x - mean) * rstd * gg.x + bb.x;
    o[1] = (v.y - mean) * rstd * gg.y + bb.y;
    o[2] = (v.z - mean) * rstd * gg.z + bb.z;
    o[3] = (v.w - mean) * rstd * gg.w + bb.w;
    size_t base = (size_t)row * DD + tid * 4;
    uint32_t p0 = packh(__float2half_rn(o[0]), __float2half_rn(o[1]));
    uint32_t p1 = packh(__float2half_rn(o[2]), __float2half_rn(o[3]));
    *(uint2*)&y[base] = make_uint2(p0, p1);

    // ---- gating from in-register LN output ----
    float pr[EE];
    #pragma unroll
    for (int e = 0; e < EE; e++) pr[e] = 0.f;
    #pragma unroll
    for (int i = 0; i < 4; i++) {
        float4 w0 = ((const float4*)Wg)[(tid * 4 + i) * 2];
        float4 w1 = ((const float4*)Wg)[(tid * 4 + i) * 2 + 1];
        pr[0] += o[i] * w0.x; pr[1] += o[i] * w0.y;
        pr[2] += o[i] * w0.z; pr[3] += o[i] * w0.w;
        pr[4] += o[i] * w1.x; pr[5] += o[i] * w1.y;
        pr[6] += o[i] * w1.z; pr[7] += o[i] * w1.w;
    }
    #pragma unroll
    for (int off = 16; off > 0; off >>= 1)
        #pragma unroll
        for (int e = 0; e < EE; e++)
            pr[e] += __shfl_down_sync(0xffffffffu, pr[e], off);
    if (lane == 0)
        #pragma unroll
        for (int e = 0; e < EE; e++) red[warp][e] = pr[e];
    __syncthreads();
    if (tid == 0) {
        float l[EE], m = -3.4e38f;
        #pragma unroll
        for (int e = 0; e < EE; e++) {
            float sum = bg[e];
            #pragma unroll
            for (int w = 0; w < 8; w++) sum += red[w][e];
            l[e] = sum;
            m = fmaxf(m, sum);
        }
        float p[EE], sm = 0.f;
        #pragma unroll
        for (int e = 0; e < EE; e++) { p[e] = __expf(l[e] - m); sm += p[e]; }
        float invs = 1.f / sm, ent = 0.f;
        #pragma unroll
        for (int e = 0; e < EE; e++) {
            p[e] *= invs;
            ent -= p[e] * logf(p[e] + 1e-8f);
        }
        atomicAdd(&g_entsum, ent);
        int i1 = 0;
        #pragma unroll
        for (int e = 1; e < EE; e++) if (p[e] > p[i1]) i1 = e;
        int i2 = (i1 == 0) ? 1 : 0;
        #pragma unroll
        for (int e = 0; e < EE; e++) if (e != i1 && p[e] > p[i2]) i2 = e;
        int s1 = atomicAdd(&g_ecount[i1], 1);
        g_etok[i1 * NTOK + s1] = row * 2 + 0; g_ewt[i1 * NTOK + s1] = p[i1];
        int s2 = atomicAdd(&g_ecount[i2], 1);
        g_etok[i2 * NTOK + s2] = row * 2 + 1; g_ewt[i2 * NTOK + s2] = p[i2];
    }
}

// ---------------- fp16 single-pass mma.sync GEMM (4-stage, 2 CTA/SM) ------
// MODE 1: QKV: cols<DD -> g_qh fp16 (scaled 1/8); cols>=DD -> g_kvf fp32
// MODE 2: C = acc + bias + resid
// MODE 3: MoE gathered rows; store fp16 w*(acc+bias) to g_moe[slot][tok]
template<int MODE>
__global__ void __launch_bounds__(256)
tc_gemm(const __half* __restrict__ A, const __half* __restrict__ B,
        const float* __restrict__ bias, const float* __restrict__ resid,
        float* __restrict__ C, int ldc) {
    __shared__ int   stok[128];
    __shared__ float swt[128];
    extern __shared__ __half smb[];

    int row0 = blockIdx.y * 128;
    int col0 = blockIdx.x * 128;
    int tid = threadIdx.x, wid = tid >> 5, lane = tid & 31;
    int quad = lane >> 2, tq = lane & 3;
    int wm = wid & 1, wn = wid >> 1;

    if (MODE == 3) {
        int e = blockIdx.z;
        int cnt = g_ecount[e];
        if (row0 >= cnt) return;
        B    += (size_t)e * DD * HID;
        bias += (size_t)e * HID;
        if (tid < 128) {
            int r = row0 + tid;
            if (r < cnt) { stok[tid] = g_etok[e * NTOK + r]; swt[tid] = g_ewt[e * NTOK + r]; }
            else         { stok[tid] = -1; swt[tid] = 0.f; }
        }
        __syncthreads();
    }

    int crow = tid >> 2;
    int seg  = tid & 3;
    const __half *sa[2], *sb[2];
    uint32_t doff[2];
    #pragma unroll
    for (int i = 0; i < 2; i++) {
        int r = crow + 64 * i;
        int tok;
        if (MODE == 3) { int t2 = stok[r]; tok = (t2 < 0) ? 0 : (t2 >> 1); }
        else           tok = row0 + r;
        sa[i] = A + (size_t)tok * DD + seg * 8;
        sb[i] = B + (size_t)(col0 + r) * DD + seg * 8;
        doff[i] = (uint32_t)(r * (BSTR * 2) + seg * 16);
    }
    uint32_t sbase = su32(smb);

    int lrow = lane & 15, lhalf = lane >> 4;
    uint32_t aLane = (uint32_t)(((wm * 64 + lrow) * BSTR + lhalf * 8) * 2);
    uint32_t bLane = (uint32_t)(((wn * 32 + lrow) * BSTR + lhalf * 8) * 2);

    float acc[4][4][4];
    #pragma unroll
    for (int mt = 0; mt < 4; mt++)
        #pragma unroll
        for (int nt = 0; nt < 4; nt++)
            #pragma unroll
            for (int i = 0; i < 4; i++) acc[mt][nt][i] = 0.f;

    // prologue: chunks 0,1,2 into stages 0,1,2
    #pragma unroll
    for (int pc = 0; pc < 3; pc++) {
        uint32_t base = sbase + pc * BUFB;
        int k0 = pc * TCK;
        #pragma unroll
        for (int i = 0; i < 2; i++) {
            CP16(base + 0 * TILEB + doff[i], sa[i] + k0);
            CP16(base + 1 * TILEB + doff[i], sb[i] + k0);
        }
        CP_COMMIT();
    }

    for (int c = 0; c < NCH; c++) {
        if (c == NCH - 1) CP_WAIT0();
        else if (c == NCH - 2) CP_WAIT1();
        else CP_WAIT2();
        __syncthreads();
        if (c + 3 < NCH) {
            uint32_t base = sbase + ((c + 3) & 3) * BUFB;
            int k0 = (c + 3) * TCK;
            #pragma unroll
            for (int i = 0; i < 2; i++) {
                CP16(base + 0 * TILEB + doff[i], sa[i] + k0);
                CP16(base + 1 * TILEB + doff[i], sb[i] + k0);
            }
            CP_COMMIT();
        }

        uint32_t sbuf = sbase + (c & 3) * BUFB;
        #pragma unroll
        for (int kk = 0; kk < 2; kk++) {
            uint32_t kof = kk * 16 * 2;
            uint32_t bh[4][2];
            uint32_t bb0 = sbuf + 1 * TILEB + bLane + kof;
            LDSM4(bh[0][0], bh[1][0], bh[0][1], bh[1][1], bb0);
            LDSM4(bh[2][0], bh[3][0], bh[2][1], bh[3][1], bb0 + 16 * BSTR * 2);
            #pragma unroll
            for (int mt = 0; mt < 4; mt++) {
                uint32_t ah[4];
                uint32_t aa = sbuf + aLane + kof + mt * 16 * BSTR * 2;
                LDSM4(ah[0], ah[1], ah[2], ah[3], aa);
                #pragma unroll
                for (int nt = 0; nt < 4; nt++)
                    mma_f16(acc[mt][nt], ah, bh[nt]);
            }
        }
    }

    #pragma unroll
    for (int mt = 0; mt < 4; mt++) {
        #pragma unroll
        for (int half = 0; half < 2; half++) {
            int lr = wm * 64 + mt * 16 + quad + half * 8;
            int r = row0 + lr;
            #pragma unroll
            for (int nt = 0; nt < 4; nt++) {
                int col = col0 + wn * 32 + nt * 8 + tq * 2;
                float v0 = acc[mt][nt][half * 2 + 0] + bias[col];
                float v1 = acc[mt][nt][half * 2 + 1] + bias[col + 1];
                if (MODE == 1) {
                    if (col < DD) {
                        // Q: pre-scaled fp16
                        *(uint32_t*)&g_qh[(size_t)r * DD + col] =
                            packh(__float2half_rn(v0 * 0.125f), __float2half_rn(v1 * 0.125f));
                    } else {
                        *(float2*)&g_kvf[(size_t)r * KVC + col - DD] = make_float2(v0, v1);
                    }
                } else if (MODE == 2) {
                    size_t o = (size_t)r * ldc + col;
                    float2 rr = *(const float2*)&resid[o];
                    *(float2*)&C[o] = make_float2(v0 + rr.x, v1 + rr.y);
                } else {
                    int t2 = stok[lr];
                    if (t2 >= 0) {
                        int tok = t2 >> 1, slot = t2 & 1;
                        float w = swt[lr];
                        size_t o = ((size_t)slot * NTOK + tok) * HID + col;
                        *(uint32_t*)&g_moe[o] =
                            packh(__float2half_rn(w * v0), __float2half_rn(w * v1));
                    }
                }
            }
        }
    }
}

// ---------------- K/V pre-convert (once per window/group/batch) -----------
// K: [tile][key 256][dim 64] fp16. V transposed: [tile][dim 64][key 256].
__global__ void __launch_bounds__(256)
kvsplit_kernel() {
    int n = blockIdx.x, g = blockIdx.y, b = blockIdx.z;
    int key = threadIdx.x;
    int base = b * LL + n * 128;
    const float* kp = g_kvf + (size_t)(base + key) * KVC + g * 64;
    size_t tileid = ((size_t)b * NWIN + n) * GG + g;
    __half* kh = g_ksp + (tileid * 256 + key) * 64;
    size_t vb = tileid * 64 * 256 + key;
    #pragma unroll
    for (int d = 0; d < 64; d += 4) {
        float4 kk = *(const float4*)(kp + d);
        uint32_t p0 = packh(__float2half_rn(kk.x), __float2half_rn(kk.y));
        uint32_t p1 = packh(__float2half_rn(kk.z), __float2half_rn(kk.w));
        *(uint2*)&kh[d] = make_uint2(p0, p1);
        float4 vv = *(const float4*)(kp + KVD + d);
        float va[4] = {vv.x, vv.y, vv.z, vv.w};
        #pragma unroll
        for (int e = 0; e < 4; e++)
            g_vsp[vb + (size_t)(d + e) * 256] = __float2half_rn(va[e]);
    }
}

// ---------------- tensor-core attention (fp16 single-pass) -----------------
__global__ void __launch_bounds__(256)
attn_kernel(__half* __restrict__ oatt) {
    extern __shared__ __half sma[];
    __half* Qh = sma;                  // 256 x APAD
    __half* Kh = Qh + 256 * APAD;      // 64 x APAD
    __half* Vh = Kh + 64 * APAD;       // [dim][key]

    int n = blockIdx.x, h = blockIdx.y, b = blockIdx.z;
    int g = h & (GG - 1);
    int base = b * LL + n * 128;
    int tid = threadIdx.x, wid = tid >> 5, lane = tid & 31;
    int quad = lane >> 2, tq = lane & 3;
    int lrow = lane & 15, lhalf = lane >> 4;
    size_t tileid = ((size_t)b * NWIN + n) * GG + g;

    uint32_t qBase = su32(Qh), kBase = su32(Kh), vBase = su32(Vh);

    // cp.async Q rows (pre-scaled fp16 in g_qh): each thread loads its row
    {
        const __half* qsrc = g_qh + (size_t)(base + tid) * DD + h * 64;
        uint32_t qdst = qBase + (uint32_t)(tid * APAD) * 2;
        #pragma unroll
        for (int s2 = 0; s2 < 8; s2++)
            CP16(qdst + s2 * 16, qsrc + s2 * 8);
        CP_COMMIT();
    }

    float o[2][8][4];
    #pragma unroll
    for (int mt = 0; mt < 2; mt++)
        #pragma unroll
        for (int nt = 0; nt < 8; nt++)
            #pragma unroll
            for (int i = 0; i < 4; i++) o[mt][nt][i] = 0.f;
    float denomAcc[2][2] = {{0.f, 0.f}, {0.f, 0.f}};

    int trow = tid >> 2, tseg = tid & 3;
    const __half* ksrc = g_ksp + (tileid * 256 + trow) * 64;
    const __half* vsrc = g_vsp + (tileid * 64 + trow) * 256;
    uint32_t kdst = (uint32_t)(trow * APAD) * 2;

    for (int kt = 0; kt < 4; kt++) {
        __syncthreads();
        #pragma unroll
        for (int s2 = 0; s2 < 2; s2++) {
            int sg = tseg + s2 * 4;
            CP16(kBase + kdst + sg * 16, ksrc + (size_t)kt * 64 * 64 + sg * 8);
            CP16(vBase + kdst + sg * 16, vsrc + kt * 64 + sg * 8);
        }
        CP_COMMIT();
        CP_WAIT0();
        __syncthreads();

        // ---- S = Q @ K^T ----
        float s[2][8][4];
        #pragma unroll
        for (int mt = 0; mt < 2; mt++)
            #pragma unroll
            for (int nt = 0; nt < 8; nt++)
                #pragma unroll
                for (int i = 0; i < 4; i++) s[mt][nt][i] = 0.f;

        #pragma unroll
        for (int ks = 0; ks < 4; ks++) {
            uint32_t kof = (uint32_t)(ks * 16 + lhalf * 8) * 2;
            uint32_t ah[2][4];
            #pragma unroll
            for (int mt = 0; mt < 2; mt++) {
                uint32_t aa = qBase + (uint32_t)((wid * 32 + mt * 16 + lrow) * APAD) * 2 + kof;
                LDSM4(ah[mt][0], ah[mt][1], ah[mt][2], ah[mt][3], aa);
            }
            uint32_t bh[8][2];
            #pragma unroll
            for (int p = 0; p < 4; p++) {
                uint32_t bb = kBase + (uint32_t)((p * 16 + lrow) * APAD) * 2 + kof;
                LDSM4(bh[2*p][0], bh[2*p+1][0], bh[2*p][1], bh[2*p+1][1], bb);
            }
            #pragma unroll
            for (int mt = 0; mt < 2; mt++)
                #pragma unroll
                for (int nt = 0; nt < 8; nt++)
                    mma_f16(s[mt][nt], ah[mt], bh[nt]);
        }

        // ---- exp, denominators, pack P (fp16) ----
        uint32_t ph[2][8][2];
        #pragma unroll
        for (int mt = 0; mt < 2; mt++) {
            float d0 = 0.f, d1 = 0.f;
            #pragma unroll
            for (int nt = 0; nt < 8; nt++) {
                float p0 = __expf(fminf(s[mt][nt][0], 75.f));
                float p1 = __expf(fminf(s[mt][nt][1], 75.f));
                float p2 = __expf(fminf(s[mt][nt][2], 75.f));
                float p3 = __expf(fminf(s[mt][nt][3], 75.f));
                d0 += p0 + p1;
                d1 += p2 + p3;
                ph[mt][nt][0] = packh(__float2half_rn(p0), __float2half_rn(p1));
                ph[mt][nt][1] = packh(__float2half_rn(p2), __float2half_rn(p3));
            }
            d0 += __shfl_xor_sync(0xffffffffu, d0, 1);
            d0 += __shfl_xor_sync(0xffffffffu, d0, 2);
            d1 += __shfl_xor_sync(0xffffffffu, d1, 1);
            d1 += __shfl_xor_sync(0xffffffffu, d1, 2);
            denomAcc[mt][0] += d0;
            denomAcc[mt][1] += d1;
        }

        // ---- O += P @ V^T ----
        #pragma unroll
        for (int ks = 0; ks < 4; ks++) {
            uint32_t kof = (uint32_t)(ks * 16 + lhalf * 8) * 2;
            uint32_t bvh[8][2];
            #pragma unroll
            for (int p = 0; p < 4; p++) {
                uint32_t bb = vBase + (uint32_t)((p * 16 + lrow) * APAD) * 2 + kof;
                LDSM4(bvh[2*p][0], bvh[2*p+1][0], bvh[2*p][1], bvh[2*p+1][1], bb);
            }
            #pragma unroll
            for (int mt = 0; mt < 2; mt++) {
                uint32_t ah4[4] = { ph[mt][2*ks][0], ph[mt][2*ks][1],
                                    ph[mt][2*ks+1][0], ph[mt][2*ks+1][1] };
                #pragma unroll
                for (int nt = 0; nt < 8; nt++)
                    mma_f16(o[mt][nt], ah4, bvh[nt]);
            }
        }
    }

    // ---- epilogue ----
    #pragma unroll
    for (int mt = 0; mt < 2; mt++) {
        #pragma unroll
        for (int half = 0; half < 2; half++) {
            float inv = 1.f / denomAcc[mt][half];
            int tokout = b * LL + n * 256 + wid * 32 + mt * 16 + quad + half * 8;
            size_t rowb = (size_t)tokout * DD + h * 64;
            #pragma unroll
            for (int nt = 0; nt < 8; nt++) {
                float v0 = o[mt][nt][half * 2 + 0] * inv;
                float v1 = o[mt][nt][half * 2 + 1] * inv;
                int col = nt * 8 + tq * 2;
                *(uint32_t*)&oatt[rowb + col] = packh(__float2half_rn(v0), __float2half_rn(v1));
            }
        }
    }
}

// ---------------- MoE combine: out += moe0 + moe1 (fp16 slots) -------------
__global__ void __launch_bounds__(256)
combine_kernel(float* __restrict__ out) {
    size_t i = ((size_t)blockIdx.x * 256 + threadIdx.x) * 4;
    float4 a = *(float4*)&out[i];
    const __half2* m0 = (const __half2*)&g_moe[i];
    const __half2* m1 = (const __half2*)&g_moe[(size_t)NTOK * HID + i];
    float2 a0 = __half22float2(m0[0]);
    float2 a1 = __half22float2(m0[1]);
    float2 b0 = __half22float2(m1[0]);
    float2 b1 = __half22float2(m1[1]);
    a.x += a0.x + b0.x;
    a.y += a0.y + b0.y;
    a.z += a1.x + b1.x;
    a.w += a1.y + b1.y;
    *(float4*)&out[i] = a;
}

// ---------------- aux scalar ----------------
__global__ void aux_kernel(float* __restrict__ out, long long out_size) {
    if (threadIdx.x == 0 && blockIdx.x == 0) {
        float pen = 0.f;
        #pragma unroll
        for (int e = 0; e < EE; e++) {
            float usage = (float)g_ecount[e] / ((float)NTOK + 1e-8f);
            pen += fmaxf(usage - 0.4f, 0.f);
        }
        float ent = g_entsum / (float)NTOK;
        float aux = 0.05f * ent + pen;
        long long total = (long long)NTOK * HID;
        if (out_size > total) out[total] = aux;
    }
}

// ---------------- launch ----------------
extern "C" void kernel_launch(void* const* d_in, const int* in_sizes, int n_in,
                              void* d_out, int out_size) {
    const float* x     = (const float*)d_in[0];
    const float* Wq    = (const float*)d_in[1];
    const float* bq    = (const float*)d_in[2];
    const float* Wk    = (const float*)d_in[3];
    const float* bk    = (const float*)d_in[4];
    const float* Wv    = (const float*)d_in[5];
    const float* bv    = (const float*)d_in[6];
    const float* Wo    = (const float*)d_in[7];
    const float* bo    = (const float*)d_in[8];
    const float* ln1_g = (const float*)d_in[9];
    const float* ln1_b = (const float*)d_in[10];
    const float* ln2_g = (const float*)d_in[11];
    const float* ln2_b = (const float*)d_in[12];
    const float* Wg    = (const float*)d_in[13];
    const float* bg    = (const float*)d_in[14];
    const float* We    = (const float*)d_in[15];
    const float* be    = (const float*)d_in[16];
    float* out = (float*)d_out;

    __half *ln1, *att, *ln2, *wqkv, *wot, *wet;
    float *bqkv;
    cudaGetSymbolAddress((void**)&ln1,  g_ln1);
    cudaGetSymbolAddress((void**)&att,  g_att);
    cudaGetSymbolAddress((void**)&ln2,  g_ln2);
    cudaGetSymbolAddress((void**)&wqkv, g_wqkv);
    cudaGetSymbolAddress((void**)&wot,  g_wot);
    cudaGetSymbolAddress((void**)&wet,  g_wet);
    cudaGetSymbolAddress((void**)&bqkv, g_bqkv);

    const int ASM = (256 + 64 + 64) * APAD * 2;   // 55296
    cudaFuncSetAttribute(attn_kernel, cudaFuncAttributeMaxDynamicSharedMemorySize, ASM);
    cudaFuncSetAttribute(tc_gemm<1>, cudaFuncAttributeMaxDynamicSharedMemorySize, GSMEM);
    cudaFuncSetAttribute(tc_gemm<2>, cudaFuncAttributeMaxDynamicSharedMemorySize, GSMEM);
    cudaFuncSetAttribute(tc_gemm<3>, cudaFuncAttributeMaxDynamicSharedMemorySize, GSMEM);

    zero_kernel<<<1, 32>>>();

    transpose_all<<<10496, dim3(32, 8)>>>(Wq, Wk, Wv, Wo, We);
    bqkv_kernel<<<(QKVC + 255) / 256, 256>>>(bq, bk, bv);

    ln_kernel<<<NTOK, 256>>>(x, ln1_g, ln1_b, ln1);

    // QKV GEMM: writes g_qh (fp16, scaled) + g_kvf (fp32 compact)
    tc_gemm<1><<<dim3(10, 64), 256, GSMEM>>>(ln1, wqkv, bqkv, nullptr, nullptr, 0);

    kvsplit_kernel<<<dim3(NWIN, GG, BB), 256>>>();
    attn_kernel<<<dim3(NWIN, HH, BB), 256, ASM>>>(att);

    // out = x + attn@Wo + bo
    tc_gemm<2><<<dim3(8, 64), 256, GSMEM>>>(att, wot, bo, x, out, DD);

    ln2_gate_kernel<<<NTOK, 256>>>(out, ln2_g, ln2_b, Wg, bg, ln2);

    tc_gemm<3><<<dim3(8, 64, EE), 256, GSMEM>>>(ln2, wet, be, nullptr, nullptr, HID);

    combine_kernel<<<NTOK * HID / 1024, 256>>>(out);

    aux_kernel<<<1, 32>>>(out, (long long)out_size);
}

// round 13
// speedup vs baseline: 2.0791x; 1.0202x over previous
#include <cuda_runtime.h>
#include <cuda_fp16.h>
#include <math.h>
#include <stdint.h>

// Problem constants
#define BB 2
#define LL 4096
#define DD 1024
#define HH 16
#define GG 2
#define HD 64
#define KVD 128
#define KVC 256
#define QKVC 1280        // Q(1024) | K(128) | V(128)
#define EE 8
#define HID 1024
#define NTOK (BB*LL)     // 8192
#define NWIN 16
#define WIN 256
#define TCK 32           // K-chunk (32 fp16 columns per stage)
#define NCH (DD/TCK)     // 32 chunks
#define BSTR 40          // padded smem row stride (80B, ldmatrix conflict-free)
#define TILE (128*BSTR)
#define TILEB (TILE*2)   // 10240 bytes
#define BUFB (2*TILEB)   // one stage = A|B = 20480 bytes
#define NSTAGE 4
#define GSMEM (NSTAGE*BUFB)  // 81920 -> 2 CTAs/SM
#define APAD 72          // attention smem row stride

// ---------------- scratch (static device globals) ----------------
__device__ __half g_ln1 [NTOK*DD];
__device__ __half g_qh  [NTOK*DD];      // Q, pre-scaled by 1/8, fp16
__device__ float  g_kvf [NTOK*KVC];     // K|V compact fp32
__device__ __half g_att [NTOK*DD];
__device__ __half g_ln2 [NTOK*DD];
__device__ __half g_wqkv[QKVC*DD];
__device__ __half g_wot [DD*DD];
__device__ __half g_wet [EE*DD*HID];
__device__ __half g_ksp [BB*NWIN*GG*256*64];
__device__ __half g_vsp [BB*NWIN*GG*64*256];
__device__ float g_bqkv[QKVC];
__device__ int   g_ecount[EE];
__device__ float g_entsum;
__device__ int   g_etok[EE*NTOK];   // tok*2 + slot
__device__ float g_ewt [EE*NTOK];

// ---------------- helpers ----------------
__device__ __forceinline__ uint32_t su32(const void* p) {
    uint32_t r;
    asm("{ .reg .u64 t; cvta.to.shared.u64 t, %1; cvt.u32.u64 %0, t; }" : "=r"(r) : "l"(p));
    return r;
}
#define CP16(dst, src) asm volatile("cp.async.cg.shared.global [%0], [%1], 16;" :: "r"(dst), "l"(src))
#define CP_COMMIT()    asm volatile("cp.async.commit_group;" ::: "memory")
#define CP_WAIT0()     asm volatile("cp.async.wait_group 0;" ::: "memory")
#define CP_WAIT1()     asm volatile("cp.async.wait_group 1;" ::: "memory")
#define CP_WAIT2()     asm volatile("cp.async.wait_group 2;" ::: "memory")

#define LDSM4(r0, r1, r2, r3, addr) \
    asm volatile("ldmatrix.sync.aligned.m8n8.x4.shared.b16 {%0,%1,%2,%3}, [%4];" \
                 : "=r"(r0), "=r"(r1), "=r"(r2), "=r"(r3) : "r"(addr))

__device__ __forceinline__ void mma_f16(float* c, const uint32_t* a, const uint32_t* b) {
    asm volatile(
        "mma.sync.aligned.m16n8k16.row.col.f32.f16.f16.f32 "
        "{%0,%1,%2,%3}, {%4,%5,%6,%7}, {%8,%9}, {%0,%1,%2,%3};"
        : "+f"(c[0]), "+f"(c[1]), "+f"(c[2]), "+f"(c[3])
        : "r"(a[0]), "r"(a[1]), "r"(a[2]), "r"(a[3]), "r"(b[0]), "r"(b[1]));
}
__device__ __forceinline__ uint32_t packh(__half lo, __half hi) {
    return (uint32_t)__half_as_ushort(lo) | ((uint32_t)__half_as_ushort(hi) << 16);
}

// ---------------- zero bookkeeping ----------------
__global__ void zero_kernel() {
    int t = threadIdx.x;
    if (t < EE) g_ecount[t] = 0;
    if (t == EE) g_entsum = 0.f;
}

// ---------------- fused weight transpose + fp16 convert (one launch) ------
__global__ void __launch_bounds__(256)
transpose_all(const float* __restrict__ Wq, const float* __restrict__ Wk,
              const float* __restrict__ Wv, const float* __restrict__ Wo,
              const float* __restrict__ We) {
    __shared__ float t[32][33];
    int bid = blockIdx.x;
    const float* src;
    __half* dh;
    int cols, rowOff, bx, by;
    size_t dstOff = 0;
    if (bid < 1024) {
        src = Wq; dh = g_wqkv; cols = DD; rowOff = 0;
        bx = bid & 31; by = bid >> 5;
    } else if (bid < 1152) {
        int r = bid - 1024;
        src = Wk; dh = g_wqkv; cols = KVD; rowOff = DD;
        bx = r & 3; by = r >> 2;
    } else if (bid < 1280) {
        int r = bid - 1152;
        src = Wv; dh = g_wqkv; cols = KVD; rowOff = DD + KVD;
        bx = r & 3; by = r >> 2;
    } else if (bid < 2304) {
        int r = bid - 1280;
        src = Wo; dh = g_wot; cols = DD; rowOff = 0;
        bx = r & 31; by = r >> 5;
    } else {
        int r = bid - 2304;
        int e = r >> 10; r &= 1023;
        src = We + (size_t)e * DD * HID;
        dh = g_wet; dstOff = (size_t)e * DD * HID;
        cols = HID; rowOff = 0;
        bx = r & 31; by = r >> 5;
    }
    int c0 = bx * 32, r0 = by * 32;
    int tx = threadIdx.x, ty = threadIdx.y;
    #pragma unroll
    for (int i = 0; i < 32; i += 8)
        t[ty + i][tx] = src[(size_t)(r0 + ty + i) * cols + c0 + tx];
    __syncthreads();
    #pragma unroll
    for (int i = 0; i < 32; i += 8) {
        size_t o = dstOff + (size_t)(c0 + ty + i + rowOff) * DD + r0 + tx;
        dh[o] = __float2half_rn(t[tx][ty + i]);
    }
}

__global__ void bqkv_kernel(const float* __restrict__ bq, const float* __restrict__ bk,
                            const float* __restrict__ bv) {
    int t = threadIdx.x + blockIdx.x * 256;
    if (t < DD) g_bqkv[t] = bq[t];
    else if (t < DD + KVD) g_bqkv[t] = bk[t - DD];
    else if (t < QKVC) g_bqkv[t] = bv[t - DD - KVD];
}

// ---------------- LayerNorm (fp16 output) ----------
__global__ void ln_kernel(const float* __restrict__ x, const float* __restrict__ g,
                          const float* __restrict__ b, __half* __restrict__ y) {
    int row = blockIdx.x;
    const float4* xr = (const float4*)(x + (size_t)row * DD);
    int tid = threadIdx.x;
    float4 v = xr[tid];
    float s  = v.x + v.y + v.z + v.w;
    float ss = v.x*v.x + v.y*v.y + v.z*v.z + v.w*v.w;
    #pragma unroll
    for (int o = 16; o > 0; o >>= 1) {
        s  += __shfl_down_sync(0xffffffffu, s,  o);
        ss += __shfl_down_sync(0xffffffffu, ss, o);
    }
    __shared__ float sh_s[8], sh_ss[8];
    __shared__ float s_mean, s_rstd;
    int warp = tid >> 5, lane = tid & 31;
    if (lane == 0) { sh_s[warp] = s; sh_ss[warp] = ss; }
    __syncthreads();
    if (tid == 0) {
        float S = 0.f, SS = 0.f;
        #pragma unroll
        for (int i = 0; i < 8; i++) { S += sh_s[i]; SS += sh_ss[i]; }
        float mean = S / (float)DD;
        float var  = SS / (float)DD - mean * mean;
        s_mean = mean;
        s_rstd = rsqrtf(var + 1e-5f);
    }
    __syncthreads();
    float mean = s_mean, rstd = s_rstd;
    float4 gg = ((const float4*)g)[tid];
    float4 bb = ((const float4*)b)[tid];
    float o[4];
    o[0] = (v.x - mean) * rstd * gg.x + bb.x;
    o[1] = (v.y - mean) * rstd * gg.y + bb.y;
    o[2] = (v.z - mean) * rstd * gg.z + bb.z;
    o[3] = (v.w - mean) * rstd * gg.w + bb.w;
    size_t base = (size_t)row * DD + tid * 4;
    uint32_t p0 = packh(__float2half_rn(o[0]), __float2half_rn(o[1]));
    uint32_t p1 = packh(__float2half_rn(o[2]), __float2half_rn(o[3]));
    *(uint2*)&y[base] = make_uint2(p0, p1);
}

// ---------------- LN2 + MoE gate fused ----------------
__global__ void ln2_gate_kernel(const float* __restrict__ x, const float* __restrict__ g,
                                const float* __restrict__ b,
                                const float* __restrict__ Wg, const float* __restrict__ bg,
                                __half* __restrict__ y) {
    int row = blockIdx.x;
    const float4* xr = (const float4*)(x + (size_t)row * DD);
    int tid = threadIdx.x;
    float4 v = xr[tid];
    float s  = v.x + v.y + v.z + v.w;
    float ss = v.x*v.x + v.y*v.y + v.z*v.z + v.w*v.w;
    #pragma unroll
    for (int o = 16; o > 0; o >>= 1) {
        s  += __shfl_down_sync(0xffffffffu, s,  o);
        ss += __shfl_down_sync(0xffffffffu, ss, o);
    }
    __shared__ float sh_s[8], sh_ss[8];
    __shared__ float s_mean, s_rstd;
    __shared__ float red[8][8];
    int warp = tid >> 5, lane = tid & 31;
    if (lane == 0) { sh_s[warp] = s; sh_ss[warp] = ss; }
    __syncthreads();
    if (tid == 0) {
        float S = 0.f, SS = 0.f;
        #pragma unroll
        for (int i = 0; i < 8; i++) { S += sh_s[i]; SS += sh_ss[i]; }
        float mean = S / (float)DD;
        float var  = SS / (float)DD - mean * mean;
        s_mean = mean;
        s_rstd = rsqrtf(var + 1e-5f);
    }
    __syncthreads();
    float mean = s_mean, rstd = s_rstd;
    float4 gg = ((const float4*)g)[tid];
    float4 bb = ((const float4*)b)[tid];
    float o[4];
    o[0] = (v.x - mean) * rstd * gg.x + bb.x;
    o[1] = (v.y - mean) * rstd * gg.y + bb.y;
    o[2] = (v.z - mean) * rstd * gg.z + bb.z;
    o[3] = (v.w - mean) * rstd * gg.w + bb.w;
    size_t base = (size_t)row * DD + tid * 4;
    uint32_t p0 = packh(__float2half_rn(o[0]), __float2half_rn(o[1]));
    uint32_t p1 = packh(__float2half_rn(o[2]), __float2half_rn(o[3]));
    *(uint2*)&y[base] = make_uint2(p0, p1);

    // ---- gating from in-register LN output ----
    float pr[EE];
    #pragma unroll
    for (int e = 0; e < EE; e++) pr[e] = 0.f;
    #pragma unroll
    for (int i = 0; i < 4; i++) {
        float4 w0 = ((const float4*)Wg)[(tid * 4 + i) * 2];
        float4 w1 = ((const float4*)Wg)[(tid * 4 + i) * 2 + 1];
        pr[0] += o[i] * w0.x; pr[1] += o[i] * w0.y;
        pr[2] += o[i] * w0.z; pr[3] += o[i] * w0.w;
        pr[4] += o[i] * w1.x; pr[5] += o[i] * w1.y;
        pr[6] += o[i] * w1.z; pr[7] += o[i] * w1.w;
    }
    #pragma unroll
    for (int off = 16; off > 0; off >>= 1)
        #pragma unroll
        for (int e = 0; e < EE; e++)
            pr[e] += __shfl_down_sync(0xffffffffu, pr[e], off);
    if (lane == 0)
        #pragma unroll
        for (int e = 0; e < EE; e++) red[warp][e] = pr[e];
    __syncthreads();
    if (tid == 0) {
        float l[EE], m = -3.4e38f;
        #pragma unroll
        for (int e = 0; e < EE; e++) {
            float sum = bg[e];
            #pragma unroll
            for (int w = 0; w < 8; w++) sum += red[w][e];
            l[e] = sum;
            m = fmaxf(m, sum);
        }
        float p[EE], sm = 0.f;
        #pragma unroll
        for (int e = 0; e < EE; e++) { p[e] = __expf(l[e] - m); sm += p[e]; }
        float invs = 1.f / sm, ent = 0.f;
        #pragma unroll
        for (int e = 0; e < EE; e++) {
            p[e] *= invs;
            ent -= p[e] * logf(p[e] + 1e-8f);
        }
        atomicAdd(&g_entsum, ent);
        int i1 = 0;
        #pragma unroll
        for (int e = 1; e < EE; e++) if (p[e] > p[i1]) i1 = e;
        int i2 = (i1 == 0) ? 1 : 0;
        #pragma unroll
        for (int e = 0; e < EE; e++) if (e != i1 && p[e] > p[i2]) i2 = e;
        int s1 = atomicAdd(&g_ecount[i1], 1);
        g_etok[i1 * NTOK + s1] = row * 2 + 0; g_ewt[i1 * NTOK + s1] = p[i1];
        int s2 = atomicAdd(&g_ecount[i2], 1);
        g_etok[i2 * NTOK + s2] = row * 2 + 1; g_ewt[i2 * NTOK + s2] = p[i2];
    }
}

// ---------------- fp16 single-pass mma.sync GEMM (4-stage, 2 CTA/SM) ------
// MODE 1: QKV: cols<DD -> g_qh fp16 (scaled 1/8); cols>=DD -> g_kvf fp32
// MODE 2: C = acc + bias + resid
// MODE 3: MoE gathered rows; atomicAdd(C[tok*ldc+col], w*(acc+bias))
template<int MODE>
__global__ void __launch_bounds__(256)
tc_gemm(const __half* __restrict__ A, const __half* __restrict__ B,
        const float* __restrict__ bias, const float* __restrict__ resid,
        float* __restrict__ C, int ldc) {
    __shared__ int   stok[128];
    __shared__ float swt[128];
    extern __shared__ __half smb[];

    int row0 = blockIdx.y * 128;
    int col0 = blockIdx.x * 128;
    int tid = threadIdx.x, wid = tid >> 5, lane = tid & 31;
    int quad = lane >> 2, tq = lane & 3;
    int wm = wid & 1, wn = wid >> 1;

    if (MODE == 3) {
        int e = blockIdx.z;
        int cnt = g_ecount[e];
        if (row0 >= cnt) return;
        B    += (size_t)e * DD * HID;
        bias += (size_t)e * HID;
        if (tid < 128) {
            int r = row0 + tid;
            if (r < cnt) { stok[tid] = g_etok[e * NTOK + r]; swt[tid] = g_ewt[e * NTOK + r]; }
            else         { stok[tid] = -1; swt[tid] = 0.f; }
        }
        __syncthreads();
    }

    int crow = tid >> 2;
    int seg  = tid & 3;
    const __half *sa[2], *sb[2];
    uint32_t doff[2];
    #pragma unroll
    for (int i = 0; i < 2; i++) {
        int r = crow + 64 * i;
        int tok;
        if (MODE == 3) { int t2 = stok[r]; tok = (t2 < 0) ? 0 : (t2 >> 1); }
        else           tok = row0 + r;
        sa[i] = A + (size_t)tok * DD + seg * 8;
        sb[i] = B + (size_t)(col0 + r) * DD + seg * 8;
        doff[i] = (uint32_t)(r * (BSTR * 2) + seg * 16);
    }
    uint32_t sbase = su32(smb);

    int lrow = lane & 15, lhalf = lane >> 4;
    uint32_t aLane = (uint32_t)(((wm * 64 + lrow) * BSTR + lhalf * 8) * 2);
    uint32_t bLane = (uint32_t)(((wn * 32 + lrow) * BSTR + lhalf * 8) * 2);

    float acc[4][4][4];
    #pragma unroll
    for (int mt = 0; mt < 4; mt++)
        #pragma unroll
        for (int nt = 0; nt < 4; nt++)
            #pragma unroll
            for (int i = 0; i < 4; i++) acc[mt][nt][i] = 0.f;

    // prologue: chunks 0,1,2 into stages 0,1,2
    #pragma unroll
    for (int pc = 0; pc < 3; pc++) {
        uint32_t base = sbase + pc * BUFB;
        int k0 = pc * TCK;
        #pragma unroll
        for (int i = 0; i < 2; i++) {
            CP16(base + 0 * TILEB + doff[i], sa[i] + k0);
            CP16(base + 1 * TILEB + doff[i], sb[i] + k0);
        }
        CP_COMMIT();
    }

    for (int c = 0; c < NCH; c++) {
        if (c == NCH - 1) CP_WAIT0();
        else if (c == NCH - 2) CP_WAIT1();
        else CP_WAIT2();
        __syncthreads();
        if (c + 3 < NCH) {
            uint32_t base = sbase + ((c + 3) & 3) * BUFB;
            int k0 = (c + 3) * TCK;
            #pragma unroll
            for (int i = 0; i < 2; i++) {
                CP16(base + 0 * TILEB + doff[i], sa[i] + k0);
                CP16(base + 1 * TILEB + doff[i], sb[i] + k0);
            }
            CP_COMMIT();
        }

        uint32_t sbuf = sbase + (c & 3) * BUFB;
        #pragma unroll
        for (int kk = 0; kk < 2; kk++) {
            uint32_t kof = kk * 16 * 2;
            uint32_t bh[4][2];
            uint32_t bb0 = sbuf + 1 * TILEB + bLane + kof;
            LDSM4(bh[0][0], bh[1][0], bh[0][1], bh[1][1], bb0);
            LDSM4(bh[2][0], bh[3][0], bh[2][1], bh[3][1], bb0 + 16 * BSTR * 2);
            #pragma unroll
            for (int mt = 0; mt < 4; mt++) {
                uint32_t ah[4];
                uint32_t aa = sbuf + aLane + kof + mt * 16 * BSTR * 2;
                LDSM4(ah[0], ah[1], ah[2], ah[3], aa);
                #pragma unroll
                for (int nt = 0; nt < 4; nt++)
                    mma_f16(acc[mt][nt], ah, bh[nt]);
            }
        }
    }

    #pragma unroll
    for (int mt = 0; mt < 4; mt++) {
        #pragma unroll
        for (int half = 0; half < 2; half++) {
            int lr = wm * 64 + mt * 16 + quad + half * 8;
            int r = row0 + lr;
            #pragma unroll
            for (int nt = 0; nt < 4; nt++) {
                int col = col0 + wn * 32 + nt * 8 + tq * 2;
                float v0 = acc[mt][nt][half * 2 + 0] + bias[col];
                float v1 = acc[mt][nt][half * 2 + 1] + bias[col + 1];
                if (MODE == 1) {
                    if (col < DD) {
                        *(uint32_t*)&g_qh[(size_t)r * DD + col] =
                            packh(__float2half_rn(v0 * 0.125f), __float2half_rn(v1 * 0.125f));
                    } else {
                        *(float2*)&g_kvf[(size_t)r * KVC + col - DD] = make_float2(v0, v1);
                    }
                } else if (MODE == 2) {
                    size_t o = (size_t)r * ldc + col;
                    float2 rr = *(const float2*)&resid[o];
                    *(float2*)&C[o] = make_float2(v0 + rr.x, v1 + rr.y);
                } else {
                    int t2 = stok[lr];
                    if (t2 >= 0) {
                        int tok = t2 >> 1;
                        float w = swt[lr];
                        atomicAdd(&C[(size_t)tok * ldc + col],     w * v0);
                        atomicAdd(&C[(size_t)tok * ldc + col + 1], w * v1);
                    }
                }
            }
        }
    }
}

// ---------------- K/V pre-convert (once per window/group/batch) -----------
__global__ void __launch_bounds__(256)
kvsplit_kernel() {
    int n = blockIdx.x, g = blockIdx.y, b = blockIdx.z;
    int key = threadIdx.x;
    int base = b * LL + n * 128;
    const float* kp = g_kvf + (size_t)(base + key) * KVC + g * 64;
    size_t tileid = ((size_t)b * NWIN + n) * GG + g;
    __half* kh = g_ksp + (tileid * 256 + key) * 64;
    size_t vb = tileid * 64 * 256 + key;
    #pragma unroll
    for (int d = 0; d < 64; d += 4) {
        float4 kk = *(const float4*)(kp + d);
        uint32_t p0 = packh(__float2half_rn(kk.x), __float2half_rn(kk.y));
        uint32_t p1 = packh(__float2half_rn(kk.z), __float2half_rn(kk.w));
        *(uint2*)&kh[d] = make_uint2(p0, p1);
        float4 vv = *(const float4*)(kp + KVD + d);
        float va[4] = {vv.x, vv.y, vv.z, vv.w};
        #pragma unroll
        for (int e = 0; e < 4; e++)
            g_vsp[vb + (size_t)(d + e) * 256] = __float2half_rn(va[e]);
    }
}

// ---------------- tensor-core attention (fp16, double-buffered K/V) --------
__global__ void __launch_bounds__(256)
attn_kernel(__half* __restrict__ oatt) {
    extern __shared__ __half sma[];
    __half* Qh = sma;                  // 256 x APAD
    // 2 K/V stages follow: stage s at Qh + 256*APAD + s*128*APAD (K 64 rows, V 64 rows)

    int n = blockIdx.x, h = blockIdx.y, b = blockIdx.z;
    int g = h & (GG - 1);
    int base = b * LL + n * 128;
    int tid = threadIdx.x, wid = tid >> 5, lane = tid & 31;
    int quad = lane >> 2, tq = lane & 3;
    int lrow = lane & 15, lhalf = lane >> 4;
    size_t tileid = ((size_t)b * NWIN + n) * GG + g;

    uint32_t qBase = su32(Qh);
    uint32_t kvStage[2];
    kvStage[0] = qBase + (uint32_t)(256 * APAD) * 2;
    kvStage[1] = kvStage[0] + (uint32_t)(128 * APAD) * 2;
    uint32_t vOff = (uint32_t)(64 * APAD) * 2;

    int trow = tid >> 2, tseg = tid & 3;
    const __half* ksrc = g_ksp + (tileid * 256 + trow) * 64;
    const __half* vsrc = g_vsp + (tileid * 64 + trow) * 256;
    uint32_t kdst = (uint32_t)(trow * APAD) * 2;

    // Q cp.async (group 0)
    {
        const __half* qsrc = g_qh + (size_t)(base + tid) * DD + h * 64;
        uint32_t qdst = qBase + (uint32_t)(tid * APAD) * 2;
        #pragma unroll
        for (int s2 = 0; s2 < 8; s2++)
            CP16(qdst + s2 * 16, qsrc + s2 * 8);
        CP_COMMIT();
    }
    // prologue tiles 0, 1 (groups 1, 2)
    #pragma unroll
    for (int pt = 0; pt < 2; pt++) {
        uint32_t kb = kvStage[pt];
        #pragma unroll
        for (int s2 = 0; s2 < 2; s2++) {
            int sg = tseg + s2 * 4;
            CP16(kb + kdst + sg * 16,        ksrc + (size_t)pt * 64 * 64 + sg * 8);
            CP16(kb + vOff + kdst + sg * 16, vsrc + pt * 64 + sg * 8);
        }
        CP_COMMIT();
    }

    float o[2][8][4];
    #pragma unroll
    for (int mt = 0; mt < 2; mt++)
        #pragma unroll
        for (int nt = 0; nt < 8; nt++)
            #pragma unroll
            for (int i = 0; i < 4; i++) o[mt][nt][i] = 0.f;
    float denomAcc[2][2] = {{0.f, 0.f}, {0.f, 0.f}};

    for (int kt = 0; kt < 4; kt++) {
        if (kt == 3) CP_WAIT0(); else CP_WAIT1();
        __syncthreads();

        uint32_t kBase = kvStage[kt & 1];
        uint32_t vBase = kBase + vOff;

        // ---- S = Q @ K^T ----
        float s[2][8][4];
        #pragma unroll
        for (int mt = 0; mt < 2; mt++)
            #pragma unroll
            for (int nt = 0; nt < 8; nt++)
                #pragma unroll
                for (int i = 0; i < 4; i++) s[mt][nt][i] = 0.f;

        #pragma unroll
        for (int ks = 0; ks < 4; ks++) {
            uint32_t kof = (uint32_t)(ks * 16 + lhalf * 8) * 2;
            uint32_t ah[2][4];
            #pragma unroll
            for (int mt = 0; mt < 2; mt++) {
                uint32_t aa = qBase + (uint32_t)((wid * 32 + mt * 16 + lrow) * APAD) * 2 + kof;
                LDSM4(ah[mt][0], ah[mt][1], ah[mt][2], ah[mt][3], aa);
            }
            uint32_t bh[8][2];
            #pragma unroll
            for (int p = 0; p < 4; p++) {
                uint32_t bb = kBase + (uint32_t)((p * 16 + lrow) * APAD) * 2 + kof;
                LDSM4(bh[2*p][0], bh[2*p+1][0], bh[2*p][1], bh[2*p+1][1], bb);
            }
            #pragma unroll
            for (int mt = 0; mt < 2; mt++)
                #pragma unroll
                for (int nt = 0; nt < 8; nt++)
                    mma_f16(s[mt][nt], ah[mt], bh[nt]);
        }

        // ---- exp, denominators, pack P (fp16) ----
        uint32_t ph[2][8][2];
        #pragma unroll
        for (int mt = 0; mt < 2; mt++) {
            float d0 = 0.f, d1 = 0.f;
            #pragma unroll
            for (int nt = 0; nt < 8; nt++) {
                float p0 = __expf(fminf(s[mt][nt][0], 75.f));
                float p1 = __expf(fminf(s[mt][nt][1], 75.f));
                float p2 = __expf(fminf(s[mt][nt][2], 75.f));
                float p3 = __expf(fminf(s[mt][nt][3], 75.f));
                d0 += p0 + p1;
                d1 += p2 + p3;
                ph[mt][nt][0] = packh(__float2half_rn(p0), __float2half_rn(p1));
                ph[mt][nt][1] = packh(__float2half_rn(p2), __float2half_rn(p3));
            }
            d0 += __shfl_xor_sync(0xffffffffu, d0, 1);
            d0 += __shfl_xor_sync(0xffffffffu, d0, 2);
            d1 += __shfl_xor_sync(0xffffffffu, d1, 1);
            d1 += __shfl_xor_sync(0xffffffffu, d1, 2);
            denomAcc[mt][0] += d0;
            denomAcc[mt][1] += d1;
        }

        // ---- O += P @ V^T ----
        #pragma unroll
        for (int ks = 0; ks < 4; ks++) {
            uint32_t kof = (uint32_t)(ks * 16 + lhalf * 8) * 2;
            uint32_t bvh[8][2];
            #pragma unroll
            for (int p = 0; p < 4; p++) {
                uint32_t bb = vBase + (uint32_t)((p * 16 + lrow) * APAD) * 2 + kof;
                LDSM4(bvh[2*p][0], bvh[2*p+1][0], bvh[2*p][1], bvh[2*p+1][1], bb);
            }
            #pragma unroll
            for (int mt = 0; mt < 2; mt++) {
                uint32_t ah4[4] = { ph[mt][2*ks][0], ph[mt][2*ks][1],
                                    ph[mt][2*ks+1][0], ph[mt][2*ks+1][1] };
                #pragma unroll
                for (int nt = 0; nt < 8; nt++)
                    mma_f16(o[mt][nt], ah4, bvh[nt]);
            }
        }

        // prefetch tile kt+2 into the stage just consumed
        if (kt + 2 < 4) {
            __syncthreads();   // all warps done reading stage (kt&1)
            int pt = kt + 2;
            uint32_t kb = kvStage[kt & 1];
            #pragma unroll
            for (int s2 = 0; s2 < 2; s2++) {
                int sg = tseg + s2 * 4;
                CP16(kb + kdst + sg * 16,        ksrc + (size_t)pt * 64 * 64 + sg * 8);
                CP16(kb + vOff + kdst + sg * 16, vsrc + pt * 64 + sg * 8);
            }
            CP_COMMIT();
        }
    }

    // ---- epilogue ----
    #pragma unroll
    for (int mt = 0; mt < 2; mt++) {
        #pragma unroll
        for (int half = 0; half < 2; half++) {
            float inv = 1.f / denomAcc[mt][half];
            int tokout = b * LL + n * 256 + wid * 32 + mt * 16 + quad + half * 8;
            size_t rowb = (size_t)tokout * DD + h * 64;
            #pragma unroll
            for (int nt = 0; nt < 8; nt++) {
                float v0 = o[mt][nt][half * 2 + 0] * inv;
                float v1 = o[mt][nt][half * 2 + 1] * inv;
                int col = nt * 8 + tq * 2;
                *(uint32_t*)&oatt[rowb + col] = packh(__float2half_rn(v0), __float2half_rn(v1));
            }
        }
    }
}

// ---------------- aux scalar ----------------
__global__ void aux_kernel(float* __restrict__ out, long long out_size) {
    if (threadIdx.x == 0 && blockIdx.x == 0) {
        float pen = 0.f;
        #pragma unroll
        for (int e = 0; e < EE; e++) {
            float usage = (float)g_ecount[e] / ((float)NTOK + 1e-8f);
            pen += fmaxf(usage - 0.4f, 0.f);
        }
        float ent = g_entsum / (float)NTOK;
        float aux = 0.05f * ent + pen;
        long long total = (long long)NTOK * HID;
        if (out_size > total) out[total] = aux;
    }
}

// ---------------- launch ----------------
extern "C" void kernel_launch(void* const* d_in, const int* in_sizes, int n_in,
                              void* d_out, int out_size) {
    const float* x     = (const float*)d_in[0];
    const float* Wq    = (const float*)d_in[1];
    const float* bq    = (const float*)d_in[2];
    const float* Wk    = (const float*)d_in[3];
    const float* bk    = (const float*)d_in[4];
    const float* Wv    = (const float*)d_in[5];
    const float* bv    = (const float*)d_in[6];
    const float* Wo    = (const float*)d_in[7];
    const float* bo    = (const float*)d_in[8];
    const float* ln1_g = (const float*)d_in[9];
    const float* ln1_b = (const float*)d_in[10];
    const float* ln2_g = (const float*)d_in[11];
    const float* ln2_b = (const float*)d_in[12];
    const float* Wg    = (const float*)d_in[13];
    const float* bg    = (const float*)d_in[14];
    const float* We    = (const float*)d_in[15];
    const float* be    = (const float*)d_in[16];
    float* out = (float*)d_out;

    __half *ln1, *att, *ln2, *wqkv, *wot, *wet;
    float *bqkv;
    cudaGetSymbolAddress((void**)&ln1,  g_ln1);
    cudaGetSymbolAddress((void**)&att,  g_att);
    cudaGetSymbolAddress((void**)&ln2,  g_ln2);
    cudaGetSymbolAddress((void**)&wqkv, g_wqkv);
    cudaGetSymbolAddress((void**)&wot,  g_wot);
    cudaGetSymbolAddress((void**)&wet,  g_wet);
    cudaGetSymbolAddress((void**)&bqkv, g_bqkv);

    const int ASM = (256 + 2 * 128) * APAD * 2;   // 73728
    cudaFuncSetAttribute(attn_kernel, cudaFuncAttributeMaxDynamicSharedMemorySize, ASM);
    cudaFuncSetAttribute(tc_gemm<1>, cudaFuncAttributeMaxDynamicSharedMemorySize, GSMEM);
    cudaFuncSetAttribute(tc_gemm<2>, cudaFuncAttributeMaxDynamicSharedMemorySize, GSMEM);
    cudaFuncSetAttribute(tc_gemm<3>, cudaFuncAttributeMaxDynamicSharedMemorySize, GSMEM);

    zero_kernel<<<1, 32>>>();

    transpose_all<<<10496, dim3(32, 8)>>>(Wq, Wk, Wv, Wo, We);
    bqkv_kernel<<<(QKVC + 255) / 256, 256>>>(bq, bk, bv);

    ln_kernel<<<NTOK, 256>>>(x, ln1_g, ln1_b, ln1);

    // QKV GEMM: writes g_qh (fp16, scaled) + g_kvf (fp32 compact)
    tc_gemm<1><<<dim3(10, 64), 256, GSMEM>>>(ln1, wqkv, bqkv, nullptr, nullptr, 0);

    kvsplit_kernel<<<dim3(NWIN, GG, BB), 256>>>();
    attn_kernel<<<dim3(NWIN, HH, BB), 256, ASM>>>(att);

    // out = x + attn@Wo + bo
    tc_gemm<2><<<dim3(8, 64), 256, GSMEM>>>(att, wot, bo, x, out, DD);

    ln2_gate_kernel<<<NTOK, 256>>>(out, ln2_g, ln2_b, Wg, bg, ln2);

    // MoE: atomicAdd directly into out
    tc_gemm<3><<<dim3(8, 64, EE), 256, GSMEM>>>(ln2, wet, be, nullptr, out, HID);

    aux_kernel<<<1, 32>>>(out, (long long)out_size);
}

// round 14
// speedup vs baseline: 2.1218x; 1.0206x over previous
#include <cuda_runtime.h>
#include <cuda_fp16.h>
#include <math.h>
#include <stdint.h>

// Problem constants
#define BB 2
#define LL 4096
#define DD 1024
#define HH 16
#define GG 2
#define HD 64
#define KVD 128
#define KVC 256
#define QKVC 1280        // Q(1024) | K(128) | V(128)
#define EE 8
#define HID 1024
#define NTOK (BB*LL)     // 8192
#define NWIN 16
#define WIN 256
#define TCK 32           // K-chunk (32 fp16 columns per stage)
#define NCH (DD/TCK)     // 32 chunks
#define BSTR 40          // padded smem row stride (80B, ldmatrix conflict-free)
#define TILE (128*BSTR)
#define TILEB (TILE*2)   // 10240 bytes
#define BUFB (2*TILEB)   // one stage = A|B = 20480 bytes
#define NSTAGE 4
#define GSMEM (NSTAGE*BUFB)  // 81920 -> 2 CTAs/SM
#define APAD 72          // attention smem row stride

// ---------------- scratch (static device globals) ----------------
__device__ __align__(16) __half g_ln1 [NTOK*DD];
__device__ __align__(16) __half g_qh  [NTOK*DD];      // Q, pre-scaled 1/8, fp16
__device__ __align__(16) __half g_kh  [NTOK*KVD];     // K fp16 [token][128]
__device__ __align__(16) __half g_vt  [BB*GG*64*LL];  // V fp16 transposed [(b,g,dim)][pos]
__device__ __align__(16) __half g_att [NTOK*DD];
__device__ __align__(16) __half g_ln2 [NTOK*DD];
__device__ __align__(16) __half g_wqkv[QKVC*DD];
__device__ __align__(16) __half g_wot [DD*DD];
__device__ __align__(16) __half g_wet [EE*DD*HID];
__device__ float g_bqkv[QKVC];
__device__ int   g_ecount[EE];
__device__ float g_entsum;
__device__ int   g_etok[EE*NTOK];   // tok*2 + slot
__device__ float g_ewt [EE*NTOK];

// ---------------- helpers ----------------
__device__ __forceinline__ uint32_t su32(const void* p) {
    uint32_t r;
    asm("{ .reg .u64 t; cvta.to.shared.u64 t, %1; cvt.u32.u64 %0, t; }" : "=r"(r) : "l"(p));
    return r;
}
#define CP16(dst, src) asm volatile("cp.async.cg.shared.global [%0], [%1], 16;" :: "r"(dst), "l"(src))
#define CP_COMMIT()    asm volatile("cp.async.commit_group;" ::: "memory")
#define CP_WAIT0()     asm volatile("cp.async.wait_group 0;" ::: "memory")
#define CP_WAIT1()     asm volatile("cp.async.wait_group 1;" ::: "memory")
#define CP_WAIT2()     asm volatile("cp.async.wait_group 2;" ::: "memory")

#define LDSM4(r0, r1, r2, r3, addr) \
    asm volatile("ldmatrix.sync.aligned.m8n8.x4.shared.b16 {%0,%1,%2,%3}, [%4];" \
                 : "=r"(r0), "=r"(r1), "=r"(r2), "=r"(r3) : "r"(addr))

__device__ __forceinline__ void mma_f16(float* c, const uint32_t* a, const uint32_t* b) {
    asm volatile(
        "mma.sync.aligned.m16n8k16.row.col.f32.f16.f16.f32 "
        "{%0,%1,%2,%3}, {%4,%5,%6,%7}, {%8,%9}, {%0,%1,%2,%3};"
        : "+f"(c[0]), "+f"(c[1]), "+f"(c[2]), "+f"(c[3])
        : "r"(a[0]), "r"(a[1]), "r"(a[2]), "r"(a[3]), "r"(b[0]), "r"(b[1]));
}
__device__ __forceinline__ uint32_t packh(__half lo, __half hi) {
    return (uint32_t)__half_as_ushort(lo) | ((uint32_t)__half_as_ushort(hi) << 16);
}

// ---------------- fused weight transpose + fp16 convert + init ------------
// blocks: [0,1024) Wq | [1024,1152) Wk | [1152,1280) Wv | [1280,2304) Wo |
//         [2304,10496) We | [10496,10501) bias copy + bookkeeping zero
__global__ void __launch_bounds__(256)
transpose_all(const float* __restrict__ Wq, const float* __restrict__ Wk,
              const float* __restrict__ Wv, const float* __restrict__ Wo,
              const float* __restrict__ We,
              const float* __restrict__ bq, const float* __restrict__ bk,
              const float* __restrict__ bv) {
    __shared__ float t[32][33];
    int bid = blockIdx.x;
    if (bid >= 10496) {
        int tt = threadIdx.y * 32 + threadIdx.x + (bid - 10496) * 256;
        if (tt < DD) g_bqkv[tt] = bq[tt];
        else if (tt < DD + KVD) g_bqkv[tt] = bk[tt - DD];
        else if (tt < QKVC) g_bqkv[tt] = bv[tt - DD - KVD];
        if (bid == 10496) {
            if (tt < EE) g_ecount[tt] = 0;
            if (tt == EE) g_entsum = 0.f;
        }
        return;
    }
    const float* src;
    __half* dh;
    int cols, rowOff, bx, by;
    size_t dstOff = 0;
    if (bid < 1024) {
        src = Wq; dh = g_wqkv; cols = DD; rowOff = 0;
        bx = bid & 31; by = bid >> 5;
    } else if (bid < 1152) {
        int r = bid - 1024;
        src = Wk; dh = g_wqkv; cols = KVD; rowOff = DD;
        bx = r & 3; by = r >> 2;
    } else if (bid < 1280) {
        int r = bid - 1152;
        src = Wv; dh = g_wqkv; cols = KVD; rowOff = DD + KVD;
        bx = r & 3; by = r >> 2;
    } else if (bid < 2304) {
        int r = bid - 1280;
        src = Wo; dh = g_wot; cols = DD; rowOff = 0;
        bx = r & 31; by = r >> 5;
    } else {
        int r = bid - 2304;
        int e = r >> 10; r &= 1023;
        src = We + (size_t)e * DD * HID;
        dh = g_wet; dstOff = (size_t)e * DD * HID;
        cols = HID; rowOff = 0;
        bx = r & 31; by = r >> 5;
    }
    int c0 = bx * 32, r0 = by * 32;
    int tx = threadIdx.x, ty = threadIdx.y;
    #pragma unroll
    for (int i = 0; i < 32; i += 8)
        t[ty + i][tx] = src[(size_t)(r0 + ty + i) * cols + c0 + tx];
    __syncthreads();
    #pragma unroll
    for (int i = 0; i < 32; i += 8) {
        size_t o = dstOff + (size_t)(c0 + ty + i + rowOff) * DD + r0 + tx;
        dh[o] = __float2half_rn(t[tx][ty + i]);
    }
}

// ---------------- LayerNorm (fp16 output) ----------
__global__ void ln_kernel(const float* __restrict__ x, const float* __restrict__ g,
                          const float* __restrict__ b, __half* __restrict__ y) {
    int row = blockIdx.x;
    const float4* xr = (const float4*)(x + (size_t)row * DD);
    int tid = threadIdx.x;
    float4 v = xr[tid];
    float s  = v.x + v.y + v.z + v.w;
    float ss = v.x*v.x + v.y*v.y + v.z*v.z + v.w*v.w;
    #pragma unroll
    for (int o = 16; o > 0; o >>= 1) {
        s  += __shfl_down_sync(0xffffffffu, s,  o);
        ss += __shfl_down_sync(0xffffffffu, ss, o);
    }
    __shared__ float sh_s[8], sh_ss[8];
    __shared__ float s_mean, s_rstd;
    int warp = tid >> 5, lane = tid & 31;
    if (lane == 0) { sh_s[warp] = s; sh_ss[warp] = ss; }
    __syncthreads();
    if (tid == 0) {
        float S = 0.f, SS = 0.f;
        #pragma unroll
        for (int i = 0; i < 8; i++) { S += sh_s[i]; SS += sh_ss[i]; }
        float mean = S / (float)DD;
        float var  = SS / (float)DD - mean * mean;
        s_mean = mean;
        s_rstd = rsqrtf(var + 1e-5f);
    }
    __syncthreads();
    float mean = s_mean, rstd = s_rstd;
    float4 gg = ((const float4*)g)[tid];
    float4 bb = ((const float4*)b)[tid];
    float o[4];
    o[0] = (v.x - mean) * rstd * gg.x + bb.x;
    o[1] = (v.y - mean) * rstd * gg.y + bb.y;
    o[2] = (v.z - mean) * rstd * gg.z + bb.z;
    o[3] = (v.w - mean) * rstd * gg.w + bb.w;
    size_t base = (size_t)row * DD + tid * 4;
    uint32_t p0 = packh(__float2half_rn(o[0]), __float2half_rn(o[1]));
    uint32_t p1 = packh(__float2half_rn(o[2]), __float2half_rn(o[3]));
    *(uint2*)&y[base] = make_uint2(p0, p1);
}

// ---------------- LN2 + MoE gate fused ----------------
__global__ void ln2_gate_kernel(const float* __restrict__ x, const float* __restrict__ g,
                                const float* __restrict__ b,
                                const float* __restrict__ Wg, const float* __restrict__ bg,
                                __half* __restrict__ y) {
    int row = blockIdx.x;
    const float4* xr = (const float4*)(x + (size_t)row * DD);
    int tid = threadIdx.x;
    float4 v = xr[tid];
    float s  = v.x + v.y + v.z + v.w;
    float ss = v.x*v.x + v.y*v.y + v.z*v.z + v.w*v.w;
    #pragma unroll
    for (int o = 16; o > 0; o >>= 1) {
        s  += __shfl_down_sync(0xffffffffu, s,  o);
        ss += __shfl_down_sync(0xffffffffu, ss, o);
    }
    __shared__ float sh_s[8], sh_ss[8];
    __shared__ float s_mean, s_rstd;
    __shared__ float red[8][8];
    int warp = tid >> 5, lane = tid & 31;
    if (lane == 0) { sh_s[warp] = s; sh_ss[warp] = ss; }
    __syncthreads();
    if (tid == 0) {
        float S = 0.f, SS = 0.f;
        #pragma unroll
        for (int i = 0; i < 8; i++) { S += sh_s[i]; SS += sh_ss[i]; }
        float mean = S / (float)DD;
        float var  = SS / (float)DD - mean * mean;
        s_mean = mean;
        s_rstd = rsqrtf(var + 1e-5f);
    }
    __syncthreads();
    float mean = s_mean, rstd = s_rstd;
    float4 gg = ((const float4*)g)[tid];
    float4 bb = ((const float4*)b)[tid];
    float o[4];
    o[0] = (v.x - mean) * rstd * gg.x + bb.x;
    o[1] = (v.y - mean) * rstd * gg.y + bb.y;
    o[2] = (v.z - mean) * rstd * gg.z + bb.z;
    o[3] = (v.w - mean) * rstd * gg.w + bb.w;
    size_t base = (size_t)row * DD + tid * 4;
    uint32_t p0 = packh(__float2half_rn(o[0]), __float2half_rn(o[1]));
    uint32_t p1 = packh(__float2half_rn(o[2]), __float2half_rn(o[3]));
    *(uint2*)&y[base] = make_uint2(p0, p1);

    // ---- gating from in-register LN output ----
    float pr[EE];
    #pragma unroll
    for (int e = 0; e < EE; e++) pr[e] = 0.f;
    #pragma unroll
    for (int i = 0; i < 4; i++) {
        float4 w0 = ((const float4*)Wg)[(tid * 4 + i) * 2];
        float4 w1 = ((const float4*)Wg)[(tid * 4 + i) * 2 + 1];
        pr[0] += o[i] * w0.x; pr[1] += o[i] * w0.y;
        pr[2] += o[i] * w0.z; pr[3] += o[i] * w0.w;
        pr[4] += o[i] * w1.x; pr[5] += o[i] * w1.y;
        pr[6] += o[i] * w1.z; pr[7] += o[i] * w1.w;
    }
    #pragma unroll
    for (int off = 16; off > 0; off >>= 1)
        #pragma unroll
        for (int e = 0; e < EE; e++)
            pr[e] += __shfl_down_sync(0xffffffffu, pr[e], off);
    if (lane == 0)
        #pragma unroll
        for (int e = 0; e < EE; e++) red[warp][e] = pr[e];
    __syncthreads();
    if (tid == 0) {
        float l[EE], m = -3.4e38f;
        #pragma unroll
        for (int e = 0; e < EE; e++) {
            float sum = bg[e];
            #pragma unroll
            for (int w = 0; w < 8; w++) sum += red[w][e];
            l[e] = sum;
            m = fmaxf(m, sum);
        }
        float p[EE], sm = 0.f;
        #pragma unroll
        for (int e = 0; e < EE; e++) { p[e] = __expf(l[e] - m); sm += p[e]; }
        float invs = 1.f / sm, ent = 0.f;
        #pragma unroll
        for (int e = 0; e < EE; e++) {
            p[e] *= invs;
            ent -= p[e] * logf(p[e] + 1e-8f);
        }
        atomicAdd(&g_entsum, ent);
        int i1 = 0;
        #pragma unroll
        for (int e = 1; e < EE; e++) if (p[e] > p[i1]) i1 = e;
        int i2 = (i1 == 0) ? 1 : 0;
        #pragma unroll
        for (int e = 0; e < EE; e++) if (e != i1 && p[e] > p[i2]) i2 = e;
        int s1 = atomicAdd(&g_ecount[i1], 1);
        g_etok[i1 * NTOK + s1] = row * 2 + 0; g_ewt[i1 * NTOK + s1] = p[i1];
        int s2 = atomicAdd(&g_ecount[i2], 1);
        g_etok[i2 * NTOK + s2] = row * 2 + 1; g_ewt[i2 * NTOK + s2] = p[i2];
    }
}

// ---------------- fp16 single-pass mma.sync GEMM (4-stage, 2 CTA/SM) ------
// MODE 1: QKV: cols<DD -> g_qh fp16 (scaled); K cols -> g_kh; V cols -> g_vt (transposed)
// MODE 2: C = acc + bias + resid
// MODE 3: MoE gathered rows; atomicAdd(C[tok*ldc+col], w*(acc+bias))
template<int MODE>
__global__ void __launch_bounds__(256)
tc_gemm(const __half* __restrict__ A, const __half* __restrict__ B,
        const float* __restrict__ bias, const float* __restrict__ resid,
        float* __restrict__ C, int ldc) {
    __shared__ int   stok[128];
    __shared__ float swt[128];
    extern __shared__ __half smb[];

    int row0 = blockIdx.y * 128;
    int col0 = blockIdx.x * 128;
    int tid = threadIdx.x, wid = tid >> 5, lane = tid & 31;
    int quad = lane >> 2, tq = lane & 3;
    int wm = wid & 1, wn = wid >> 1;

    if (MODE == 3) {
        int e = blockIdx.z;
        int cnt = g_ecount[e];
        if (row0 >= cnt) return;
        B    += (size_t)e * DD * HID;
        bias += (size_t)e * HID;
        if (tid < 128) {
            int r = row0 + tid;
            if (r < cnt) { stok[tid] = g_etok[e * NTOK + r]; swt[tid] = g_ewt[e * NTOK + r]; }
            else         { stok[tid] = -1; swt[tid] = 0.f; }
        }
        __syncthreads();
    }

    int crow = tid >> 2;
    int seg  = tid & 3;
    const __half *sa[2], *sb[2];
    uint32_t doff[2];
    #pragma unroll
    for (int i = 0; i < 2; i++) {
        int r = crow + 64 * i;
        int tok;
        if (MODE == 3) { int t2 = stok[r]; tok = (t2 < 0) ? 0 : (t2 >> 1); }
        else           tok = row0 + r;
        sa[i] = A + (size_t)tok * DD + seg * 8;
        sb[i] = B + (size_t)(col0 + r) * DD + seg * 8;
        doff[i] = (uint32_t)(r * (BSTR * 2) + seg * 16);
    }
    uint32_t sbase = su32(smb);

    int lrow = lane & 15, lhalf = lane >> 4;
    uint32_t aLane = (uint32_t)(((wm * 64 + lrow) * BSTR + lhalf * 8) * 2);
    uint32_t bLane = (uint32_t)(((wn * 32 + lrow) * BSTR + lhalf * 8) * 2);

    float acc[4][4][4];
    #pragma unroll
    for (int mt = 0; mt < 4; mt++)
        #pragma unroll
        for (int nt = 0; nt < 4; nt++)
            #pragma unroll
            for (int i = 0; i < 4; i++) acc[mt][nt][i] = 0.f;

    // prologue: chunks 0,1,2 into stages 0,1,2
    #pragma unroll
    for (int pc = 0; pc < 3; pc++) {
        uint32_t base = sbase + pc * BUFB;
        int k0 = pc * TCK;
        #pragma unroll
        for (int i = 0; i < 2; i++) {
            CP16(base + 0 * TILEB + doff[i], sa[i] + k0);
            CP16(base + 1 * TILEB + doff[i], sb[i] + k0);
        }
        CP_COMMIT();
    }

    for (int c = 0; c < NCH; c++) {
        if (c == NCH - 1) CP_WAIT0();
        else if (c == NCH - 2) CP_WAIT1();
        else CP_WAIT2();
        __syncthreads();
        if (c + 3 < NCH) {
            uint32_t base = sbase + ((c + 3) & 3) * BUFB;
            int k0 = (c + 3) * TCK;
            #pragma unroll
            for (int i = 0; i < 2; i++) {
                CP16(base + 0 * TILEB + doff[i], sa[i] + k0);
                CP16(base + 1 * TILEB + doff[i], sb[i] + k0);
            }
            CP_COMMIT();
        }

        uint32_t sbuf = sbase + (c & 3) * BUFB;
        #pragma unroll
        for (int kk = 0; kk < 2; kk++) {
            uint32_t kof = kk * 16 * 2;
            uint32_t bh[4][2];
            uint32_t bb0 = sbuf + 1 * TILEB + bLane + kof;
            LDSM4(bh[0][0], bh[1][0], bh[0][1], bh[1][1], bb0);
            LDSM4(bh[2][0], bh[3][0], bh[2][1], bh[3][1], bb0 + 16 * BSTR * 2);
            #pragma unroll
            for (int mt = 0; mt < 4; mt++) {
                uint32_t ah[4];
                uint32_t aa = sbuf + aLane + kof + mt * 16 * BSTR * 2;
                LDSM4(ah[0], ah[1], ah[2], ah[3], aa);
                #pragma unroll
                for (int nt = 0; nt < 4; nt++)
                    mma_f16(acc[mt][nt], ah, bh[nt]);
            }
        }
    }

    #pragma unroll
    for (int mt = 0; mt < 4; mt++) {
        #pragma unroll
        for (int half = 0; half < 2; half++) {
            int lr = wm * 64 + mt * 16 + quad + half * 8;
            int r = row0 + lr;
            #pragma unroll
            for (int nt = 0; nt < 4; nt++) {
                int col = col0 + wn * 32 + nt * 8 + tq * 2;
                float v0 = acc[mt][nt][half * 2 + 0] + bias[col];
                float v1 = acc[mt][nt][half * 2 + 1] + bias[col + 1];
                if (MODE == 1) {
                    if (col < DD) {
                        *(uint32_t*)&g_qh[(size_t)r * DD + col] =
                            packh(__float2half_rn(v0 * 0.125f), __float2half_rn(v1 * 0.125f));
                    } else if (col < DD + KVD) {
                        *(uint32_t*)&g_kh[(size_t)r * KVD + (col - DD)] =
                            packh(__float2half_rn(v0), __float2half_rn(v1));
                    } else {
                        int c2 = col - DD - KVD;       // 0..127
                        int gidx = c2 >> 6, d = c2 & 63;
                        int bb2 = r >> 12, pos = r & (LL - 1);
                        size_t vbase = ((size_t)(bb2 * GG + gidx) * 64 + d) * LL + pos;
                        g_vt[vbase]      = __float2half_rn(v0);
                        g_vt[vbase + LL] = __float2half_rn(v1);
                    }
                } else if (MODE == 2) {
                    size_t o = (size_t)r * ldc + col;
                    float2 rr = *(const float2*)&resid[o];
                    *(float2*)&C[o] = make_float2(v0 + rr.x, v1 + rr.y);
                } else {
                    int t2 = stok[lr];
                    if (t2 >= 0) {
                        int tok = t2 >> 1;
                        float w = swt[lr];
                        atomicAdd(&C[(size_t)tok * ldc + col],     w * v0);
                        atomicAdd(&C[(size_t)tok * ldc + col + 1], w * v1);
                    }
                }
            }
        }
    }
}

// ---------------- tensor-core attention (fp16, double-buffered K/V) --------
__global__ void __launch_bounds__(256)
attn_kernel(__half* __restrict__ oatt) {
    extern __shared__ __half sma[];
    __half* Qh = sma;                  // 256 x APAD

    int n = blockIdx.x, h = blockIdx.y, b = blockIdx.z;
    int g = h & (GG - 1);
    int base = b * LL + n * 128;
    int tid = threadIdx.x, wid = tid >> 5, lane = tid & 31;
    int quad = lane >> 2, tq = lane & 3;
    int lrow = lane & 15, lhalf = lane >> 4;

    uint32_t qBase = su32(Qh);
    uint32_t kvStage[2];
    kvStage[0] = qBase + (uint32_t)(256 * APAD) * 2;
    kvStage[1] = kvStage[0] + (uint32_t)(128 * APAD) * 2;
    uint32_t vOff = (uint32_t)(64 * APAD) * 2;

    int trow = tid >> 2, tseg = tid & 3;
    const __half* ksrc = g_kh + (size_t)(base + trow) * KVD + g * 64;       // + kt*64*KVD
    const __half* vsrc = g_vt + ((size_t)(b * GG + g) * 64 + trow) * LL + n * 128;  // + kt*64
    uint32_t kdst = (uint32_t)(trow * APAD) * 2;

    // Q cp.async (group 0)
    {
        const __half* qsrc = g_qh + (size_t)(base + tid) * DD + h * 64;
        uint32_t qdst = qBase + (uint32_t)(tid * APAD) * 2;
        #pragma unroll
        for (int s2 = 0; s2 < 8; s2++)
            CP16(qdst + s2 * 16, qsrc + s2 * 8);
        CP_COMMIT();
    }
    // prologue tiles 0, 1 (groups 1, 2)
    #pragma unroll
    for (int pt = 0; pt < 2; pt++) {
        uint32_t kb = kvStage[pt];
        #pragma unroll
        for (int s2 = 0; s2 < 2; s2++) {
            int sg = tseg + s2 * 4;
            CP16(kb + kdst + sg * 16,        ksrc + (size_t)pt * 64 * KVD + sg * 8);
            CP16(kb + vOff + kdst + sg * 16, vsrc + pt * 64 + sg * 8);
        }
        CP_COMMIT();
    }

    float o[2][8][4];
    #pragma unroll
    for (int mt = 0; mt < 2; mt++)
        #pragma unroll
        for (int nt = 0; nt < 8; nt++)
            #pragma unroll
            for (int i = 0; i < 4; i++) o[mt][nt][i] = 0.f;
    float denomAcc[2][2] = {{0.f, 0.f}, {0.f, 0.f}};

    for (int kt = 0; kt < 4; kt++) {
        if (kt == 3) CP_WAIT0(); else CP_WAIT1();
        __syncthreads();

        uint32_t kBase = kvStage[kt & 1];
        uint32_t vBase = kBase + vOff;

        // ---- S = Q @ K^T ----
        float s[2][8][4];
        #pragma unroll
        for (int mt = 0; mt < 2; mt++)
            #pragma unroll
            for (int nt = 0; nt < 8; nt++)
                #pragma unroll
                for (int i = 0; i < 4; i++) s[mt][nt][i] = 0.f;

        #pragma unroll
        for (int ks = 0; ks < 4; ks++) {
            uint32_t kof = (uint32_t)(ks * 16 + lhalf * 8) * 2;
            uint32_t ah[2][4];
            #pragma unroll
            for (int mt = 0; mt < 2; mt++) {
                uint32_t aa = qBase + (uint32_t)((wid * 32 + mt * 16 + lrow) * APAD) * 2 + kof;
                LDSM4(ah[mt][0], ah[mt][1], ah[mt][2], ah[mt][3], aa);
            }
            uint32_t bh[8][2];
            #pragma unroll
            for (int p = 0; p < 4; p++) {
                uint32_t bb = kBase + (uint32_t)((p * 16 + lrow) * APAD) * 2 + kof;
                LDSM4(bh[2*p][0], bh[2*p+1][0], bh[2*p][1], bh[2*p+1][1], bb);
            }
            #pragma unroll
            for (int mt = 0; mt < 2; mt++)
                #pragma unroll
                for (int nt = 0; nt < 8; nt++)
                    mma_f16(s[mt][nt], ah[mt], bh[nt]);
        }

        // ---- exp, denominators, pack P (fp16) ----
        uint32_t ph[2][8][2];
        #pragma unroll
        for (int mt = 0; mt < 2; mt++) {
            float d0 = 0.f, d1 = 0.f;
            #pragma unroll
            for (int nt = 0; nt < 8; nt++) {
                float p0 = __expf(fminf(s[mt][nt][0], 75.f));
                float p1 = __expf(fminf(s[mt][nt][1], 75.f));
                float p2 = __expf(fminf(s[mt][nt][2], 75.f));
                float p3 = __expf(fminf(s[mt][nt][3], 75.f));
                d0 += p0 + p1;
                d1 += p2 + p3;
                ph[mt][nt][0] = packh(__float2half_rn(p0), __float2half_rn(p1));
                ph[mt][nt][1] = packh(__float2half_rn(p2), __float2half_rn(p3));
            }
            d0 += __shfl_xor_sync(0xffffffffu, d0, 1);
            d0 += __shfl_xor_sync(0xffffffffu, d0, 2);
            d1 += __shfl_xor_sync(0xffffffffu, d1, 1);
            d1 += __shfl_xor_sync(0xffffffffu, d1, 2);
            denomAcc[mt][0] += d0;
            denomAcc[mt][1] += d1;
        }

        // ---- O += P @ V^T ----
        #pragma unroll
        for (int ks = 0; ks < 4; ks++) {
            uint32_t kof = (uint32_t)(ks * 16 + lhalf * 8) * 2;
            uint32_t bvh[8][2];
            #pragma unroll
            for (int p = 0; p < 4; p++) {
                uint32_t bb = vBase + (uint32_t)((p * 16 + lrow) * APAD) * 2 + kof;
                LDSM4(bvh[2*p][0], bvh[2*p+1][0], bvh[2*p][1], bvh[2*p+1][1], bb);
            }
            #pragma unroll
            for (int mt = 0; mt < 2; mt++) {
                uint32_t ah4[4] = { ph[mt][2*ks][0], ph[mt][2*ks][1],
                                    ph[mt][2*ks+1][0], ph[mt][2*ks+1][1] };
                #pragma unroll
                for (int nt = 0; nt < 8; nt++)
                    mma_f16(o[mt][nt], ah4, bvh[nt]);
            }
        }

        // prefetch tile kt+2 into the stage just consumed
        if (kt + 2 < 4) {
            __syncthreads();
            int pt = kt + 2;
            uint32_t kb = kvStage[kt & 1];
            #pragma unroll
            for (int s2 = 0; s2 < 2; s2++) {
                int sg = tseg + s2 * 4;
                CP16(kb + kdst + sg * 16,        ksrc + (size_t)pt * 64 * KVD + sg * 8);
                CP16(kb + vOff + kdst + sg * 16, vsrc + pt * 64 + sg * 8);
            }
            CP_COMMIT();
        }
    }

    // ---- epilogue ----
    #pragma unroll
    for (int mt = 0; mt < 2; mt++) {
        #pragma unroll
        for (int half = 0; half < 2; half++) {
            float inv = 1.f / denomAcc[mt][half];
            int tokout = b * LL + n * 256 + wid * 32 + mt * 16 + quad + half * 8;
            size_t rowb = (size_t)tokout * DD + h * 64;
            #pragma unroll
            for (int nt = 0; nt < 8; nt++) {
                float v0 = o[mt][nt][half * 2 + 0] * inv;
                float v1 = o[mt][nt][half * 2 + 1] * inv;
                int col = nt * 8 + tq * 2;
                *(uint32_t*)&oatt[rowb + col] = packh(__float2half_rn(v0), __float2half_rn(v1));
            }
        }
    }
}

// ---------------- aux scalar ----------------
__global__ void aux_kernel(float* __restrict__ out, long long out_size) {
    if (threadIdx.x == 0 && blockIdx.x == 0) {
        float pen = 0.f;
        #pragma unroll
        for (int e = 0; e < EE; e++) {
            float usage = (float)g_ecount[e] / ((float)NTOK + 1e-8f);
            pen += fmaxf(usage - 0.4f, 0.f);
        }
        float ent = g_entsum / (float)NTOK;
        float aux = 0.05f * ent + pen;
        long long total = (long long)NTOK * HID;
        if (out_size > total) out[total] = aux;
    }
}

// ---------------- launch ----------------
extern "C" void kernel_launch(void* const* d_in, const int* in_sizes, int n_in,
                              void* d_out, int out_size) {
    const float* x     = (const float*)d_in[0];
    const float* Wq    = (const float*)d_in[1];
    const float* bq    = (const float*)d_in[2];
    const float* Wk    = (const float*)d_in[3];
    const float* bk    = (const float*)d_in[4];
    const float* Wv    = (const float*)d_in[5];
    const float* bv    = (const float*)d_in[6];
    const float* Wo    = (const float*)d_in[7];
    const float* bo    = (const float*)d_in[8];
    const float* ln1_g = (const float*)d_in[9];
    const float* ln1_b = (const float*)d_in[10];
    const float* ln2_g = (const float*)d_in[11];
    const float* ln2_b = (const float*)d_in[12];
    const float* Wg    = (const float*)d_in[13];
    const float* bg    = (const float*)d_in[14];
    const float* We    = (const float*)d_in[15];
    const float* be    = (const float*)d_in[16];
    float* out = (float*)d_out;

    __half *ln1, *att, *ln2, *wqkv, *wot, *wet;
    float *bqkv;
    cudaGetSymbolAddress((void**)&ln1,  g_ln1);
    cudaGetSymbolAddress((void**)&att,  g_att);
    cudaGetSymbolAddress((void**)&ln2,  g_ln2);
    cudaGetSymbolAddress((void**)&wqkv, g_wqkv);
    cudaGetSymbolAddress((void**)&wot,  g_wot);
    cudaGetSymbolAddress((void**)&wet,  g_wet);
    cudaGetSymbolAddress((void**)&bqkv, g_bqkv);

    const int ASM = (256 + 2 * 128) * APAD * 2;   // 73728
    cudaFuncSetAttribute(attn_kernel, cudaFuncAttributeMaxDynamicSharedMemorySize, ASM);
    cudaFuncSetAttribute(tc_gemm<1>, cudaFuncAttributeMaxDynamicSharedMemorySize, GSMEM);
    cudaFuncSetAttribute(tc_gemm<2>, cudaFuncAttributeMaxDynamicSharedMemorySize, GSMEM);
    cudaFuncSetAttribute(tc_gemm<3>, cudaFuncAttributeMaxDynamicSharedMemorySize, GSMEM);

    transpose_all<<<10501, dim3(32, 8)>>>(Wq, Wk, Wv, Wo, We, bq, bk, bv);

    ln_kernel<<<NTOK, 256>>>(x, ln1_g, ln1_b, ln1);

    // QKV GEMM: writes g_qh (fp16, scaled) + g_kh (fp16) + g_vt (fp16 transposed)
    tc_gemm<1><<<dim3(10, 64), 256, GSMEM>>>(ln1, wqkv, bqkv, nullptr, nullptr, 0);

    attn_kernel<<<dim3(NWIN, HH, BB), 256, ASM>>>(att);

    // out = x + attn@Wo + bo
    tc_gemm<2><<<dim3(8, 64), 256, GSMEM>>>(att, wot, bo, x, out, DD);

    ln2_gate_kernel<<<NTOK, 256>>>(out, ln2_g, ln2_b, Wg, bg, ln2);

    // MoE: atomicAdd directly into out
    tc_gemm<3><<<dim3(8, 64, EE), 256, GSMEM>>>(ln2, wet, be, nullptr, out, HID);

    aux_kernel<<<1, 32>>>(out, (long long)out_size);
}

// round 15
// speedup vs baseline: 2.1616x; 1.0187x over previous
#include <cuda_runtime.h>
#include <cuda_fp16.h>
#include <math.h>
#include <stdint.h>

// Problem constants
#define BB 2
#define LL 4096
#define DD 1024
#define HH 16
#define GG 2
#define HD 64
#define KVD 128
#define KVC 256
#define QKVC 1280        // Q(1024) | K(128) | V(128)
#define EE 8
#define HID 1024
#define NTOK (BB*LL)     // 8192
#define NWIN 16
#define WIN 256
#define TCK 32           // K-chunk (32 fp16 columns per stage)
#define NCH (DD/TCK)     // 32 chunks
#define BSTR 40          // padded smem row stride (80B, ldmatrix conflict-free)
#define TILE (128*BSTR)
#define TILEB (TILE*2)   // 10240 bytes
#define BUFB (2*TILEB)   // one stage = A|B = 20480 bytes
#define NSTAGE 4
#define GSMEM (NSTAGE*BUFB)  // 81920 -> 2 CTAs/SM
#define APAD 72          // attention smem row stride

// ---------------- scratch (static device globals) ----------------
__device__ __align__(16) __half g_ln1 [NTOK*DD];
__device__ __align__(16) __half g_qh  [NTOK*DD];      // Q, pre-scaled 1/8, fp16
__device__ __align__(16) __half g_kh  [NTOK*KVD];     // K fp16 [token][128]
__device__ __align__(16) __half g_vt  [BB*GG*64*LL];  // V fp16 transposed [(b,g,dim)][pos]
__device__ __align__(16) __half g_att [NTOK*DD];
__device__ __align__(16) __half g_ln2 [NTOK*DD];
__device__ __align__(16) __half g_wqkv[QKVC*DD];
__device__ __align__(16) __half g_wot [DD*DD];
__device__ __align__(16) __half g_wet [EE*DD*HID];
__device__ float g_bqkv[QKVC];
__device__ int   g_ecount[EE];
__device__ float g_entsum;
__device__ int   g_etok[EE*NTOK];   // tok*2 + slot
__device__ float g_ewt [EE*NTOK];

// ---------------- helpers ----------------
__device__ __forceinline__ uint32_t su32(const void* p) {
    uint32_t r;
    asm("{ .reg .u64 t; cvta.to.shared.u64 t, %1; cvt.u32.u64 %0, t; }" : "=r"(r) : "l"(p));
    return r;
}
#define CP16(dst, src) asm volatile("cp.async.cg.shared.global [%0], [%1], 16;" :: "r"(dst), "l"(src))
#define CP_COMMIT()    asm volatile("cp.async.commit_group;" ::: "memory")
#define CP_WAIT0()     asm volatile("cp.async.wait_group 0;" ::: "memory")
#define CP_WAIT1()     asm volatile("cp.async.wait_group 1;" ::: "memory")
#define CP_WAIT2()     asm volatile("cp.async.wait_group 2;" ::: "memory")

#define LDSM4(r0, r1, r2, r3, addr) \
    asm volatile("ldmatrix.sync.aligned.m8n8.x4.shared.b16 {%0,%1,%2,%3}, [%4];" \
                 : "=r"(r0), "=r"(r1), "=r"(r2), "=r"(r3) : "r"(addr))

__device__ __forceinline__ void mma_f16(float* c, const uint32_t* a, const uint32_t* b) {
    asm volatile(
        "mma.sync.aligned.m16n8k16.row.col.f32.f16.f16.f32 "
        "{%0,%1,%2,%3}, {%4,%5,%6,%7}, {%8,%9}, {%0,%1,%2,%3};"
        : "+f"(c[0]), "+f"(c[1]), "+f"(c[2]), "+f"(c[3])
        : "r"(a[0]), "r"(a[1]), "r"(a[2]), "r"(a[3]), "r"(b[0]), "r"(b[1]));
}
__device__ __forceinline__ uint32_t packh(__half lo, __half hi) {
    return (uint32_t)__half_as_ushort(lo) | ((uint32_t)__half_as_ushort(hi) << 16);
}

// ---------------- fused weight transpose + fp16 convert + init ------------
__global__ void __launch_bounds__(256)
transpose_all(const float* __restrict__ Wq, const float* __restrict__ Wk,
              const float* __restrict__ Wv, const float* __restrict__ Wo,
              const float* __restrict__ We,
              const float* __restrict__ bq, const float* __restrict__ bk,
              const float* __restrict__ bv) {
    __shared__ float t[32][33];
    int bid = blockIdx.x;
    if (bid >= 10496) {
        int tt = threadIdx.y * 32 + threadIdx.x + (bid - 10496) * 256;
        if (tt < DD) g_bqkv[tt] = bq[tt];
        else if (tt < DD + KVD) g_bqkv[tt] = bk[tt - DD];
        else if (tt < QKVC) g_bqkv[tt] = bv[tt - DD - KVD];
        if (bid == 10496) {
            if (tt < EE) g_ecount[tt] = 0;
            if (tt == EE) g_entsum = 0.f;
        }
        return;
    }
    const float* src;
    __half* dh;
    int cols, rowOff, bx, by;
    size_t dstOff = 0;
    if (bid < 1024) {
        src = Wq; dh = g_wqkv; cols = DD; rowOff = 0;
        bx = bid & 31; by = bid >> 5;
    } else if (bid < 1152) {
        int r = bid - 1024;
        src = Wk; dh = g_wqkv; cols = KVD; rowOff = DD;
        bx = r & 3; by = r >> 2;
    } else if (bid < 1280) {
        int r = bid - 1152;
        src = Wv; dh = g_wqkv; cols = KVD; rowOff = DD + KVD;
        bx = r & 3; by = r >> 2;
    } else if (bid < 2304) {
        int r = bid - 1280;
        src = Wo; dh = g_wot; cols = DD; rowOff = 0;
        bx = r & 31; by = r >> 5;
    } else {
        int r = bid - 2304;
        int e = r >> 10; r &= 1023;
        src = We + (size_t)e * DD * HID;
        dh = g_wet; dstOff = (size_t)e * DD * HID;
        cols = HID; rowOff = 0;
        bx = r & 31; by = r >> 5;
    }
    int c0 = bx * 32, r0 = by * 32;
    int tx = threadIdx.x, ty = threadIdx.y;
    #pragma unroll
    for (int i = 0; i < 32; i += 8)
        t[ty + i][tx] = src[(size_t)(r0 + ty + i) * cols + c0 + tx];
    __syncthreads();
    #pragma unroll
    for (int i = 0; i < 32; i += 8) {
        size_t o = dstOff + (size_t)(c0 + ty + i + rowOff) * DD + r0 + tx;
        dh[o] = __float2half_rn(t[tx][ty + i]);
    }
}

// ---------------- LayerNorm (fp16 output) ----------
__global__ void ln_kernel(const float* __restrict__ x, const float* __restrict__ g,
                          const float* __restrict__ b, __half* __restrict__ y) {
    int row = blockIdx.x;
    const float4* xr = (const float4*)(x + (size_t)row * DD);
    int tid = threadIdx.x;
    float4 v = xr[tid];
    float s  = v.x + v.y + v.z + v.w;
    float ss = v.x*v.x + v.y*v.y + v.z*v.z + v.w*v.w;
    #pragma unroll
    for (int o = 16; o > 0; o >>= 1) {
        s  += __shfl_down_sync(0xffffffffu, s,  o);
        ss += __shfl_down_sync(0xffffffffu, ss, o);
    }
    __shared__ float sh_s[8], sh_ss[8];
    __shared__ float s_mean, s_rstd;
    int warp = tid >> 5, lane = tid & 31;
    if (lane == 0) { sh_s[warp] = s; sh_ss[warp] = ss; }
    __syncthreads();
    if (tid == 0) {
        float S = 0.f, SS = 0.f;
        #pragma unroll
        for (int i = 0; i < 8; i++) { S += sh_s[i]; SS += sh_ss[i]; }
        float mean = S / (float)DD;
        float var  = SS / (float)DD - mean * mean;
        s_mean = mean;
        s_rstd = rsqrtf(var + 1e-5f);
    }
    __syncthreads();
    float mean = s_mean, rstd = s_rstd;
    float4 gg = ((const float4*)g)[tid];
    float4 bb = ((const float4*)b)[tid];
    float o[4];
    o[0] = (v.x - mean) * rstd * gg.x + bb.x;
    o[1] = (v.y - mean) * rstd * gg.y + bb.y;
    o[2] = (v.z - mean) * rstd * gg.z + bb.z;
    o[3] = (v.w - mean) * rstd * gg.w + bb.w;
    size_t base = (size_t)row * DD + tid * 4;
    uint32_t p0 = packh(__float2half_rn(o[0]), __float2half_rn(o[1]));
    uint32_t p1 = packh(__float2half_rn(o[2]), __float2half_rn(o[3]));
    *(uint2*)&y[base] = make_uint2(p0, p1);
}

// ---------------- LN2 + MoE gate fused ----------------
__global__ void ln2_gate_kernel(const float* __restrict__ x, const float* __restrict__ g,
                                const float* __restrict__ b,
                                const float* __restrict__ Wg, const float* __restrict__ bg,
                                __half* __restrict__ y) {
    int row = blockIdx.x;
    const float4* xr = (const float4*)(x + (size_t)row * DD);
    int tid = threadIdx.x;
    float4 v = xr[tid];
    float s  = v.x + v.y + v.z + v.w;
    float ss = v.x*v.x + v.y*v.y + v.z*v.z + v.w*v.w;
    #pragma unroll
    for (int o = 16; o > 0; o >>= 1) {
        s  += __shfl_down_sync(0xffffffffu, s,  o);
        ss += __shfl_down_sync(0xffffffffu, ss, o);
    }
    __shared__ float sh_s[8], sh_ss[8];
    __shared__ float s_mean, s_rstd;
    __shared__ float red[8][8];
    int warp = tid >> 5, lane = tid & 31;
    if (lane == 0) { sh_s[warp] = s; sh_ss[warp] = ss; }
    __syncthreads();
    if (tid == 0) {
        float S = 0.f, SS = 0.f;
        #pragma unroll
        for (int i = 0; i < 8; i++) { S += sh_s[i]; SS += sh_ss[i]; }
        float mean = S / (float)DD;
        float var  = SS / (float)DD - mean * mean;
        s_mean = mean;
        s_rstd = rsqrtf(var + 1e-5f);
    }
    __syncthreads();
    float mean = s_mean, rstd = s_rstd;
    float4 gg = ((const float4*)g)[tid];
    float4 bb = ((const float4*)b)[tid];
    float o[4];
    o[0] = (v.x - mean) * rstd * gg.x + bb.x;
    o[1] = (v.y - mean) * rstd * gg.y + bb.y;
    o[2] = (v.z - mean) * rstd * gg.z + bb.z;
    o[3] = (v.w - mean) * rstd * gg.w + bb.w;
    size_t base = (size_t)row * DD + tid * 4;
    uint32_t p0 = packh(__float2half_rn(o[0]), __float2half_rn(o[1]));
    uint32_t p1 = packh(__float2half_rn(o[2]), __float2half_rn(o[3]));
    *(uint2*)&y[base] = make_uint2(p0, p1);

    // ---- gating from in-register LN output ----
    float pr[EE];
    #pragma unroll
    for (int e = 0; e < EE; e++) pr[e] = 0.f;
    #pragma unroll
    for (int i = 0; i < 4; i++) {
        float4 w0 = ((const float4*)Wg)[(tid * 4 + i) * 2];
        float4 w1 = ((const float4*)Wg)[(tid * 4 + i) * 2 + 1];
        pr[0] += o[i] * w0.x; pr[1] += o[i] * w0.y;
        pr[2] += o[i] * w0.z; pr[3] += o[i] * w0.w;
        pr[4] += o[i] * w1.x; pr[5] += o[i] * w1.y;
        pr[6] += o[i] * w1.z; pr[7] += o[i] * w1.w;
    }
    #pragma unroll
    for (int off = 16; off > 0; off >>= 1)
        #pragma unroll
        for (int e = 0; e < EE; e++)
            pr[e] += __shfl_down_sync(0xffffffffu, pr[e], off);
    if (lane == 0)
        #pragma unroll
        for (int e = 0; e < EE; e++) red[warp][e] = pr[e];
    __syncthreads();
    if (tid == 0) {
        float l[EE], m = -3.4e38f;
        #pragma unroll
        for (int e = 0; e < EE; e++) {
            float sum = bg[e];
            #pragma unroll
            for (int w = 0; w < 8; w++) sum += red[w][e];
            l[e] = sum;
            m = fmaxf(m, sum);
        }
        float p[EE], sm = 0.f;
        #pragma unroll
        for (int e = 0; e < EE; e++) { p[e] = __expf(l[e] - m); sm += p[e]; }
        float invs = 1.f / sm, ent = 0.f;
        #pragma unroll
        for (int e = 0; e < EE; e++) {
            p[e] *= invs;
            ent -= p[e] * logf(p[e] + 1e-8f);
        }
        atomicAdd(&g_entsum, ent);
        int i1 = 0;
        #pragma unroll
        for (int e = 1; e < EE; e++) if (p[e] > p[i1]) i1 = e;
        int i2 = (i1 == 0) ? 1 : 0;
        #pragma unroll
        for (int e = 0; e < EE; e++) if (e != i1 && p[e] > p[i2]) i2 = e;
        int s1 = atomicAdd(&g_ecount[i1], 1);
        g_etok[i1 * NTOK + s1] = row * 2 + 0; g_ewt[i1 * NTOK + s1] = p[i1];
        int s2 = atomicAdd(&g_ecount[i2], 1);
        g_etok[i2 * NTOK + s2] = row * 2 + 1; g_ewt[i2 * NTOK + s2] = p[i2];
    }
}

// ---------------- fp16 single-pass mma.sync GEMM (4-stage, 2 CTA/SM) ------
// MODE 1: QKV: cols<DD -> g_qh fp16 (scaled); K cols -> g_kh; V cols -> g_vt (transposed)
// MODE 2: C = acc + bias + resid
// MODE 3: MoE gathered rows; atomicAdd(C[tok*ldc+col], w*(acc+bias))
template<int MODE>
__global__ void __launch_bounds__(256)
tc_gemm(const __half* __restrict__ A, const __half* __restrict__ B,
        const float* __restrict__ bias, const float* __restrict__ resid,
        float* __restrict__ C, int ldc) {
    __shared__ int   stok[128];
    __shared__ float swt[128];
    extern __shared__ __half smb[];

    int row0 = blockIdx.y * 128;
    int col0 = blockIdx.x * 128;
    int tid = threadIdx.x, wid = tid >> 5, lane = tid & 31;
    int quad = lane >> 2, tq = lane & 3;
    int wm = wid & 1, wn = wid >> 1;

    if (MODE == 3) {
        int e = blockIdx.z;
        int cnt = g_ecount[e];
        if (row0 >= cnt) return;
        B    += (size_t)e * DD * HID;
        bias += (size_t)e * HID;
        if (tid < 128) {
            int r = row0 + tid;
            if (r < cnt) { stok[tid] = g_etok[e * NTOK + r]; swt[tid] = g_ewt[e * NTOK + r]; }
            else         { stok[tid] = -1; swt[tid] = 0.f; }
        }
        __syncthreads();
    }

    int crow = tid >> 2;
    int seg  = tid & 3;
    const __half *sa[2], *sb[2];
    uint32_t doff[2];
    #pragma unroll
    for (int i = 0; i < 2; i++) {
        int r = crow + 64 * i;
        int tok;
        if (MODE == 3) { int t2 = stok[r]; tok = (t2 < 0) ? 0 : (t2 >> 1); }
        else           tok = row0 + r;
        sa[i] = A + (size_t)tok * DD + seg * 8;
        sb[i] = B + (size_t)(col0 + r) * DD + seg * 8;
        doff[i] = (uint32_t)(r * (BSTR * 2) + seg * 16);
    }
    uint32_t sbase = su32(smb);

    int lrow = lane & 15, lhalf = lane >> 4;
    uint32_t aLane = (uint32_t)(((wm * 64 + lrow) * BSTR + lhalf * 8) * 2);
    uint32_t bLane = (uint32_t)(((wn * 32 + lrow) * BSTR + lhalf * 8) * 2);

    float acc[4][4][4];
    #pragma unroll
    for (int mt = 0; mt < 4; mt++)
        #pragma unroll
        for (int nt = 0; nt < 4; nt++)
            #pragma unroll
            for (int i = 0; i < 4; i++) acc[mt][nt][i] = 0.f;

    // prologue: chunks 0,1,2 into stages 0,1,2
    #pragma unroll
    for (int pc = 0; pc < 3; pc++) {
        uint32_t base = sbase + pc * BUFB;
        int k0 = pc * TCK;
        #pragma unroll
        for (int i = 0; i < 2; i++) {
            CP16(base + 0 * TILEB + doff[i], sa[i] + k0);
            CP16(base + 1 * TILEB + doff[i], sb[i] + k0);
        }
        CP_COMMIT();
    }

    for (int c = 0; c < NCH; c++) {
        if (c == NCH - 1) CP_WAIT0();
        else if (c == NCH - 2) CP_WAIT1();
        else CP_WAIT2();
        __syncthreads();
        if (c + 3 < NCH) {
            uint32_t base = sbase + ((c + 3) & 3) * BUFB;
            int k0 = (c + 3) * TCK;
            #pragma unroll
            for (int i = 0; i < 2; i++) {
                CP16(base + 0 * TILEB + doff[i], sa[i] + k0);
                CP16(base + 1 * TILEB + doff[i], sb[i] + k0);
            }
            CP_COMMIT();
        }

        uint32_t sbuf = sbase + (c & 3) * BUFB;
        #pragma unroll
        for (int kk = 0; kk < 2; kk++) {
            uint32_t kof = kk * 16 * 2;
            uint32_t bh[4][2];
            uint32_t bb0 = sbuf + 1 * TILEB + bLane + kof;
            LDSM4(bh[0][0], bh[1][0], bh[0][1], bh[1][1], bb0);
            LDSM4(bh[2][0], bh[3][0], bh[2][1], bh[3][1], bb0 + 16 * BSTR * 2);
            #pragma unroll
            for (int mt = 0; mt < 4; mt++) {
                uint32_t ah[4];
                uint32_t aa = sbuf + aLane + kof + mt * 16 * BSTR * 2;
                LDSM4(ah[0], ah[1], ah[2], ah[3], aa);
                #pragma unroll
                for (int nt = 0; nt < 4; nt++)
                    mma_f16(acc[mt][nt], ah, bh[nt]);
            }
        }
    }

    #pragma unroll
    for (int mt = 0; mt < 4; mt++) {
        #pragma unroll
        for (int half = 0; half < 2; half++) {
            int lr = wm * 64 + mt * 16 + quad + half * 8;
            int r = row0 + lr;
            #pragma unroll
            for (int nt = 0; nt < 4; nt++) {
                int col = col0 + wn * 32 + nt * 8 + tq * 2;
                float v0 = acc[mt][nt][half * 2 + 0] + bias[col];
                float v1 = acc[mt][nt][half * 2 + 1] + bias[col + 1];
                if (MODE == 1) {
                    if (col < DD) {
                        *(uint32_t*)&g_qh[(size_t)r * DD + col] =
                            packh(__float2half_rn(v0 * 0.125f), __float2half_rn(v1 * 0.125f));
                    } else if (col < DD + KVD) {
                        *(uint32_t*)&g_kh[(size_t)r * KVD + (col - DD)] =
                            packh(__float2half_rn(v0), __float2half_rn(v1));
                    } else {
                        int c2 = col - DD - KVD;       // 0..127
                        int gidx = c2 >> 6, d = c2 & 63;
                        int bb2 = r >> 12, pos = r & (LL - 1);
                        size_t vbase = ((size_t)(bb2 * GG + gidx) * 64 + d) * LL + pos;
                        g_vt[vbase]      = __float2half_rn(v0);
                        g_vt[vbase + LL] = __float2half_rn(v1);
                    }
                } else if (MODE == 2) {
                    size_t o = (size_t)r * ldc + col;
                    float2 rr = *(const float2*)&resid[o];
                    *(float2*)&C[o] = make_float2(v0 + rr.x, v1 + rr.y);
                } else {
                    int t2 = stok[lr];
                    if (t2 >= 0) {
                        int tok = t2 >> 1;
                        float w = swt[lr];
                        atomicAdd(&C[(size_t)tok * ldc + col],     w * v0);
                        atomicAdd(&C[(size_t)tok * ldc + col + 1], w * v1);
                    }
                }
            }
        }
    }
}

// ---------------- tensor-core attention: 512 thr, 16 warps x 16 rows -------
__global__ void __launch_bounds__(512)
attn_kernel(__half* __restrict__ oatt) {
    extern __shared__ __half sma[];
    __half* Qh = sma;                  // 256 x APAD

    int n = blockIdx.x, h = blockIdx.y, b = blockIdx.z;
    int g = h & (GG - 1);
    int base = b * LL + n * 128;
    int tid = threadIdx.x, wid = tid >> 5, lane = tid & 31;
    int quad = lane >> 2, tq = lane & 3;
    int lrow = lane & 15, lhalf = lane >> 4;

    uint32_t qBase = su32(Qh);
    uint32_t kvStage[2];
    kvStage[0] = qBase + (uint32_t)(256 * APAD) * 2;
    kvStage[1] = kvStage[0] + (uint32_t)(128 * APAD) * 2;
    uint32_t vOff = (uint32_t)(64 * APAD) * 2;

    // Q cp.async: 4 segs per thread (256 rows x 8 segs / 512 thr)
    {
        int qrow = tid >> 1, qs = (tid & 1) * 4;
        const __half* qsrc = g_qh + (size_t)(base + qrow) * DD + h * 64 + qs * 8;
        uint32_t qdst = qBase + (uint32_t)(qrow * APAD + qs * 8) * 2;
        #pragma unroll
        for (int s2 = 0; s2 < 4; s2++)
            CP16(qdst + s2 * 16, qsrc + s2 * 8);
        CP_COMMIT();
    }

    // K/V: 1 seg each per thread per tile (64 rows x 8 segs = 512)
    int trow = tid >> 3, tseg = tid & 7;
    const __half* ksrc = g_kh + (size_t)(base + trow) * KVD + g * 64 + tseg * 8;  // + kt*64*KVD
    const __half* vsrc = g_vt + ((size_t)(b * GG + g) * 64 + trow) * LL + n * 128 + tseg * 8; // + kt*64
    uint32_t kdst = (uint32_t)(trow * APAD + tseg * 8) * 2;

    // prologue tiles 0, 1
    #pragma unroll
    for (int pt = 0; pt < 2; pt++) {
        uint32_t kb = kvStage[pt];
        CP16(kb + kdst,        ksrc + (size_t)pt * 64 * KVD);
        CP16(kb + vOff + kdst, vsrc + pt * 64);
        CP_COMMIT();
    }

    float o[8][4];
    #pragma unroll
    for (int nt = 0; nt < 8; nt++)
        #pragma unroll
        for (int i = 0; i < 4; i++) o[nt][i] = 0.f;
    float denomAcc[2] = {0.f, 0.f};

    for (int kt = 0; kt < 4; kt++) {
        if (kt == 3) CP_WAIT0(); else CP_WAIT1();
        __syncthreads();

        uint32_t kBase = kvStage[kt & 1];
        uint32_t vBase = kBase + vOff;

        // ---- S = Q @ K^T ----
        float s[8][4];
        #pragma unroll
        for (int nt = 0; nt < 8; nt++)
            #pragma unroll
            for (int i = 0; i < 4; i++) s[nt][i] = 0.f;

        #pragma unroll
        for (int ks = 0; ks < 4; ks++) {
            uint32_t kof = (uint32_t)(ks * 16 + lhalf * 8) * 2;
            uint32_t ah[4];
            uint32_t aa = qBase + (uint32_t)((wid * 16 + lrow) * APAD) * 2 + kof;
            LDSM4(ah[0], ah[1], ah[2], ah[3], aa);
            uint32_t bh[8][2];
            #pragma unroll
            for (int p = 0; p < 4; p++) {
                uint32_t bb = kBase + (uint32_t)((p * 16 + lrow) * APAD) * 2 + kof;
                LDSM4(bh[2*p][0], bh[2*p+1][0], bh[2*p][1], bh[2*p+1][1], bb);
            }
            #pragma unroll
            for (int nt = 0; nt < 8; nt++)
                mma_f16(s[nt], ah, bh[nt]);
        }

        // ---- exp, denominators, pack P (fp16) ----
        uint32_t ph[8][2];
        {
            float d0 = 0.f, d1 = 0.f;
            #pragma unroll
            for (int nt = 0; nt < 8; nt++) {
                float p0 = __expf(fminf(s[nt][0], 75.f));
                float p1 = __expf(fminf(s[nt][1], 75.f));
                float p2 = __expf(fminf(s[nt][2], 75.f));
                float p3 = __expf(fminf(s[nt][3], 75.f));
                d0 += p0 + p1;
                d1 += p2 + p3;
                ph[nt][0] = packh(__float2half_rn(p0), __float2half_rn(p1));
                ph[nt][1] = packh(__float2half_rn(p2), __float2half_rn(p3));
            }
            d0 += __shfl_xor_sync(0xffffffffu, d0, 1);
            d0 += __shfl_xor_sync(0xffffffffu, d0, 2);
            d1 += __shfl_xor_sync(0xffffffffu, d1, 1);
            d1 += __shfl_xor_sync(0xffffffffu, d1, 2);
            denomAcc[0] += d0;
            denomAcc[1] += d1;
        }

        // ---- O += P @ V^T ----
        #pragma unroll
        for (int ks = 0; ks < 4; ks++) {
            uint32_t kof = (uint32_t)(ks * 16 + lhalf * 8) * 2;
            uint32_t bvh[8][2];
            #pragma unroll
            for (int p = 0; p < 4; p++) {
                uint32_t bb = vBase + (uint32_t)((p * 16 + lrow) * APAD) * 2 + kof;
                LDSM4(bvh[2*p][0], bvh[2*p+1][0], bvh[2*p][1], bvh[2*p+1][1], bb);
            }
            uint32_t ah4[4] = { ph[2*ks][0], ph[2*ks][1], ph[2*ks+1][0], ph[2*ks+1][1] };
            #pragma unroll
            for (int nt = 0; nt < 8; nt++)
                mma_f16(o[nt], ah4, bvh[nt]);
        }

        // prefetch tile kt+2 into the stage just consumed
        if (kt + 2 < 4) {
            __syncthreads();
            int pt = kt + 2;
            uint32_t kb = kvStage[kt & 1];
            CP16(kb + kdst,        ksrc + (size_t)pt * 64 * KVD);
            CP16(kb + vOff + kdst, vsrc + pt * 64);
            CP_COMMIT();
        }
    }

    // ---- epilogue ----
    #pragma unroll
    for (int half = 0; half < 2; half++) {
        float inv = 1.f / denomAcc[half];
        int tokout = b * LL + n * 256 + wid * 16 + quad + half * 8;
        size_t rowb = (size_t)tokout * DD + h * 64;
        #pragma unroll
        for (int nt = 0; nt < 8; nt++) {
            float v0 = o[nt][half * 2 + 0] * inv;
            float v1 = o[nt][half * 2 + 1] * inv;
            int col = nt * 8 + tq * 2;
            *(uint32_t*)&oatt[rowb + col] = packh(__float2half_rn(v0), __float2half_rn(v1));
        }
    }
}

// ---------------- aux scalar ----------------
__global__ void aux_kernel(float* __restrict__ out, long long out_size) {
    if (threadIdx.x == 0 && blockIdx.x == 0) {
        float pen = 0.f;
        #pragma unroll
        for (int e = 0; e < EE; e++) {
            float usage = (float)g_ecount[e] / ((float)NTOK + 1e-8f);
            pen += fmaxf(usage - 0.4f, 0.f);
        }
        float ent = g_entsum / (float)NTOK;
        float aux = 0.05f * ent + pen;
        long long total = (long long)NTOK * HID;
        if (out_size > total) out[total] = aux;
    }
}

// ---------------- launch ----------------
extern "C" void kernel_launch(void* const* d_in, const int* in_sizes, int n_in,
                              void* d_out, int out_size) {
    const float* x     = (const float*)d_in[0];
    const float* Wq    = (const float*)d_in[1];
    const float* bq    = (const float*)d_in[2];
    const float* Wk    = (const float*)d_in[3];
    const float* bk    = (const float*)d_in[4];
    const float* Wv    = (const float*)d_in[5];
    const float* bv    = (const float*)d_in[6];
    const float* Wo    = (const float*)d_in[7];
    const float* bo    = (const float*)d_in[8];
    const float* ln1_g = (const float*)d_in[9];
    const float* ln1_b = (const float*)d_in[10];
    const float* ln2_g = (const float*)d_in[11];
    const float* ln2_b = (const float*)d_in[12];
    const float* Wg    = (const float*)d_in[13];
    const float* bg    = (const float*)d_in[14];
    const float* We    = (const float*)d_in[15];
    const float* be    = (const float*)d_in[16];
    float* out = (float*)d_out;

    __half *ln1, *att, *ln2, *wqkv, *wot, *wet;
    float *bqkv;
    cudaGetSymbolAddress((void**)&ln1,  g_ln1);
    cudaGetSymbolAddress((void**)&att,  g_att);
    cudaGetSymbolAddress((void**)&ln2,  g_ln2);
    cudaGetSymbolAddress((void**)&wqkv, g_wqkv);
    cudaGetSymbolAddress((void**)&wot,  g_wot);
    cudaGetSymbolAddress((void**)&wet,  g_wet);
    cudaGetSymbolAddress((void**)&bqkv, g_bqkv);

    const int ASM = (256 + 2 * 128) * APAD * 2;   // 73728
    cudaFuncSetAttribute(attn_kernel, cudaFuncAttributeMaxDynamicSharedMemorySize, ASM);
    cudaFuncSetAttribute(tc_gemm<1>, cudaFuncAttributeMaxDynamicSharedMemorySize, GSMEM);
    cudaFuncSetAttribute(tc_gemm<2>, cudaFuncAttributeMaxDynamicSharedMemorySize, GSMEM);
    cudaFuncSetAttribute(tc_gemm<3>, cudaFuncAttributeMaxDynamicSharedMemorySize, GSMEM);

    transpose_all<<<10501, dim3(32, 8)>>>(Wq, Wk, Wv, Wo, We, bq, bk, bv);

    ln_kernel<<<NTOK, 256>>>(x, ln1_g, ln1_b, ln1);

    // QKV GEMM: writes g_qh (fp16, scaled) + g_kh (fp16) + g_vt (fp16 transposed)
    tc_gemm<1><<<dim3(10, 64), 256, GSMEM>>>(ln1, wqkv, bqkv, nullptr, nullptr, 0);

    attn_kernel<<<dim3(NWIN, HH, BB), 512, ASM>>>(att);

    // out = x + attn@Wo + bo
    tc_gemm<2><<<dim3(8, 64), 256, GSMEM>>>(att, wot, bo, x, out, DD);

    ln2_gate_kernel<<<NTOK, 256>>>(out, ln2_g, ln2_b, Wg, bg, ln2);

    // MoE: atomicAdd directly into out
    tc_gemm<3><<<dim3(8, 64, EE), 256, GSMEM>>>(ln2, wet, be, nullptr, out, HID);

    aux_kernel<<<1, 32>>>(out, (long long)out_size);
}

// round 16
// speedup vs baseline: 2.1800x; 1.0085x over previous
#include <cuda_runtime.h>
#include <cuda_fp16.h>
#include <math.h>
#include <stdint.h>

// Problem constants
#define BB 2
#define LL 4096
#define DD 1024
#define HH 16
#define GG 2
#define HD 64
#define KVD 128
#define KVC 256
#define QKVC 1280        // Q(1024) | K(128) | V(128)
#define EE 8
#define HID 1024
#define NTOK (BB*LL)     // 8192
#define NWIN 16
#define WIN 256
#define TCK 32           // K-chunk (32 fp16 columns per stage)
#define NCH (DD/TCK)     // 32 chunks
#define BSTR 40          // padded smem row stride (80B, ldmatrix conflict-free)
#define TILE (128*BSTR)
#define TILEB (TILE*2)   // 10240 bytes
#define BUFB (2*TILEB)   // one stage = A|B = 20480 bytes
#define NSTAGE 4
#define GSMEM (NSTAGE*BUFB)  // 81920 -> 2 CTAs/SM
#define APAD 72          // attention smem row stride

// ---------------- scratch (static device globals) ----------------
__device__ __align__(16) __half g_ln1 [NTOK*DD];
__device__ __align__(16) __half g_qh  [NTOK*DD];      // Q, pre-scaled 1/8, fp16
__device__ __align__(16) __half g_kh  [NTOK*KVD];     // K fp16 [token][128]
__device__ __align__(16) __half g_vt  [BB*GG*64*LL];  // V fp16 transposed [(b,g,dim)][pos]
__device__ __align__(16) __half g_att [NTOK*DD];
__device__ __align__(16) __half g_ln2 [NTOK*DD];
__device__ __align__(16) __half g_wqkv[QKVC*DD];
__device__ __align__(16) __half g_wot [DD*DD];
__device__ __align__(16) __half g_wet [EE*DD*HID];
__device__ float g_bqkv[QKVC];
__device__ int   g_ecount[EE];
__device__ float g_entsum;
__device__ int   g_etok[EE*NTOK];   // tok*2 + slot
__device__ float g_ewt [EE*NTOK];

// ---------------- helpers ----------------
__device__ __forceinline__ uint32_t su32(const void* p) {
    uint32_t r;
    asm("{ .reg .u64 t; cvta.to.shared.u64 t, %1; cvt.u32.u64 %0, t; }" : "=r"(r) : "l"(p));
    return r;
}
#define CP16(dst, src) asm volatile("cp.async.cg.shared.global [%0], [%1], 16;" :: "r"(dst), "l"(src))
#define CP_COMMIT()    asm volatile("cp.async.commit_group;" ::: "memory")
#define CP_WAIT0()     asm volatile("cp.async.wait_group 0;" ::: "memory")
#define CP_WAIT1()     asm volatile("cp.async.wait_group 1;" ::: "memory")
#define CP_WAIT2()     asm volatile("cp.async.wait_group 2;" ::: "memory")

#define LDSM4(r0, r1, r2, r3, addr) \
    asm volatile("ldmatrix.sync.aligned.m8n8.x4.shared.b16 {%0,%1,%2,%3}, [%4];" \
                 : "=r"(r0), "=r"(r1), "=r"(r2), "=r"(r3) : "r"(addr))

__device__ __forceinline__ void mma_f16(float* c, const uint32_t* a, const uint32_t* b) {
    asm volatile(
        "mma.sync.aligned.m16n8k16.row.col.f32.f16.f16.f32 "
        "{%0,%1,%2,%3}, {%4,%5,%6,%7}, {%8,%9}, {%0,%1,%2,%3};"
        : "+f"(c[0]), "+f"(c[1]), "+f"(c[2]), "+f"(c[3])
        : "r"(a[0]), "r"(a[1]), "r"(a[2]), "r"(a[3]), "r"(b[0]), "r"(b[1]));
}
// single-instruction fp32x2 -> fp16x2 pack (cvt.rn.f16x2.f32)
__device__ __forceinline__ uint32_t packf2(float lo, float hi) {
    __half2 h = __floats2half2_rn(lo, hi);
    return *(uint32_t*)&h;
}

// ---------------- weight prep part A: Wq|Wk|Wv + bias + zero ---------------
// blocks: [0,1024) Wq | [1024,1152) Wk | [1152,1280) Wv | [1280,1285) bias/zero
__global__ void __launch_bounds__(256)
transpose_qkv(const float* __restrict__ Wq, const float* __restrict__ Wk,
              const float* __restrict__ Wv,
              const float* __restrict__ bq, const float* __restrict__ bk,
              const float* __restrict__ bv) {
    __shared__ float t[32][33];
    int bid = blockIdx.x;
    if (bid >= 1280) {
        int tt = threadIdx.y * 32 + threadIdx.x + (bid - 1280) * 256;
        if (tt < DD) g_bqkv[tt] = bq[tt];
        else if (tt < DD + KVD) g_bqkv[tt] = bk[tt - DD];
        else if (tt < QKVC) g_bqkv[tt] = bv[tt - DD - KVD];
        if (bid == 1280) {
            if (tt < EE) g_ecount[tt] = 0;
            if (tt == EE) g_entsum = 0.f;
        }
        return;
    }
    const float* src;
    int cols, rowOff, bx, by;
    if (bid < 1024) {
        src = Wq; cols = DD; rowOff = 0;
        bx = bid & 31; by = bid >> 5;
    } else if (bid < 1152) {
        int r = bid - 1024;
        src = Wk; cols = KVD; rowOff = DD;
        bx = r & 3; by = r >> 2;
    } else {
        int r = bid - 1152;
        src = Wv; cols = KVD; rowOff = DD + KVD;
        bx = r & 3; by = r >> 2;
    }
    int c0 = bx * 32, r0 = by * 32;
    int tx = threadIdx.x, ty = threadIdx.y;
    #pragma unroll
    for (int i = 0; i < 32; i += 8)
        t[ty + i][tx] = src[(size_t)(r0 + ty + i) * cols + c0 + tx];
    __syncthreads();
    #pragma unroll
    for (int i = 0; i < 32; i += 8) {
        size_t o = (size_t)(c0 + ty + i + rowOff) * DD + r0 + tx;
        g_wqkv[o] = __float2half_rn(t[tx][ty + i]);
    }
}

// ---------------- weight prep part B: Wo + We (side stream) ----------------
// blocks: [0,1024) Wo | [1024,9216) We (1024 per expert)
__global__ void __launch_bounds__(256)
transpose_owe(const float* __restrict__ Wo, const float* __restrict__ We) {
    __shared__ float t[32][33];
    int bid = blockIdx.x;
    const float* src;
    __half* dh;
    int cols, bx, by;
    size_t dstOff = 0;
    if (bid < 1024) {
        src = Wo; dh = g_wot; cols = DD;
        bx = bid & 31; by = bid >> 5;
    } else {
        int r = bid - 1024;
        int e = r >> 10; r &= 1023;
        src = We + (size_t)e * DD * HID;
        dh = g_wet; dstOff = (size_t)e * DD * HID;
        cols = HID;
        bx = r & 31; by = r >> 5;
    }
    int c0 = bx * 32, r0 = by * 32;
    int tx = threadIdx.x, ty = threadIdx.y;
    #pragma unroll
    for (int i = 0; i < 32; i += 8)
        t[ty + i][tx] = src[(size_t)(r0 + ty + i) * cols + c0 + tx];
    __syncthreads();
    #pragma unroll
    for (int i = 0; i < 32; i += 8) {
        size_t o = dstOff + (size_t)(c0 + ty + i) * DD + r0 + tx;
        dh[o] = __float2half_rn(t[tx][ty + i]);
    }
}

// ---------------- LayerNorm (fp16 output) ----------
__global__ void ln_kernel(const float* __restrict__ x, const float* __restrict__ g,
                          const float* __restrict__ b, __half* __restrict__ y) {
    int row = blockIdx.x;
    const float4* xr = (const float4*)(x + (size_t)row * DD);
    int tid = threadIdx.x;
    float4 v = xr[tid];
    float s  = v.x + v.y + v.z + v.w;
    float ss = v.x*v.x + v.y*v.y + v.z*v.z + v.w*v.w;
    #pragma unroll
    for (int o = 16; o > 0; o >>= 1) {
        s  += __shfl_down_sync(0xffffffffu, s,  o);
        ss += __shfl_down_sync(0xffffffffu, ss, o);
    }
    __shared__ float sh_s[8], sh_ss[8];
    __shared__ float s_mean, s_rstd;
    int warp = tid >> 5, lane = tid & 31;
    if (lane == 0) { sh_s[warp] = s; sh_ss[warp] = ss; }
    __syncthreads();
    if (tid == 0) {
        float S = 0.f, SS = 0.f;
        #pragma unroll
        for (int i = 0; i < 8; i++) { S += sh_s[i]; SS += sh_ss[i]; }
        float mean = S / (float)DD;
        float var  = SS / (float)DD - mean * mean;
        s_mean = mean;
        s_rstd = rsqrtf(var + 1e-5f);
    }
    __syncthreads();
    float mean = s_mean, rstd = s_rstd;
    float4 gg = ((const float4*)g)[tid];
    float4 bb = ((const float4*)b)[tid];
    float o[4];
    o[0] = (v.x - mean) * rstd * gg.x + bb.x;
    o[1] = (v.y - mean) * rstd * gg.y + bb.y;
    o[2] = (v.z - mean) * rstd * gg.z + bb.z;
    o[3] = (v.w - mean) * rstd * gg.w + bb.w;
    size_t base = (size_t)row * DD + tid * 4;
    *(uint2*)&y[base] = make_uint2(packf2(o[0], o[1]), packf2(o[2], o[3]));
}

// ---------------- LN2 + MoE gate fused ----------------
__global__ void ln2_gate_kernel(const float* __restrict__ x, const float* __restrict__ g,
                                const float* __restrict__ b,
                                const float* __restrict__ Wg, const float* __restrict__ bg,
                                __half* __restrict__ y) {
    int row = blockIdx.x;
    const float4* xr = (const float4*)(x + (size_t)row * DD);
    int tid = threadIdx.x;
    float4 v = xr[tid];
    float s  = v.x + v.y + v.z + v.w;
    float ss = v.x*v.x + v.y*v.y + v.z*v.z + v.w*v.w;
    #pragma unroll
    for (int o = 16; o > 0; o >>= 1) {
        s  += __shfl_down_sync(0xffffffffu, s,  o);
        ss += __shfl_down_sync(0xffffffffu, ss, o);
    }
    __shared__ float sh_s[8], sh_ss[8];
    __shared__ float s_mean, s_rstd;
    __shared__ float red[8][8];
    int warp = tid >> 5, lane = tid & 31;
    if (lane == 0) { sh_s[warp] = s; sh_ss[warp] = ss; }
    __syncthreads();
    if (tid == 0) {
        float S = 0.f, SS = 0.f;
        #pragma unroll
        for (int i = 0; i < 8; i++) { S += sh_s[i]; SS += sh_ss[i]; }
        float mean = S / (float)DD;
        float var  = SS / (float)DD - mean * mean;
        s_mean = mean;
        s_rstd = rsqrtf(var + 1e-5f);
    }
    __syncthreads();
    float mean = s_mean, rstd = s_rstd;
    float4 gg = ((const float4*)g)[tid];
    float4 bb = ((const float4*)b)[tid];
    float o[4];
    o[0] = (v.x - mean) * rstd * gg.x + bb.x;
    o[1] = (v.y - mean) * rstd * gg.y + bb.y;
    o[2] = (v.z - mean) * rstd * gg.z + bb.z;
    o[3] = (v.w - mean) * rstd * gg.w + bb.w;
    size_t base = (size_t)row * DD + tid * 4;
    *(uint2*)&y[base] = make_uint2(packf2(o[0], o[1]), packf2(o[2], o[3]));

    // ---- gating from in-register LN output ----
    float pr[EE];
    #pragma unroll
    for (int e = 0; e < EE; e++) pr[e] = 0.f;
    #pragma unroll
    for (int i = 0; i < 4; i++) {
        float4 w0 = ((const float4*)Wg)[(tid * 4 + i) * 2];
        float4 w1 = ((const float4*)Wg)[(tid * 4 + i) * 2 + 1];
        pr[0] += o[i] * w0.x; pr[1] += o[i] * w0.y;
        pr[2] += o[i] * w0.z; pr[3] += o[i] * w0.w;
        pr[4] += o[i] * w1.x; pr[5] += o[i] * w1.y;
        pr[6] += o[i] * w1.z; pr[7] += o[i] * w1.w;
    }
    #pragma unroll
    for (int off = 16; off > 0; off >>= 1)
        #pragma unroll
        for (int e = 0; e < EE; e++)
            pr[e] += __shfl_down_sync(0xffffffffu, pr[e], off);
    if (lane == 0)
        #pragma unroll
        for (int e = 0; e < EE; e++) red[warp][e] = pr[e];
    __syncthreads();
    if (tid == 0) {
        float l[EE], m = -3.4e38f;
        #pragma unroll
        for (int e = 0; e < EE; e++) {
            float sum = bg[e];
            #pragma unroll
            for (int w = 0; w < 8; w++) sum += red[w][e];
            l[e] = sum;
            m = fmaxf(m, sum);
        }
        float p[EE], sm = 0.f;
        #pragma unroll
        for (int e = 0; e < EE; e++) { p[e] = __expf(l[e] - m); sm += p[e]; }
        float invs = 1.f / sm, ent = 0.f;
        #pragma unroll
        for (int e = 0; e < EE; e++) {
            p[e] *= invs;
            ent -= p[e] * logf(p[e] + 1e-8f);
        }
        atomicAdd(&g_entsum, ent);
        int i1 = 0;
        #pragma unroll
        for (int e = 1; e < EE; e++) if (p[e] > p[i1]) i1 = e;
        int i2 = (i1 == 0) ? 1 : 0;
        #pragma unroll
        for (int e = 0; e < EE; e++) if (e != i1 && p[e] > p[i2]) i2 = e;
        int s1 = atomicAdd(&g_ecount[i1], 1);
        g_etok[i1 * NTOK + s1] = row * 2 + 0; g_ewt[i1 * NTOK + s1] = p[i1];
        int s2 = atomicAdd(&g_ecount[i2], 1);
        g_etok[i2 * NTOK + s2] = row * 2 + 1; g_ewt[i2 * NTOK + s2] = p[i2];
    }
}

// ---------------- fp16 single-pass mma.sync GEMM (4-stage, 2 CTA/SM) ------
// MODE 1: QKV: cols<DD -> g_qh fp16 (scaled); K cols -> g_kh; V cols -> g_vt (transposed)
// MODE 2: C = acc + bias + resid
// MODE 3: MoE gathered rows; atomicAdd(C[tok*ldc+col], w*(acc+bias))
template<int MODE>
__global__ void __launch_bounds__(256)
tc_gemm(const __half* __restrict__ A, const __half* __restrict__ B,
        const float* __restrict__ bias, const float* __restrict__ resid,
        float* __restrict__ C, int ldc) {
    __shared__ int   stok[128];
    __shared__ float swt[128];
    extern __shared__ __half smb[];

    int row0 = blockIdx.y * 128;
    int col0 = blockIdx.x * 128;
    int tid = threadIdx.x, wid = tid >> 5, lane = tid & 31;
    int quad = lane >> 2, tq = lane & 3;
    int wm = wid & 1, wn = wid >> 1;

    if (MODE == 3) {
        int e = blockIdx.z;
        int cnt = g_ecount[e];
        if (row0 >= cnt) return;
        B    += (size_t)e * DD * HID;
        bias += (size_t)e * HID;
        if (tid < 128) {
            int r = row0 + tid;
            if (r < cnt) { stok[tid] = g_etok[e * NTOK + r]; swt[tid] = g_ewt[e * NTOK + r]; }
            else         { stok[tid] = -1; swt[tid] = 0.f; }
        }
        __syncthreads();
    }

    int crow = tid >> 2;
    int seg  = tid & 3;
    const __half *sa[2], *sb[2];
    uint32_t doff[2];
    #pragma unroll
    for (int i = 0; i < 2; i++) {
        int r = crow + 64 * i;
        int tok;
        if (MODE == 3) { int t2 = stok[r]; tok = (t2 < 0) ? 0 : (t2 >> 1); }
        else           tok = row0 + r;
        sa[i] = A + (size_t)tok * DD + seg * 8;
        sb[i] = B + (size_t)(col0 + r) * DD + seg * 8;
        doff[i] = (uint32_t)(r * (BSTR * 2) + seg * 16);
    }
    uint32_t sbase = su32(smb);

    int lrow = lane & 15, lhalf = lane >> 4;
    uint32_t aLane = (uint32_t)(((wm * 64 + lrow) * BSTR + lhalf * 8) * 2);
    uint32_t bLane = (uint32_t)(((wn * 32 + lrow) * BSTR + lhalf * 8) * 2);

    float acc[4][4][4];
    #pragma unroll
    for (int mt = 0; mt < 4; mt++)
        #pragma unroll
        for (int nt = 0; nt < 4; nt++)
            #pragma unroll
            for (int i = 0; i < 4; i++) acc[mt][nt][i] = 0.f;

    // prologue: chunks 0,1,2 into stages 0,1,2
    #pragma unroll
    for (int pc = 0; pc < 3; pc++) {
        uint32_t base = sbase + pc * BUFB;
        int k0 = pc * TCK;
        #pragma unroll
        for (int i = 0; i < 2; i++) {
            CP16(base + 0 * TILEB + doff[i], sa[i] + k0);
            CP16(base + 1 * TILEB + doff[i], sb[i] + k0);
        }
        CP_COMMIT();
    }

    for (int c = 0; c < NCH; c++) {
        if (c == NCH - 1) CP_WAIT0();
        else if (c == NCH - 2) CP_WAIT1();
        else CP_WAIT2();
        __syncthreads();
        if (c + 3 < NCH) {
            uint32_t base = sbase + ((c + 3) & 3) * BUFB;
            int k0 = (c + 3) * TCK;
            #pragma unroll
            for (int i = 0; i < 2; i++) {
                CP16(base + 0 * TILEB + doff[i], sa[i] + k0);
                CP16(base + 1 * TILEB + doff[i], sb[i] + k0);
            }
            CP_COMMIT();
        }

        uint32_t sbuf = sbase + (c & 3) * BUFB;
        #pragma unroll
        for (int kk = 0; kk < 2; kk++) {
            uint32_t kof = kk * 16 * 2;
            uint32_t bh[4][2];
            uint32_t bb0 = sbuf + 1 * TILEB + bLane + kof;
            LDSM4(bh[0][0], bh[1][0], bh[0][1], bh[1][1], bb0);
            LDSM4(bh[2][0], bh[3][0], bh[2][1], bh[3][1], bb0 + 16 * BSTR * 2);
            #pragma unroll
            for (int mt = 0; mt < 4; mt++) {
                uint32_t ah[4];
                uint32_t aa = sbuf + aLane + kof + mt * 16 * BSTR * 2;
                LDSM4(ah[0], ah[1], ah[2], ah[3], aa);
                #pragma unroll
                for (int nt = 0; nt < 4; nt++)
                    mma_f16(acc[mt][nt], ah, bh[nt]);
            }
        }
    }

    #pragma unroll
    for (int mt = 0; mt < 4; mt++) {
        #pragma unroll
        for (int half = 0; half < 2; half++) {
            int lr = wm * 64 + mt * 16 + quad + half * 8;
            int r = row0 + lr;
            #pragma unroll
            for (int nt = 0; nt < 4; nt++) {
                int col = col0 + wn * 32 + nt * 8 + tq * 2;
                float v0 = acc[mt][nt][half * 2 + 0] + bias[col];
                float v1 = acc[mt][nt][half * 2 + 1] + bias[col + 1];
                if (MODE == 1) {
                    if (col < DD) {
                        *(uint32_t*)&g_qh[(size_t)r * DD + col] =
                            packf2(v0 * 0.125f, v1 * 0.125f);
                    } else if (col < DD + KVD) {
                        *(uint32_t*)&g_kh[(size_t)r * KVD + (col - DD)] = packf2(v0, v1);
                    } else {
                        int c2 = col - DD - KVD;       // 0..127
                        int gidx = c2 >> 6, d = c2 & 63;
                        int bb2 = r >> 12, pos = r & (LL - 1);
                        size_t vbase = ((size_t)(bb2 * GG + gidx) * 64 + d) * LL + pos;
                        g_vt[vbase]      = __float2half_rn(v0);
                        g_vt[vbase + LL] = __float2half_rn(v1);
                    }
                } else if (MODE == 2) {
                    size_t o = (size_t)r * ldc + col;
                    float2 rr = *(const float2*)&resid[o];
                    *(float2*)&C[o] = make_float2(v0 + rr.x, v1 + rr.y);
                } else {
                    int t2 = stok[lr];
                    if (t2 >= 0) {
                        int tok = t2 >> 1;
                        float w = swt[lr];
                        atomicAdd(&C[(size_t)tok * ldc + col],     w * v0);
                        atomicAdd(&C[(size_t)tok * ldc + col + 1], w * v1);
                    }
                }
            }
        }
    }
}

// ---------------- tensor-core attention: 512 thr, 16 warps x 16 rows -------
__global__ void __launch_bounds__(512)
attn_kernel(__half* __restrict__ oatt) {
    extern __shared__ __half sma[];
    __half* Qh = sma;                  // 256 x APAD

    int n = blockIdx.x, h = blockIdx.y, b = blockIdx.z;
    int g = h & (GG - 1);
    int base = b * LL + n * 128;
    int tid = threadIdx.x, wid = tid >> 5, lane = tid & 31;
    int quad = lane >> 2, tq = lane & 3;
    int lrow = lane & 15, lhalf = lane >> 4;

    uint32_t qBase = su32(Qh);
    uint32_t kvStage[2];
    kvStage[0] = qBase + (uint32_t)(256 * APAD) * 2;
    kvStage[1] = kvStage[0] + (uint32_t)(128 * APAD) * 2;
    uint32_t vOff = (uint32_t)(64 * APAD) * 2;

    // Q cp.async: 4 segs per thread
    {
        int qrow = tid >> 1, qs = (tid & 1) * 4;
        const __half* qsrc = g_qh + (size_t)(base + qrow) * DD + h * 64 + qs * 8;
        uint32_t qdst = qBase + (uint32_t)(qrow * APAD + qs * 8) * 2;
        #pragma unroll
        for (int s2 = 0; s2 < 4; s2++)
            CP16(qdst + s2 * 16, qsrc + s2 * 8);
        CP_COMMIT();
    }

    // K/V: 1 seg each per thread per tile
    int trow = tid >> 3, tseg = tid & 7;
    const __half* ksrc = g_kh + (size_t)(base + trow) * KVD + g * 64 + tseg * 8;
    const __half* vsrc = g_vt + ((size_t)(b * GG + g) * 64 + trow) * LL + n * 128 + tseg * 8;
    uint32_t kdst = (uint32_t)(trow * APAD + tseg * 8) * 2;

    // prologue tiles 0, 1
    #pragma unroll
    for (int pt = 0; pt < 2; pt++) {
        uint32_t kb = kvStage[pt];
        CP16(kb + kdst,        ksrc + (size_t)pt * 64 * KVD);
        CP16(kb + vOff + kdst, vsrc + pt * 64);
        CP_COMMIT();
    }

    float o[8][4];
    #pragma unroll
    for (int nt = 0; nt < 8; nt++)
        #pragma unroll
        for (int i = 0; i < 4; i++) o[nt][i] = 0.f;
    float denomAcc[2] = {0.f, 0.f};

    for (int kt = 0; kt < 4; kt++) {
        if (kt == 3) CP_WAIT0(); else CP_WAIT1();
        __syncthreads();

        uint32_t kBase = kvStage[kt & 1];
        uint32_t vBase = kBase + vOff;

        // ---- S = Q @ K^T ----
        float s[8][4];
        #pragma unroll
        for (int nt = 0; nt < 8; nt++)
            #pragma unroll
            for (int i = 0; i < 4; i++) s[nt][i] = 0.f;

        #pragma unroll
        for (int ks = 0; ks < 4; ks++) {
            uint32_t kof = (uint32_t)(ks * 16 + lhalf * 8) * 2;
            uint32_t ah[4];
            uint32_t aa = qBase + (uint32_t)((wid * 16 + lrow) * APAD) * 2 + kof;
            LDSM4(ah[0], ah[1], ah[2], ah[3], aa);
            uint32_t bh[8][2];
            #pragma unroll
            for (int p = 0; p < 4; p++) {
                uint32_t bb = kBase + (uint32_t)((p * 16 + lrow) * APAD) * 2 + kof;
                LDSM4(bh[2*p][0], bh[2*p+1][0], bh[2*p][1], bh[2*p+1][1], bb);
            }
            #pragma unroll
            for (int nt = 0; nt < 8; nt++)
                mma_f16(s[nt], ah, bh[nt]);
        }

        // ---- exp, denominators, pack P (fp16) ----
        uint32_t ph[8][2];
        {
            float d0 = 0.f, d1 = 0.f;
            #pragma unroll
            for (int nt = 0; nt < 8; nt++) {
                float p0 = __expf(fminf(s[nt][0], 75.f));
                float p1 = __expf(fminf(s[nt][1], 75.f));
                float p2 = __expf(fminf(s[nt][2], 75.f));
                float p3 = __expf(fminf(s[nt][3], 75.f));
                d0 += p0 + p1;
                d1 += p2 + p3;
                ph[nt][0] = packf2(p0, p1);
                ph[nt][1] = packf2(p2, p3);
            }
            d0 += __shfl_xor_sync(0xffffffffu, d0, 1);
            d0 += __shfl_xor_sync(0xffffffffu, d0, 2);
            d1 += __shfl_xor_sync(0xffffffffu, d1, 1);
            d1 += __shfl_xor_sync(0xffffffffu, d1, 2);
            denomAcc[0] += d0;
            denomAcc[1] += d1;
        }

        // ---- O += P @ V^T ----
        #pragma unroll
        for (int ks = 0; ks < 4; ks++) {
            uint32_t kof = (uint32_t)(ks * 16 + lhalf * 8) * 2;
            uint32_t bvh[8][2];
            #pragma unroll
            for (int p = 0; p < 4; p++) {
                uint32_t bb = vBase + (uint32_t)((p * 16 + lrow) * APAD) * 2 + kof;
                LDSM4(bvh[2*p][0], bvh[2*p+1][0], bvh[2*p][1], bvh[2*p+1][1], bb);
            }
            uint32_t ah4[4] = { ph[2*ks][0], ph[2*ks][1], ph[2*ks+1][0], ph[2*ks+1][1] };
            #pragma unroll
            for (int nt = 0; nt < 8; nt++)
                mma_f16(o[nt], ah4, bvh[nt]);
        }

        // prefetch tile kt+2 into the stage just consumed
        if (kt + 2 < 4) {
            __syncthreads();
            int pt = kt + 2;
            uint32_t kb = kvStage[kt & 1];
            CP16(kb + kdst,        ksrc + (size_t)pt * 64 * KVD);
            CP16(kb + vOff + kdst, vsrc + pt * 64);
            CP_COMMIT();
        }
    }

    // ---- epilogue ----
    #pragma unroll
    for (int half = 0; half < 2; half++) {
        float inv = 1.f / denomAcc[half];
        int tokout = b * LL + n * 256 + wid * 16 + quad + half * 8;
        size_t rowb = (size_t)tokout * DD + h * 64;
        #pragma unroll
        for (int nt = 0; nt < 8; nt++) {
            float v0 = o[nt][half * 2 + 0] * inv;
            float v1 = o[nt][half * 2 + 1] * inv;
            int col = nt * 8 + tq * 2;
            *(uint32_t*)&oatt[rowb + col] = packf2(v0, v1);
        }
    }
}

// ---------------- aux scalar ----------------
__global__ void aux_kernel(float* __restrict__ out, long long out_size) {
    if (threadIdx.x == 0 && blockIdx.x == 0) {
        float pen = 0.f;
        #pragma unroll
        for (int e = 0; e < EE; e++) {
            float usage = (float)g_ecount[e] / ((float)NTOK + 1e-8f);
            pen += fmaxf(usage - 0.4f, 0.f);
        }
        float ent = g_entsum / (float)NTOK;
        float aux = 0.05f * ent + pen;
        long long total = (long long)NTOK * HID;
        if (out_size > total) out[total] = aux;
    }
}

// ---------------- launch ----------------
extern "C" void kernel_launch(void* const* d_in, const int* in_sizes, int n_in,
                              void* d_out, int out_size) {
    const float* x     = (const float*)d_in[0];
    const float* Wq    = (const float*)d_in[1];
    const float* bq    = (const float*)d_in[2];
    const float* Wk    = (const float*)d_in[3];
    const float* bk    = (const float*)d_in[4];
    const float* Wv    = (const float*)d_in[5];
    const float* bv    = (const float*)d_in[6];
    const float* Wo    = (const float*)d_in[7];
    const float* bo    = (const float*)d_in[8];
    const float* ln1_g = (const float*)d_in[9];
    const float* ln1_b = (const float*)d_in[10];
    const float* ln2_g = (const float*)d_in[11];
    const float* ln2_b = (const float*)d_in[12];
    const float* Wg    = (const float*)d_in[13];
    const float* bg    = (const float*)d_in[14];
    const float* We    = (const float*)d_in[15];
    const float* be    = (const float*)d_in[16];
    float* out = (float*)d_out;

    __half *ln1, *att, *ln2, *wqkv, *wot, *wet;
    float *bqkv;
    cudaGetSymbolAddress((void**)&ln1,  g_ln1);
    cudaGetSymbolAddress((void**)&att,  g_att);
    cudaGetSymbolAddress((void**)&ln2,  g_ln2);
    cudaGetSymbolAddress((void**)&wqkv, g_wqkv);
    cudaGetSymbolAddress((void**)&wot,  g_wot);
    cudaGetSymbolAddress((void**)&wet,  g_wet);
    cudaGetSymbolAddress((void**)&bqkv, g_bqkv);

    const int ASM = (256 + 2 * 128) * APAD * 2;   // 73728
    cudaFuncSetAttribute(attn_kernel, cudaFuncAttributeMaxDynamicSharedMemorySize, ASM);
    cudaFuncSetAttribute(tc_gemm<1>, cudaFuncAttributeMaxDynamicSharedMemorySize, GSMEM);
    cudaFuncSetAttribute(tc_gemm<2>, cudaFuncAttributeMaxDynamicSharedMemorySize, GSMEM);
    cudaFuncSetAttribute(tc_gemm<3>, cudaFuncAttributeMaxDynamicSharedMemorySize, GSMEM);

    // side stream for the Wo/We weight prep (graph-capturable fork/join)
    cudaStream_t s2;
    cudaEvent_t evFork, evJoin;
    cudaStreamCreateWithFlags(&s2, cudaStreamNonBlocking);
    cudaEventCreateWithFlags(&evFork, cudaEventDisableTiming);
    cudaEventCreateWithFlags(&evJoin, cudaEventDisableTiming);

    // main stream: QKV weight prep (+bias+zero) first
    transpose_qkv<<<1285, dim3(32, 8)>>>(Wq, Wk, Wv, bq, bk, bv);

    // fork: Wo/We prep runs concurrently with LN1/QKV/attention
    cudaEventRecord(evFork, 0);
    cudaStreamWaitEvent(s2, evFork, 0);
    transpose_owe<<<9216, dim3(32, 8), 0, s2>>>(Wo, We);
    cudaEventRecord(evJoin, s2);

    ln_kernel<<<NTOK, 256>>>(x, ln1_g, ln1_b, ln1);

    // QKV GEMM: writes g_qh (fp16, scaled) + g_kh (fp16) + g_vt (fp16 transposed)
    tc_gemm<1><<<dim3(10, 64), 256, GSMEM>>>(ln1, wqkv, bqkv, nullptr, nullptr, 0);

    attn_kernel<<<dim3(NWIN, HH, BB), 512, ASM>>>(att);

    // join: Wo/We prep must be done before the Wo GEMM
    cudaStreamWaitEvent(0, evJoin, 0);

    // out = x + attn@Wo + bo
    tc_gemm<2><<<dim3(8, 64), 256, GSMEM>>>(att, wot, bo, x, out, DD);

    ln2_gate_kernel<<<NTOK, 256>>>(out, ln2_g, ln2_b, Wg, bg, ln2);

    // MoE: atomicAdd directly into out
    tc_gemm<3><<<dim3(8, 64, EE), 256, GSMEM>>>(ln2, wet, be, nullptr, out, HID);

    aux_kernel<<<1, 32>>>(out, (long long)out_size);
}